// round 1
// baseline (speedup 1.0000x reference)
#include <cuda_runtime.h>
#include <math_constants.h>

// ---------------- problem constants ----------------
#define BATCH     1024
#define DIM       64
#define NCAND     200000
#define TOPK      10
#define ROWTILE   64          // users per block in topk kernel
#define NROWT     (BATCH / ROWTILE)         // 16
#define CCHUNK    2048        // candidates per block
#define NCHUNK    ((NCAND + CCHUNK - 1) / CCHUNK)   // 98
#define CTILE     64          // candidates per inner tile
#define PITCH_U   68          // uS pitch (floats), 272B rows -> 16B aligned
#define PITCH_C   68          // cS pitch
#define PITCH_S   65          // score pitch (conflict-free column scan)

// scratch for partial top-k: [row][chunk][TOPK]
static __device__ float g_pv[BATCH * NCHUNK * TOPK];
static __device__ int   g_pi[BATCH * NCHUNK * TOPK];

// ================= Kernel A: gather + MLP =================
// 64 blocks x 256 threads, 16 rows per block.
__global__ void __launch_bounds__(256) mlp_kernel(
    const int* __restrict__ user_id, const int* __restrict__ movie_id,
    const float* __restrict__ ut, const float* __restrict__ ct,
    const float* __restrict__ W1, const float* __restrict__ b1,
    const float* __restrict__ W2, const float* __restrict__ b2,
    const float* __restrict__ W3, const float* __restrict__ b3,
    float* __restrict__ outUE, float* __restrict__ outCE, float* __restrict__ outR)
{
    __shared__ float xs[16][128];
    __shared__ float h1s[16][256];
    __shared__ float h2s[16][128];
    __shared__ int uid[16], mid[16];

    const int t = threadIdx.x;
    const int rbase = blockIdx.x * 16;

    if (t < 16) { uid[t] = user_id[rbase + t]; mid[t] = movie_id[rbase + t]; }
    __syncthreads();

    // gather embeddings, write-through to outputs
    for (int idx = t; idx < 16 * 128; idx += 256) {
        int r = idx >> 7, k = idx & 127;
        float v;
        if (k < 64) {
            v = ut[(long)uid[r] * DIM + k];
            outUE[(long)(rbase + r) * DIM + k] = v;
        } else {
            v = ct[(long)mid[r] * DIM + (k - 64)];
            outCE[(long)(rbase + r) * DIM + (k - 64)] = v;
        }
        xs[r][k] = v;
    }
    __syncthreads();

    // h1 = relu(x @ W1 + b1), W1: [128][256]
    {
        float acc[16];
        float bb = b1[t];
        #pragma unroll
        for (int r = 0; r < 16; r++) acc[r] = bb;
        for (int k = 0; k < 128; k++) {
            float w = W1[k * 256 + t];
            #pragma unroll
            for (int r = 0; r < 16; r++) acc[r] += xs[r][k] * w;
        }
        #pragma unroll
        for (int r = 0; r < 16; r++) h1s[r][t] = fmaxf(acc[r], 0.0f);
    }
    __syncthreads();

    // h2 = relu(h1 @ W2 + b2), W2: [256][128]
    if (t < 128) {
        float acc[16];
        float bb = b2[t];
        #pragma unroll
        for (int r = 0; r < 16; r++) acc[r] = bb;
        for (int k = 0; k < 256; k++) {
            float w = W2[k * 128 + t];
            #pragma unroll
            for (int r = 0; r < 16; r++) acc[r] += h1s[r][k] * w;
        }
        #pragma unroll
        for (int r = 0; r < 16; r++) h2s[r][t] = fmaxf(acc[r], 0.0f);
    }
    __syncthreads();

    // rating = h2 @ W3 + b3
    if (t < 16) {
        float s = b3[0];
        for (int k = 0; k < 128; k++) s += h2s[t][k] * W3[k];
        outR[rbase + t] = s;
    }
}

// ================= Kernel B: fused similarity + partial top-k =================
// grid (NROWT, NCHUNK) x 256 threads. Block = 64 users x 2048 candidates.
__global__ void __launch_bounds__(256) topk_partial_kernel(
    const int* __restrict__ user_id,
    const float* __restrict__ ut,
    const float* __restrict__ ct)
{
    const int rowTile = blockIdx.x;            // 0..15
    const int chunk   = blockIdx.y;            // 0..97
    const int rowBase = rowTile * ROWTILE;
    const int cBase   = chunk * CCHUNK;
    const int t = threadIdx.x;

    __shared__ float uS[DIM * PITCH_U];        // [k][u]
    __shared__ float cS[CTILE * PITCH_C];      // [c][k], reused as score tile [u][PITCH_S]
    __shared__ int   uids[ROWTILE];

    if (t < ROWTILE) uids[t] = user_id[rowBase + t];
    __syncthreads();

    // load user tile transposed: uS[k][u]
    for (int idx = t; idx < ROWTILE * DIM; idx += 256) {
        int u = idx >> 6, k = idx & 63;
        uS[k * PITCH_U + u] = ut[(long)uids[u] * DIM + k];
    }

    // per-thread persistent top-k for user row t (threads 0..63 only)
    float topv[TOPK];
    int   topi[TOPK];
    #pragma unroll
    for (int j = 0; j < TOPK; j++) { topv[j] = -CUDART_INF_F; topi[j] = 0; }
    float minv = -CUDART_INF_F;
    int   minp = 0;

    const int ux = t & 15;      // user micro-tile 4*ux..+3
    const int cx = t >> 4;      // cand micro-tile 4*cx..+3
    const int ntile = min(CCHUNK / CTILE, (NCAND - cBase + CTILE - 1) / CTILE);

    __syncthreads();

    for (int tile = 0; tile < ntile; tile++) {
        const int c0 = cBase + tile * CTILE;

        // load cand tile: cS[c][k], zero-fill out of range
        {
            int lin = t;       // float4 granularity: 1024 chunks / 256 threads
            #pragma unroll
            for (int q = 0; q < 4; q++) {
                int c  = lin >> 4;
                int kk = (lin & 15) << 2;
                float4 v = make_float4(0.f, 0.f, 0.f, 0.f);
                if (c0 + c < NCAND)
                    v = *(const float4*)&ct[(long)(c0 + c) * DIM + kk];
                *(float4*)&cS[c * PITCH_C + kk] = v;
                lin += 256;
            }
        }
        __syncthreads();

        // 4x4 micro-tile fp32 GEMM, k ascending (matches fp32 fold order closely)
        float acc[4][4];
        #pragma unroll
        for (int i = 0; i < 4; i++)
            #pragma unroll
            for (int j = 0; j < 4; j++) acc[i][j] = 0.0f;

        #pragma unroll 8
        for (int k = 0; k < DIM; k++) {
            float4 uv = *(const float4*)&uS[k * PITCH_U + ux * 4];
            float c0v = cS[(cx * 4 + 0) * PITCH_C + k];
            float c1v = cS[(cx * 4 + 1) * PITCH_C + k];
            float c2v = cS[(cx * 4 + 2) * PITCH_C + k];
            float c3v = cS[(cx * 4 + 3) * PITCH_C + k];
            acc[0][0] += uv.x * c0v; acc[0][1] += uv.x * c1v;
            acc[0][2] += uv.x * c2v; acc[0][3] += uv.x * c3v;
            acc[1][0] += uv.y * c0v; acc[1][1] += uv.y * c1v;
            acc[1][2] += uv.y * c2v; acc[1][3] += uv.y * c3v;
            acc[2][0] += uv.z * c0v; acc[2][1] += uv.z * c1v;
            acc[2][2] += uv.z * c2v; acc[2][3] += uv.z * c3v;
            acc[3][0] += uv.w * c0v; acc[3][1] += uv.w * c1v;
            acc[3][2] += uv.w * c2v; acc[3][3] += uv.w * c3v;
        }
        __syncthreads();   // all reads of cS done -> safe to overwrite as scores

        // write scores into aliased buffer: sS[u][c], pitch 65 (conflict-free scan)
        float* sS = cS;
        #pragma unroll
        for (int i = 0; i < 4; i++)
            #pragma unroll
            for (int j = 0; j < 4; j++)
                sS[(ux * 4 + i) * PITCH_S + (cx * 4 + j)] = acc[i][j];
        __syncthreads();

        // threads 0..63: scan this row's 64 scores, update running top-k
        if (t < ROWTILE) {
            int cvalid = min(CTILE, NCAND - c0);
            for (int c = 0; c < cvalid; c++) {
                float s = sS[t * PITCH_S + c];
                if (s > minv) {                 // strict > : earlier (lower) index wins ties
                    topv[minp] = s;
                    topi[minp] = c0 + c;
                    minv = topv[0]; minp = 0;
                    #pragma unroll
                    for (int j = 1; j < TOPK; j++)
                        if (topv[j] < minv) { minv = topv[j]; minp = j; }
                }
            }
        }
        __syncthreads();
    }

    if (t < ROWTILE) {
        long base = ((long)(rowBase + t) * NCHUNK + chunk) * TOPK;
        #pragma unroll
        for (int j = 0; j < TOPK; j++) {
            g_pv[base + j] = topv[j];
            g_pi[base + j] = topi[j];
        }
    }
}

// ================= Kernel C: merge partial top-k =================
// 128 blocks x 256 threads; warp per row.
__global__ void __launch_bounds__(256) topk_merge_kernel(float* __restrict__ outP)
{
    const int warp = threadIdx.x >> 5;
    const int lane = threadIdx.x & 31;
    const int row  = blockIdx.x * 8 + warp;

    __shared__ float sv[8][32 * TOPK];
    __shared__ int   si[8][32 * TOPK];

    const int nent = NCHUNK * TOPK;   // 980
    float tv[TOPK]; int ti[TOPK];
    #pragma unroll
    for (int j = 0; j < TOPK; j++) { tv[j] = -CUDART_INF_F; ti[j] = 0x7fffffff; }
    float minv = -CUDART_INF_F; int minp = 0;

    const long rbase = (long)row * nent;
    for (int e = lane; e < nent; e += 32) {
        float v = g_pv[rbase + e];
        int   i = g_pi[rbase + e];
        bool take = (v > minv) || (v == minv && i < ti[minp]);
        if (take) {
            tv[minp] = v; ti[minp] = i;
            minv = tv[0]; minp = 0;
            #pragma unroll
            for (int j = 1; j < TOPK; j++)
                if (tv[j] < minv || (tv[j] == minv && ti[j] > ti[minp])) { minv = tv[j]; minp = j; }
        }
    }
    #pragma unroll
    for (int j = 0; j < TOPK; j++) {
        sv[warp][lane * TOPK + j] = tv[j];
        si[warp][lane * TOPK + j] = ti[j];
    }
    __syncwarp();

    if (lane == 0) {
        float fv[TOPK]; int fi[TOPK];
        #pragma unroll
        for (int j = 0; j < TOPK; j++) { fv[j] = -CUDART_INF_F; fi[j] = 0x7fffffff; }
        float mv = -CUDART_INF_F; int mp = 0;
        for (int e = 0; e < 32 * TOPK; e++) {
            float v = sv[warp][e];
            int   i = si[warp][e];
            bool take = (v > mv) || (v == mv && i < fi[mp]);
            if (take) {
                fv[mp] = v; fi[mp] = i;
                mv = fv[0]; mp = 0;
                #pragma unroll
                for (int j = 1; j < TOPK; j++)
                    if (fv[j] < mv || (fv[j] == mv && fi[j] > fi[mp])) { mv = fv[j]; mp = j; }
            }
        }
        // sort descending by value, ties -> lower index first (jax top_k semantics)
        for (int a = 0; a < TOPK; a++) {
            int best = a;
            for (int b = a + 1; b < TOPK; b++)
                if (fv[b] > fv[best] || (fv[b] == fv[best] && fi[b] < fi[best])) best = b;
            float v = fv[best]; fv[best] = fv[a]; fv[a] = v;
            int   i = fi[best]; fi[best] = fi[a]; fi[a] = i;
            outP[(long)row * TOPK + a] = (float)fi[a];
        }
    }
}

// ================= launch =================
extern "C" void kernel_launch(void* const* d_in, const int* in_sizes, int n_in,
                              void* d_out, int out_size)
{
    const int*   user_id  = (const int*)d_in[0];
    const int*   movie_id = (const int*)d_in[1];
    const float* ut       = (const float*)d_in[2];
    const float* ct       = (const float*)d_in[3];
    const float* W1       = (const float*)d_in[4];
    const float* b1       = (const float*)d_in[5];
    const float* W2       = (const float*)d_in[6];
    const float* b2       = (const float*)d_in[7];
    const float* W3       = (const float*)d_in[8];
    const float* b3       = (const float*)d_in[9];

    float* out   = (float*)d_out;
    float* outUE = out;                                   // [1024, 64]
    float* outCE = out + BATCH * DIM;                     // [1024, 64]
    float* outR  = out + 2 * BATCH * DIM;                 // [1024, 1]
    float* outP  = out + 2 * BATCH * DIM + BATCH;         // [1024, 10]

    mlp_kernel<<<BATCH / 16, 256>>>(user_id, movie_id, ut, ct,
                                    W1, b1, W2, b2, W3, b3,
                                    outUE, outCE, outR);

    dim3 gridB(NROWT, NCHUNK);   // x = row tile (varies fastest) -> chunk shared in L2
    topk_partial_kernel<<<gridB, 256>>>(user_id, ut, ct);

    topk_merge_kernel<<<BATCH / 8, 256>>>(outP);
}

// round 4
// speedup vs baseline: 1.2462x; 1.2462x over previous
#include <cuda_runtime.h>
#include <cuda_bf16.h>
#include <math_constants.h>
#include <cstdint>
#include <cstring>

// ---------------- problem constants ----------------
#define BATCH   1024
#define DIM     64
#define NCAND   200000
#define TOPK    10
#define K16     16                 // per-thread shortlist size
#define NT      1563               // ceil(200000/128) tiles of 128 cands
#define NCHUNKS 19                 // tile chunks  (8 x 19 = 152 CTAs)
#define NROWT   8                  // 1024/128 row tiles
#define NENT    (NCHUNKS * 64)     // shortlist entries per row (4 threads x 16)

// ---------------- device scratch ----------------
static __device__ __align__(1024) unsigned char g_B[(size_t)NT * 16384];  // SW128-swizzled bf16 cand tiles [128c x 64k]
static __device__ __align__(128)  unsigned char g_A[(size_t)BATCH * 128]; // gathered bf16 user rows
static __device__ float g_pv[(size_t)BATCH * NENT];
static __device__ int   g_pi[(size_t)BATCH * NENT];

// ---------------- helpers ----------------
__device__ __forceinline__ uint32_t smem_u32(const void* p) {
    uint32_t a;
    asm("{ .reg .u64 t; cvta.to.shared.u64 t, %1; cvt.u32.u64 %0, t; }" : "=r"(a) : "l"(p));
    return a;
}
__device__ __forceinline__ uint32_t pack_bf16x2(float x, float y) {
    __nv_bfloat16 lo = __float2bfloat16(x);
    __nv_bfloat16 hi = __float2bfloat16(y);
    uint16_t lo16, hi16;
    memcpy(&lo16, &lo, 2);
    memcpy(&hi16, &hi, 2);
    return (uint32_t)lo16 | ((uint32_t)hi16 << 16);
}
__device__ __forceinline__ uint32_t sw128(uint32_t off) {   // SW128 swizzle on byte offsets
    return off ^ ((off >> 3) & 0x70);
}
__device__ __forceinline__ void ldsm_x4(uint32_t& r0, uint32_t& r1, uint32_t& r2, uint32_t& r3, uint32_t addr) {
    asm volatile("ldmatrix.sync.aligned.m8n8.x4.shared.b16 {%0,%1,%2,%3}, [%4];"
                 : "=r"(r0), "=r"(r1), "=r"(r2), "=r"(r3) : "r"(addr));
}
__device__ __forceinline__ void mma16816(float& d0, float& d1, float& d2, float& d3,
                                         uint32_t a0, uint32_t a1, uint32_t a2, uint32_t a3,
                                         uint32_t b0, uint32_t b1) {
    asm volatile("mma.sync.aligned.m16n8k16.row.col.f32.bf16.bf16.f32 "
                 "{%0,%1,%2,%3}, {%4,%5,%6,%7}, {%8,%9}, {%0,%1,%2,%3};"
                 : "+f"(d0), "+f"(d1), "+f"(d2), "+f"(d3)
                 : "r"(a0), "r"(a1), "r"(a2), "r"(a3), "r"(b0), "r"(b1));
}
#define CP_ASYNC16(smem, gptr) \
    asm volatile("cp.async.cg.shared.global [%0], [%1], 16;" :: "r"(smem), "l"(gptr))
#define CP_COMMIT() asm volatile("cp.async.commit_group;")
#define CP_WAIT1()  asm volatile("cp.async.wait_group 1;")
#define CP_WAIT0()  asm volatile("cp.async.wait_group 0;")

// ================= Kernel 0: convert & pre-tile (fp32 -> bf16, SW128) =================
__global__ void __launch_bounds__(256) convert_kernel(
    const float* __restrict__ ct, const float* __restrict__ ut,
    const int* __restrict__ user_id)
{
    const long NBC = (long)NT * 1024;   // 16B chunks in g_B
    long gid = (long)blockIdx.x * 256 + threadIdx.x;
    if (gid < NBC) {
        long tile = gid >> 10;
        int within = (int)(gid & 1023);
        int r = within >> 3, sub = within & 7;     // cand-in-tile, 16B chunk (8 bf16)
        long c = tile * 128 + r;
        uint32_t sw = sw128((uint32_t)(r * 128 + sub * 16));
        uint4 out = make_uint4(0u, 0u, 0u, 0u);
        if (c < NCAND) {
            const float4* src = (const float4*)(ct + c * 64 + sub * 8);
            float4 a = src[0], b = src[1];
            out.x = pack_bf16x2(a.x, a.y); out.y = pack_bf16x2(a.z, a.w);
            out.z = pack_bf16x2(b.x, b.y); out.w = pack_bf16x2(b.z, b.w);
        }
        *(uint4*)(g_B + tile * 16384 + sw) = out;
    } else {
        long g2 = gid - NBC;
        if (g2 >= (long)BATCH * 8) return;
        int u = (int)(g2 >> 3), sub = (int)(g2 & 7);
        const float4* src = (const float4*)(ut + (long)user_id[u] * 64 + sub * 8);
        float4 a = src[0], b = src[1];
        uint4 out;
        out.x = pack_bf16x2(a.x, a.y); out.y = pack_bf16x2(a.z, a.w);
        out.z = pack_bf16x2(b.x, b.y); out.w = pack_bf16x2(b.z, b.w);
        *(uint4*)(g_A + (long)u * 128 + sub * 16) = out;
    }
}

// ================= Kernel 1: gather + MLP =================
__global__ void __launch_bounds__(256) mlp_kernel(
    const int* __restrict__ user_id, const int* __restrict__ movie_id,
    const float* __restrict__ ut, const float* __restrict__ ct,
    const float* __restrict__ W1, const float* __restrict__ b1,
    const float* __restrict__ W2, const float* __restrict__ b2,
    const float* __restrict__ W3, const float* __restrict__ b3,
    float* __restrict__ outUE, float* __restrict__ outCE, float* __restrict__ outR)
{
    __shared__ float xs[8][128];
    __shared__ float h1s[8][256];
    __shared__ float h2s[8][128];
    __shared__ int uid[8], mid[8];

    const int t = threadIdx.x;
    const int rbase = blockIdx.x * 8;

    if (t < 8) { uid[t] = user_id[rbase + t]; mid[t] = movie_id[rbase + t]; }
    __syncthreads();

    for (int idx = t; idx < 8 * 128; idx += 256) {
        int r = idx >> 7, k = idx & 127;
        float v;
        if (k < 64) {
            v = ut[(long)uid[r] * DIM + k];
            outUE[(long)(rbase + r) * DIM + k] = v;
        } else {
            v = ct[(long)mid[r] * DIM + (k - 64)];
            outCE[(long)(rbase + r) * DIM + (k - 64)] = v;
        }
        xs[r][k] = v;
    }
    __syncthreads();

    {
        float acc[8];
        float bb = b1[t];
        #pragma unroll
        for (int r = 0; r < 8; r++) acc[r] = bb;
        #pragma unroll 8
        for (int k = 0; k < 128; k++) {
            float w = W1[k * 256 + t];
            #pragma unroll
            for (int r = 0; r < 8; r++) acc[r] += xs[r][k] * w;
        }
        #pragma unroll
        for (int r = 0; r < 8; r++) h1s[r][t] = fmaxf(acc[r], 0.0f);
    }
    __syncthreads();

    if (t < 128) {
        float acc[8];
        float bb = b2[t];
        #pragma unroll
        for (int r = 0; r < 8; r++) acc[r] = bb;
        #pragma unroll 8
        for (int k = 0; k < 256; k++) {
            float w = W2[k * 128 + t];
            #pragma unroll
            for (int r = 0; r < 8; r++) acc[r] += h1s[r][k] * w;
        }
        #pragma unroll
        for (int r = 0; r < 8; r++) h2s[r][t] = fmaxf(acc[r], 0.0f);
    }
    __syncthreads();

    if (t < 8) {
        float s = b3[0];
        #pragma unroll 8
        for (int k = 0; k < 128; k++) s += h2s[t][k] * W3[k];
        outR[rbase + t] = s;
    }
}

// ================= Kernel 2: HMMA GEMM + in-register top-16 =================
// grid (8 rowtiles, 19 chunks) x 256 threads (8 warps). Warp w: rows w*16..w*16+15.
__device__ __forceinline__ void upd16(float s, int ci, float* tv, int* ti, float& mn, int& mp) {
    if (s > mn && ci < NCAND) {
        tv[mp] = s; ti[mp] = ci;
        mn = tv[0]; mp = 0;
        #pragma unroll
        for (int q = 1; q < K16; q++)
            if (tv[q] < mn) { mn = tv[q]; mp = q; }
    }
}

__global__ void __launch_bounds__(256, 1) gemm_topk_kernel()
{
    __shared__ __align__(1024) unsigned char sB[2][16384];

    const int tid = threadIdx.x;
    const int wid = tid >> 5;
    const int lane = tid & 31;
    const int rowtile = blockIdx.x;
    const int chunk = blockIdx.y;

    const int t_begin = chunk * 82 + min(chunk, 5);
    const int t_end = (chunk + 1) * 82 + min(chunk + 1, 5);
    const int ntiles = t_end - t_begin;

    const uint32_t sb0 = smem_u32(&sB[0][0]);
    const uint32_t sb1 = smem_u32(&sB[1][0]);

    // ---- stage A (128 rows x 128B) into sB[0], build register A-fragments ----
    {
        const uint4* asrc = (const uint4*)(g_A + (size_t)rowtile * 128 * 128);
        uint4* adst = (uint4*)&sB[0][0];
        #pragma unroll
        for (int p = 0; p < 4; p++)
            adst[p * 256 + tid] = asrc[p * 256 + tid];
    }
    __syncthreads();

    uint32_t af[4][4];   // [kstep][frag reg]
    {
        // ldmatrix.x4 non-trans: lanes 0-7: rows m0..7 klo; 8-15: m8..15 klo; 16-23: m0..7 khi; 24-31: m8..15 khi
        const int g2 = lane >> 3;
        const int mrow = wid * 16 + (g2 & 1) * 8 + (lane & 7);
        const int kb = (g2 >> 1) * 16;
        #pragma unroll
        for (int s = 0; s < 4; s++) {
            uint32_t addr = sb0 + (uint32_t)(mrow * 128 + s * 32 + kb);
            ldsm_x4(af[s][0], af[s][1], af[s][2], af[s][3], addr);
        }
    }
    __syncthreads();

    // ---- per-thread shortlist state (rows lo = wid*16 + lane/4, hi = +8) ----
    float tvLo[K16], tvHi[K16];
    int   tiLo[K16], tiHi[K16];
    #pragma unroll
    for (int j = 0; j < K16; j++) {
        tvLo[j] = -CUDART_INF_F; tvHi[j] = -CUDART_INF_F;
        tiLo[j] = 0x7fffffff;    tiHi[j] = 0x7fffffff;
    }
    float mnLo = -CUDART_INF_F, mnHi = -CUDART_INF_F;
    int mpLo = 0, mpHi = 0;

    // B ldmatrix lane addressing: n-tile pair p covers n in [p*16, p*16+16)
    // lanes 0-7: n=p*16+i klo | 8-15: n=p*16+(i-8) khi | 16-23: n=p*16+8+(i-16) klo | 24-31: khi
    const int bg2 = lane >> 3;
    const int b_nloc = ((bg2 >> 1) & 1) * 8 + (lane & 7);   // 0..15 within pair
    const int b_kb = (bg2 & 1) * 16;                        // 0 or 16 bytes (k lo/hi 8)
    const int ccol = 2 * (lane & 3);                        // accum col base within n-tile

    // ---- prefetch tile 0 ----
    {
        const char* src = (const char*)(g_B + (size_t)t_begin * 16384);
        #pragma unroll
        for (int p = 0; p < 4; p++)
            CP_ASYNC16(sb0 + (uint32_t)(p * 4096 + tid * 16), src + p * 4096 + tid * 16);
        CP_COMMIT();
    }

    for (int i = 0; i < ntiles; i++) {
        // prefetch next
        if (i + 1 < ntiles) {
            const char* src = (const char*)(g_B + (size_t)(t_begin + i + 1) * 16384);
            uint32_t dst = ((i + 1) & 1) ? sb1 : sb0;
            #pragma unroll
            for (int p = 0; p < 4; p++)
                CP_ASYNC16(dst + (uint32_t)(p * 4096 + tid * 16), src + p * 4096 + tid * 16);
        }
        CP_COMMIT();
        CP_WAIT1();
        __syncthreads();

        const uint32_t bs = (i & 1) ? sb1 : sb0;
        const int tilec0 = (t_begin + i) * 128;

        #pragma unroll
        for (int half = 0; half < 2; half++) {
            float acc[8][4];
            #pragma unroll
            for (int j = 0; j < 8; j++)
                #pragma unroll
                for (int e = 0; e < 4; e++) acc[j][e] = 0.0f;

            #pragma unroll
            for (int s = 0; s < 4; s++) {
                #pragma unroll
                for (int p = 0; p < 4; p++) {
                    const int n = half * 64 + p * 16 + b_nloc;
                    uint32_t off = (uint32_t)(n * 128 + s * 32 + b_kb);
                    uint32_t b0, b1, b2, b3;
                    ldsm_x4(b0, b1, b2, b3, bs + sw128(off));
                    mma16816(acc[2 * p][0], acc[2 * p][1], acc[2 * p][2], acc[2 * p][3],
                             af[s][0], af[s][1], af[s][2], af[s][3], b0, b1);
                    mma16816(acc[2 * p + 1][0], acc[2 * p + 1][1], acc[2 * p + 1][2], acc[2 * p + 1][3],
                             af[s][0], af[s][1], af[s][2], af[s][3], b2, b3);
                }
            }

            const int cbase = tilec0 + half * 64;
            #pragma unroll
            for (int j = 0; j < 8; j++) {
                const int c0 = cbase + j * 8 + ccol;
                upd16(acc[j][0], c0,     tvLo, tiLo, mnLo, mpLo);
                upd16(acc[j][1], c0 + 1, tvLo, tiLo, mnLo, mpLo);
                upd16(acc[j][2], c0,     tvHi, tiHi, mnHi, mpHi);
                upd16(acc[j][3], c0 + 1, tvHi, tiHi, mnHi, mpHi);
            }
        }
        __syncthreads();
    }

    // ---- dump shortlists: [row][chunk][c*16 + j] ----
    {
        const int c = lane & 3;
        const int rowLo = rowtile * 128 + wid * 16 + (lane >> 2);
        const int rowHi = rowLo + 8;
        const long baseLo = ((long)rowLo * NCHUNKS + chunk) * 64 + c * 16;
        const long baseHi = ((long)rowHi * NCHUNKS + chunk) * 64 + c * 16;
        #pragma unroll
        for (int j = 0; j < K16; j++) {
            g_pv[baseLo + j] = tvLo[j]; g_pi[baseLo + j] = tiLo[j];
            g_pv[baseHi + j] = tvHi[j]; g_pi[baseHi + j] = tiHi[j];
        }
    }
}

// ================= Kernel 3: merge shortlists + exact fp32 rescore =================
__global__ void __launch_bounds__(256) merge_kernel(
    const int* __restrict__ user_id,
    const float* __restrict__ ut, const float* __restrict__ ct,
    float* __restrict__ outP)
{
    __shared__ float sv[8][32 * K16];
    __shared__ int   si[8][32 * K16];
    __shared__ float su[8][64];
    __shared__ int   sidx[8][K16];
    __shared__ float ssc[8][K16];

    const int wid = threadIdx.x >> 5;
    const int lane = threadIdx.x & 31;
    const int row = blockIdx.x * 8 + wid;

    const float* urow = ut + (long)user_id[row] * 64;
    su[wid][lane] = urow[lane];
    su[wid][lane + 32] = urow[lane + 32];

    // phase 1: lane-strided approx top-16 over NENT entries
    float tv[K16]; int ti[K16];
    #pragma unroll
    for (int j = 0; j < K16; j++) { tv[j] = -CUDART_INF_F; ti[j] = 0x7fffffff; }
    float minv = -CUDART_INF_F; int minp = 0;
    const long rb = (long)row * NENT;
    for (int e = lane; e < NENT; e += 32) {
        float v = g_pv[rb + e];
        if (v > minv) {
            int idx = g_pi[rb + e];
            if (idx < NCAND) {
                tv[minp] = v; ti[minp] = idx;
                minv = tv[0]; minp = 0;
                #pragma unroll
                for (int q = 1; q < K16; q++)
                    if (tv[q] < minv) { minv = tv[q]; minp = q; }
            }
        }
    }
    #pragma unroll
    for (int j = 0; j < K16; j++) {
        sv[wid][lane * K16 + j] = tv[j];
        si[wid][lane * K16 + j] = ti[j];
    }
    __syncwarp();

    // phase 2: lane 0 merges to global approx top-16 (dedup not needed: subsets disjoint)
    if (lane == 0) {
        float fv[K16]; int fi[K16];
        #pragma unroll
        for (int j = 0; j < K16; j++) { fv[j] = -CUDART_INF_F; fi[j] = 0x7fffffff; }
        float mv = -CUDART_INF_F; int mp = 0;
        for (int e = 0; e < 32 * K16; e++) {
            float v = sv[wid][e];
            if (v > mv) {
                fv[mp] = v; fi[mp] = si[wid][e];
                mv = fv[0]; mp = 0;
                #pragma unroll
                for (int q = 1; q < K16; q++)
                    if (fv[q] < mv) { mv = fv[q]; mp = q; }
            }
        }
        #pragma unroll
        for (int j = 0; j < K16; j++) sidx[wid][j] = fi[j];
    }
    __syncwarp();

    // phase 3: exact fp32 rescore of 16-candidate shortlist
    if (lane < K16) {
        int c = sidx[wid][lane];
        float s = -CUDART_INF_F;
        if (c >= 0 && c < NCAND) {
            const float* crow = ct + (long)c * 64;
            s = 0.0f;
            #pragma unroll 8
            for (int k = 0; k < 64; k++) s += su[wid][k] * crow[k];
        }
        ssc[wid][lane] = s;
    }
    __syncwarp();

    // phase 4: sort top-10 (desc value, asc index) and write
    if (lane == 0) {
        float fv[K16]; int fi[K16];
        #pragma unroll
        for (int j = 0; j < K16; j++) { fv[j] = ssc[wid][j]; fi[j] = sidx[wid][j]; }
        for (int a = 0; a < TOPK; a++) {
            int best = a;
            for (int b = a + 1; b < K16; b++)
                if (fv[b] > fv[best] || (fv[b] == fv[best] && fi[b] < fi[best])) best = b;
            float v = fv[best]; fv[best] = fv[a]; fv[a] = v;
            int   i = fi[best]; fi[best] = fi[a]; fi[a] = i;
            outP[(long)row * TOPK + a] = (float)fi[a];
        }
    }
}

// ================= launch =================
extern "C" void kernel_launch(void* const* d_in, const int* in_sizes, int n_in,
                              void* d_out, int out_size)
{
    const int*   user_id  = (const int*)d_in[0];
    const int*   movie_id = (const int*)d_in[1];
    const float* ut       = (const float*)d_in[2];
    const float* ct       = (const float*)d_in[3];
    const float* W1       = (const float*)d_in[4];
    const float* b1       = (const float*)d_in[5];
    const float* W2       = (const float*)d_in[6];
    const float* b2       = (const float*)d_in[7];
    const float* W3       = (const float*)d_in[8];
    const float* b3       = (const float*)d_in[9];

    float* out   = (float*)d_out;
    float* outUE = out;
    float* outCE = out + BATCH * DIM;
    float* outR  = out + 2 * BATCH * DIM;
    float* outP  = out + 2 * BATCH * DIM + BATCH;

    const int convBlocks = (NT * 1024 + BATCH * 8 + 255) / 256;
    convert_kernel<<<convBlocks, 256>>>(ct, ut, user_id);

    mlp_kernel<<<BATCH / 8, 256>>>(user_id, movie_id, ut, ct,
                                   W1, b1, W2, b2, W3, b3,
                                   outUE, outCE, outR);

    dim3 g2(NROWT, NCHUNKS);
    gemm_topk_kernel<<<g2, 256>>>();

    merge_kernel<<<BATCH / 8, 256>>>(user_id, ut, ct, outP);
}

// round 5
// speedup vs baseline: 1.6195x; 1.2996x over previous
#include <cuda_runtime.h>
#include <cuda_bf16.h>
#include <math_constants.h>
#include <cstdint>
#include <cstring>

// ---------------- problem constants ----------------
#define BATCH   1024
#define DIM     64
#define NCAND   200000
#define TOPK    10
#define K8      8                  // per-thread shortlist size (sorted, in registers)
#define NT      1563               // ceil(200000/128) tiles of 128 cands
#define NCHUNKS 19                 // tile chunks  (8 x 19 = 152 CTAs)
#define NROWT   8                  // 1024/128 row tiles
#define NENT    (NCHUNKS * 4 * K8) // shortlist entries per row = 608

// ---------------- device scratch ----------------
static __device__ __align__(1024) unsigned char g_B[(size_t)NT * 16384];  // SW128-swizzled bf16 cand tiles [128c x 64k]
static __device__ __align__(128)  unsigned char g_A[(size_t)BATCH * 128]; // gathered bf16 user rows
static __device__ float g_pv[(size_t)BATCH * NENT];
static __device__ int   g_pi[(size_t)BATCH * NENT];

// ---------------- helpers ----------------
__device__ __forceinline__ uint32_t smem_u32(const void* p) {
    uint32_t a;
    asm("{ .reg .u64 t; cvta.to.shared.u64 t, %1; cvt.u32.u64 %0, t; }" : "=r"(a) : "l"(p));
    return a;
}
__device__ __forceinline__ uint32_t pack_bf16x2(float x, float y) {
    __nv_bfloat16 lo = __float2bfloat16(x);
    __nv_bfloat16 hi = __float2bfloat16(y);
    uint16_t lo16, hi16;
    memcpy(&lo16, &lo, 2);
    memcpy(&hi16, &hi, 2);
    return (uint32_t)lo16 | ((uint32_t)hi16 << 16);
}
__device__ __forceinline__ uint32_t sw128(uint32_t off) {
    return off ^ ((off >> 3) & 0x70);
}
__device__ __forceinline__ void ldsm_x4(uint32_t& r0, uint32_t& r1, uint32_t& r2, uint32_t& r3, uint32_t addr) {
    asm volatile("ldmatrix.sync.aligned.m8n8.x4.shared.b16 {%0,%1,%2,%3}, [%4];"
                 : "=r"(r0), "=r"(r1), "=r"(r2), "=r"(r3) : "r"(addr));
}
__device__ __forceinline__ void mma16816(float& d0, float& d1, float& d2, float& d3,
                                         uint32_t a0, uint32_t a1, uint32_t a2, uint32_t a3,
                                         uint32_t b0, uint32_t b1) {
    asm volatile("mma.sync.aligned.m16n8k16.row.col.f32.bf16.bf16.f32 "
                 "{%0,%1,%2,%3}, {%4,%5,%6,%7}, {%8,%9}, {%0,%1,%2,%3};"
                 : "+f"(d0), "+f"(d1), "+f"(d2), "+f"(d3)
                 : "r"(a0), "r"(a1), "r"(a2), "r"(a3), "r"(b0), "r"(b1));
}
#define CP_ASYNC16(smem, gptr) \
    asm volatile("cp.async.cg.shared.global [%0], [%1], 16;" :: "r"(smem), "l"(gptr))
#define CP_COMMIT() asm volatile("cp.async.commit_group;")
#define CP_WAIT1()  asm volatile("cp.async.wait_group 1;")

// Sorted-descending top-N insert, all constant indices after unroll (register-resident).
template<int N>
__device__ __forceinline__ void insN(float s, int ci, float* v, int* ix) {
    v[N - 1] = s; ix[N - 1] = ci;
    #pragma unroll
    for (int q = N - 1; q > 0; q--) {
        if (v[q] > v[q - 1]) {
            float tv = v[q]; v[q] = v[q - 1]; v[q - 1] = tv;
            int  ti = ix[q]; ix[q] = ix[q - 1]; ix[q - 1] = ti;
        }
    }
}

// ================= Kernel 0: convert & pre-tile (fp32 -> bf16, SW128) =================
__global__ void __launch_bounds__(256) convert_kernel(
    const float* __restrict__ ct, const float* __restrict__ ut,
    const int* __restrict__ user_id)
{
    const long NBC = (long)NT * 1024;   // 16B chunks in g_B
    long gid = (long)blockIdx.x * 256 + threadIdx.x;
    if (gid < NBC) {
        long tile = gid >> 10;
        int within = (int)(gid & 1023);
        int r = within >> 3, sub = within & 7;
        long c = tile * 128 + r;
        uint32_t sw = sw128((uint32_t)(r * 128 + sub * 16));
        uint4 out = make_uint4(0u, 0u, 0u, 0u);
        if (c < NCAND) {
            const float4* src = (const float4*)(ct + c * 64 + sub * 8);
            float4 a = src[0], b = src[1];
            out.x = pack_bf16x2(a.x, a.y); out.y = pack_bf16x2(a.z, a.w);
            out.z = pack_bf16x2(b.x, b.y); out.w = pack_bf16x2(b.z, b.w);
        }
        *(uint4*)(g_B + tile * 16384 + sw) = out;
    } else {
        long g2 = gid - NBC;
        if (g2 >= (long)BATCH * 8) return;
        int u = (int)(g2 >> 3), sub = (int)(g2 & 7);
        const float4* src = (const float4*)(ut + (long)user_id[u] * 64 + sub * 8);
        float4 a = src[0], b = src[1];
        uint4 out;
        out.x = pack_bf16x2(a.x, a.y); out.y = pack_bf16x2(a.z, a.w);
        out.z = pack_bf16x2(b.x, b.y); out.w = pack_bf16x2(b.z, b.w);
        *(uint4*)(g_A + (long)u * 128 + sub * 16) = out;
    }
}

// ================= Kernel 1: gather + MLP =================
__global__ void __launch_bounds__(256) mlp_kernel(
    const int* __restrict__ user_id, const int* __restrict__ movie_id,
    const float* __restrict__ ut, const float* __restrict__ ct,
    const float* __restrict__ W1, const float* __restrict__ b1,
    const float* __restrict__ W2, const float* __restrict__ b2,
    const float* __restrict__ W3, const float* __restrict__ b3,
    float* __restrict__ outUE, float* __restrict__ outCE, float* __restrict__ outR)
{
    __shared__ float xs[8][128];
    __shared__ float h1s[8][256];
    __shared__ float h2s[8][128];
    __shared__ int uid[8], mid[8];

    const int t = threadIdx.x;
    const int rbase = blockIdx.x * 8;

    if (t < 8) { uid[t] = user_id[rbase + t]; mid[t] = movie_id[rbase + t]; }
    __syncthreads();

    for (int idx = t; idx < 8 * 128; idx += 256) {
        int r = idx >> 7, k = idx & 127;
        float v;
        if (k < 64) {
            v = ut[(long)uid[r] * DIM + k];
            outUE[(long)(rbase + r) * DIM + k] = v;
        } else {
            v = ct[(long)mid[r] * DIM + (k - 64)];
            outCE[(long)(rbase + r) * DIM + (k - 64)] = v;
        }
        xs[r][k] = v;
    }
    __syncthreads();

    {
        float acc[8];
        float bb = b1[t];
        #pragma unroll
        for (int r = 0; r < 8; r++) acc[r] = bb;
        #pragma unroll 8
        for (int k = 0; k < 128; k++) {
            float w = W1[k * 256 + t];
            #pragma unroll
            for (int r = 0; r < 8; r++) acc[r] += xs[r][k] * w;
        }
        #pragma unroll
        for (int r = 0; r < 8; r++) h1s[r][t] = fmaxf(acc[r], 0.0f);
    }
    __syncthreads();

    if (t < 128) {
        float acc[8];
        float bb = b2[t];
        #pragma unroll
        for (int r = 0; r < 8; r++) acc[r] = bb;
        #pragma unroll 8
        for (int k = 0; k < 256; k++) {
            float w = W2[k * 128 + t];
            #pragma unroll
            for (int r = 0; r < 8; r++) acc[r] += h1s[r][k] * w;
        }
        #pragma unroll
        for (int r = 0; r < 8; r++) h2s[r][t] = fmaxf(acc[r], 0.0f);
    }
    __syncthreads();

    if (t < 8) {
        float s = b3[0];
        #pragma unroll 8
        for (int k = 0; k < 128; k++) s += h2s[t][k] * W3[k];
        outR[rbase + t] = s;
    }
}

// ================= Kernel 2: HMMA GEMM + register-sorted top-8 =================
// grid (8 rowtiles, 19 chunks) x 256 threads (8 warps). Warp w: rows w*16..w*16+15.
__global__ void __launch_bounds__(256, 1) gemm_topk_kernel()
{
    __shared__ __align__(1024) unsigned char sB[2][16384];

    const int tid = threadIdx.x;
    const int wid = tid >> 5;
    const int lane = tid & 31;
    const int rowtile = blockIdx.x;
    const int chunk = blockIdx.y;

    const int t_begin = chunk * 82 + min(chunk, 5);
    const int t_end = (chunk + 1) * 82 + min(chunk + 1, 5);
    const int ntiles = t_end - t_begin;

    const uint32_t sb0 = smem_u32(&sB[0][0]);
    const uint32_t sb1 = smem_u32(&sB[1][0]);

    // ---- stage A into sB[0], build register A-fragments ----
    {
        const uint4* asrc = (const uint4*)(g_A + (size_t)rowtile * 128 * 128);
        uint4* adst = (uint4*)&sB[0][0];
        #pragma unroll
        for (int p = 0; p < 4; p++)
            adst[p * 256 + tid] = asrc[p * 256 + tid];
    }
    __syncthreads();

    uint32_t af[4][4];
    {
        const int g2 = lane >> 3;
        const int mrow = wid * 16 + (g2 & 1) * 8 + (lane & 7);
        const int kb = (g2 >> 1) * 16;
        #pragma unroll
        for (int s = 0; s < 4; s++) {
            uint32_t addr = sb0 + (uint32_t)(mrow * 128 + s * 32 + kb);
            ldsm_x4(af[s][0], af[s][1], af[s][2], af[s][3], addr);
        }
    }
    __syncthreads();

    // ---- sorted top-8 per thread per row (descending; v[7] = current min) ----
    float vLo[K8], vHi[K8];
    int   iLo[K8], iHi[K8];
    #pragma unroll
    for (int j = 0; j < K8; j++) {
        vLo[j] = -CUDART_INF_F; vHi[j] = -CUDART_INF_F;
        iLo[j] = 0x7fffffff;    iHi[j] = 0x7fffffff;
    }

    const int bg2 = lane >> 3;
    const int b_nloc = ((bg2 >> 1) & 1) * 8 + (lane & 7);
    const int b_kb = (bg2 & 1) * 16;
    const int ccol = 2 * (lane & 3);

    // ---- prefetch tile 0 ----
    {
        const char* src = (const char*)(g_B + (size_t)t_begin * 16384);
        #pragma unroll
        for (int p = 0; p < 4; p++)
            CP_ASYNC16(sb0 + (uint32_t)(p * 4096 + tid * 16), src + p * 4096 + tid * 16);
        CP_COMMIT();
    }

    for (int i = 0; i < ntiles; i++) {
        if (i + 1 < ntiles) {
            const char* src = (const char*)(g_B + (size_t)(t_begin + i + 1) * 16384);
            uint32_t dst = ((i + 1) & 1) ? sb1 : sb0;
            #pragma unroll
            for (int p = 0; p < 4; p++)
                CP_ASYNC16(dst + (uint32_t)(p * 4096 + tid * 16), src + p * 4096 + tid * 16);
        }
        CP_COMMIT();
        CP_WAIT1();
        __syncthreads();

        const uint32_t bs = (i & 1) ? sb1 : sb0;
        const int tilec0 = (t_begin + i) * 128;

        #pragma unroll
        for (int half = 0; half < 2; half++) {
            float acc[8][4];
            #pragma unroll
            for (int j = 0; j < 8; j++)
                #pragma unroll
                for (int e = 0; e < 4; e++) acc[j][e] = 0.0f;

            #pragma unroll
            for (int s = 0; s < 4; s++) {
                #pragma unroll
                for (int p = 0; p < 4; p++) {
                    const int n = half * 64 + p * 16 + b_nloc;
                    uint32_t off = (uint32_t)(n * 128 + s * 32 + b_kb);
                    uint32_t b0, b1, b2, b3;
                    ldsm_x4(b0, b1, b2, b3, bs + sw128(off));
                    mma16816(acc[2 * p][0], acc[2 * p][1], acc[2 * p][2], acc[2 * p][3],
                             af[s][0], af[s][1], af[s][2], af[s][3], b0, b1);
                    mma16816(acc[2 * p + 1][0], acc[2 * p + 1][1], acc[2 * p + 1][2], acc[2 * p + 1][3],
                             af[s][0], af[s][1], af[s][2], af[s][3], b2, b3);
                }
            }

            const int cbase = tilec0 + half * 64;
            #pragma unroll
            for (int j = 0; j < 8; j++) {
                const int c0 = cbase + j * 8 + ccol;
                if (acc[j][0] > vLo[K8 - 1] && c0 < NCAND)     insN<K8>(acc[j][0], c0,     vLo, iLo);
                if (acc[j][1] > vLo[K8 - 1] && c0 + 1 < NCAND) insN<K8>(acc[j][1], c0 + 1, vLo, iLo);
                if (acc[j][2] > vHi[K8 - 1] && c0 < NCAND)     insN<K8>(acc[j][2], c0,     vHi, iHi);
                if (acc[j][3] > vHi[K8 - 1] && c0 + 1 < NCAND) insN<K8>(acc[j][3], c0 + 1, vHi, iHi);
            }
        }
        __syncthreads();
    }

    // ---- dump shortlists: [row][chunk][c*8 + j] ----
    {
        const int c = lane & 3;
        const int rowLo = rowtile * 128 + wid * 16 + (lane >> 2);
        const int rowHi = rowLo + 8;
        const long baseLo = ((long)rowLo * NCHUNKS + chunk) * (4 * K8) + c * K8;
        const long baseHi = ((long)rowHi * NCHUNKS + chunk) * (4 * K8) + c * K8;
        #pragma unroll
        for (int j = 0; j < K8; j++) {
            g_pv[baseLo + j] = vLo[j]; g_pi[baseLo + j] = iLo[j];
            g_pv[baseHi + j] = vHi[j]; g_pi[baseHi + j] = iHi[j];
        }
    }
}

// ================= Kernel 3: merge shortlists + exact fp32 rescore =================
__global__ void __launch_bounds__(256) merge_kernel(
    const int* __restrict__ user_id,
    const float* __restrict__ ut, const float* __restrict__ ct,
    float* __restrict__ outP)
{
    __shared__ float sv[8][32 * K8];
    __shared__ int   si[8][32 * K8];
    __shared__ float su[8][64];
    __shared__ int   sidx[8][16];
    __shared__ float ssc[8][16];

    const int wid = threadIdx.x >> 5;
    const int lane = threadIdx.x & 31;
    const int row = blockIdx.x * 8 + wid;

    const float* urow = ut + (long)user_id[row] * 64;
    su[wid][lane] = urow[lane];
    su[wid][lane + 32] = urow[lane + 32];

    // phase 1: lane-strided sorted top-8 (registers)
    float tv[K8]; int ti[K8];
    #pragma unroll
    for (int j = 0; j < K8; j++) { tv[j] = -CUDART_INF_F; ti[j] = 0x7fffffff; }
    const long rb = (long)row * NENT;
    for (int e = lane; e < NENT; e += 32) {
        float v = g_pv[rb + e];
        if (v > tv[K8 - 1]) {
            int idx = g_pi[rb + e];
            if (idx < NCAND) insN<K8>(v, idx, tv, ti);
        }
    }
    #pragma unroll
    for (int j = 0; j < K8; j++) {
        sv[wid][lane * K8 + j] = tv[j];
        si[wid][lane * K8 + j] = ti[j];
    }
    __syncwarp();

    // phase 2: lane 0 sorted top-16 over 256 entries (registers, constant-indexed)
    if (lane == 0) {
        float fv[16]; int fi[16];
        #pragma unroll
        for (int j = 0; j < 16; j++) { fv[j] = -CUDART_INF_F; fi[j] = 0x7fffffff; }
        for (int e = 0; e < 32 * K8; e++) {
            float v = sv[wid][e];
            if (v > fv[15]) insN<16>(v, si[wid][e], fv, fi);
        }
        #pragma unroll
        for (int j = 0; j < 16; j++) sidx[wid][j] = fi[j];
    }
    __syncwarp();

    // phase 3: exact fp32 rescore of 16-candidate shortlist
    if (lane < 16) {
        int c = sidx[wid][lane];
        float s = -CUDART_INF_F;
        if (c >= 0 && c < NCAND) {
            const float* crow = ct + (long)c * 64;
            s = 0.0f;
            #pragma unroll 8
            for (int k = 0; k < 64; k++) s += su[wid][k] * crow[k];
        }
        ssc[wid][lane] = s;
    }
    __syncwarp();

    // phase 4: sort top-10 (desc value, asc index) and write
    if (lane == 0) {
        float fv[16]; int fi[16];
        #pragma unroll
        for (int j = 0; j < 16; j++) { fv[j] = ssc[wid][j]; fi[j] = sidx[wid][j]; }
        for (int a = 0; a < TOPK; a++) {
            int best = a;
            for (int b = a + 1; b < 16; b++)
                if (fv[b] > fv[best] || (fv[b] == fv[best] && fi[b] < fi[best])) best = b;
            float v = fv[best]; fv[best] = fv[a]; fv[a] = v;
            int   i = fi[best]; fi[best] = fi[a]; fi[a] = i;
            outP[(long)row * TOPK + a] = (float)fi[a];
        }
    }
}

// ================= launch =================
extern "C" void kernel_launch(void* const* d_in, const int* in_sizes, int n_in,
                              void* d_out, int out_size)
{
    const int*   user_id  = (const int*)d_in[0];
    const int*   movie_id = (const int*)d_in[1];
    const float* ut       = (const float*)d_in[2];
    const float* ct       = (const float*)d_in[3];
    const float* W1       = (const float*)d_in[4];
    const float* b1       = (const float*)d_in[5];
    const float* W2       = (const float*)d_in[6];
    const float* b2       = (const float*)d_in[7];
    const float* W3       = (const float*)d_in[8];
    const float* b3       = (const float*)d_in[9];

    float* out   = (float*)d_out;
    float* outUE = out;
    float* outCE = out + BATCH * DIM;
    float* outR  = out + 2 * BATCH * DIM;
    float* outP  = out + 2 * BATCH * DIM + BATCH;

    const int convBlocks = (NT * 1024 + BATCH * 8 + 255) / 256;
    convert_kernel<<<convBlocks, 256>>>(ct, ut, user_id);

    mlp_kernel<<<BATCH / 8, 256>>>(user_id, movie_id, ut, ct,
                                   W1, b1, W2, b2, W3, b3,
                                   outUE, outCE, outR);

    dim3 g2(NROWT, NCHUNKS);
    gemm_topk_kernel<<<g2, 256>>>();

    merge_kernel<<<BATCH / 8, 256>>>(user_id, ut, ct, outP);
}

// round 6
// speedup vs baseline: 1.6428x; 1.0144x over previous
#include <cuda_runtime.h>
#include <cuda_bf16.h>
#include <math_constants.h>
#include <cstdint>
#include <cstring>

// ---------------- problem constants ----------------
#define BATCH   1024
#define DIM     64
#define NCAND   200000
#define TOPK    10
#define K8      8                  // per-thread shortlist size (sorted, in registers)
#define NT      1563               // ceil(200000/128) tiles of 128 cands
#define NCHUNKS 19                 // tile chunks  (8 x 19 = 152 CTAs)
#define NROWT   8                  // 1024/128 row tiles
#define NENT    (NCHUNKS * 4 * K8) // shortlist entries per row = 608

// ---------------- device scratch ----------------
static __device__ __align__(1024) unsigned char g_B[(size_t)NT * 16384];  // SW128-swizzled bf16 cand tiles [128c x 64k]
static __device__ __align__(128)  unsigned char g_A[(size_t)BATCH * 128]; // gathered bf16 user rows
static __device__ uint2 g_p[(size_t)BATCH * NENT];                        // packed (float bits, cand idx)

// ---------------- helpers ----------------
__device__ __forceinline__ uint32_t smem_u32(const void* p) {
    uint32_t a;
    asm("{ .reg .u64 t; cvta.to.shared.u64 t, %1; cvt.u32.u64 %0, t; }" : "=r"(a) : "l"(p));
    return a;
}
__device__ __forceinline__ uint32_t pack_bf16x2(float x, float y) {
    __nv_bfloat16 lo = __float2bfloat16(x);
    __nv_bfloat16 hi = __float2bfloat16(y);
    uint16_t lo16, hi16;
    memcpy(&lo16, &lo, 2);
    memcpy(&hi16, &hi, 2);
    return (uint32_t)lo16 | ((uint32_t)hi16 << 16);
}
__device__ __forceinline__ uint32_t sw128(uint32_t off) {
    return off ^ ((off >> 3) & 0x70);
}
__device__ __forceinline__ void ldsm_x4(uint32_t& r0, uint32_t& r1, uint32_t& r2, uint32_t& r3, uint32_t addr) {
    asm volatile("ldmatrix.sync.aligned.m8n8.x4.shared.b16 {%0,%1,%2,%3}, [%4];"
                 : "=r"(r0), "=r"(r1), "=r"(r2), "=r"(r3) : "r"(addr));
}
__device__ __forceinline__ void mma16816(float& d0, float& d1, float& d2, float& d3,
                                         uint32_t a0, uint32_t a1, uint32_t a2, uint32_t a3,
                                         uint32_t b0, uint32_t b1) {
    asm volatile("mma.sync.aligned.m16n8k16.row.col.f32.bf16.bf16.f32 "
                 "{%0,%1,%2,%3}, {%4,%5,%6,%7}, {%8,%9}, {%0,%1,%2,%3};"
                 : "+f"(d0), "+f"(d1), "+f"(d2), "+f"(d3)
                 : "r"(a0), "r"(a1), "r"(a2), "r"(a3), "r"(b0), "r"(b1));
}
#define CP_ASYNC16(smem, gptr) \
    asm volatile("cp.async.cg.shared.global [%0], [%1], 16;" :: "r"(smem), "l"(gptr))
#define CP_COMMIT() asm volatile("cp.async.commit_group;")
#define CP_WAIT1()  asm volatile("cp.async.wait_group 1;")

// Sorted-descending top-N insert, all constant indices after unroll (register-resident).
template<int N>
__device__ __forceinline__ void insN(float s, int ci, float* v, int* ix) {
    v[N - 1] = s; ix[N - 1] = ci;
    #pragma unroll
    for (int q = N - 1; q > 0; q--) {
        if (v[q] > v[q - 1]) {
            float tv = v[q]; v[q] = v[q - 1]; v[q - 1] = tv;
            int  ti = ix[q]; ix[q] = ix[q - 1]; ix[q - 1] = ti;
        }
    }
}

// ================= Kernel 0: convert & pre-tile (fp32 -> bf16, SW128) =================
__global__ void __launch_bounds__(256) convert_kernel(
    const float* __restrict__ ct, const float* __restrict__ ut,
    const int* __restrict__ user_id)
{
    const long NBC = (long)NT * 1024;   // 16B chunks in g_B
    long gid = (long)blockIdx.x * 256 + threadIdx.x;
    if (gid < NBC) {
        long tile = gid >> 10;
        int within = (int)(gid & 1023);
        int r = within >> 3, sub = within & 7;
        long c = tile * 128 + r;
        uint32_t sw = sw128((uint32_t)(r * 128 + sub * 16));
        uint4 out = make_uint4(0u, 0u, 0u, 0u);
        if (c < NCAND) {
            const float4* src = (const float4*)(ct + c * 64 + sub * 8);
            float4 a = src[0], b = src[1];
            out.x = pack_bf16x2(a.x, a.y); out.y = pack_bf16x2(a.z, a.w);
            out.z = pack_bf16x2(b.x, b.y); out.w = pack_bf16x2(b.z, b.w);
        }
        *(uint4*)(g_B + tile * 16384 + sw) = out;
    } else {
        long g2 = gid - NBC;
        if (g2 >= (long)BATCH * 8) return;
        int u = (int)(g2 >> 3), sub = (int)(g2 & 7);
        const float4* src = (const float4*)(ut + (long)user_id[u] * 64 + sub * 8);
        float4 a = src[0], b = src[1];
        uint4 out;
        out.x = pack_bf16x2(a.x, a.y); out.y = pack_bf16x2(a.z, a.w);
        out.z = pack_bf16x2(b.x, b.y); out.w = pack_bf16x2(b.z, b.w);
        *(uint4*)(g_A + (long)u * 128 + sub * 16) = out;
    }
}

// ================= Kernel 1: gather + MLP (256 blocks x 4 rows) =================
__global__ void __launch_bounds__(256) mlp_kernel(
    const int* __restrict__ user_id, const int* __restrict__ movie_id,
    const float* __restrict__ ut, const float* __restrict__ ct,
    const float* __restrict__ W1, const float* __restrict__ b1,
    const float* __restrict__ W2, const float* __restrict__ b2,
    const float* __restrict__ W3, const float* __restrict__ b3,
    float* __restrict__ outUE, float* __restrict__ outCE, float* __restrict__ outR)
{
    __shared__ float xs[4][128];
    __shared__ float h1s[4][256];
    __shared__ float h2s[4][128];
    __shared__ int uid[4], mid[4];

    const int t = threadIdx.x;
    const int rbase = blockIdx.x * 4;

    if (t < 4) { uid[t] = user_id[rbase + t]; mid[t] = movie_id[rbase + t]; }
    __syncthreads();

    for (int idx = t; idx < 4 * 128; idx += 256) {
        int r = idx >> 7, k = idx & 127;
        float v;
        if (k < 64) {
            v = ut[(long)uid[r] * DIM + k];
            outUE[(long)(rbase + r) * DIM + k] = v;
        } else {
            v = ct[(long)mid[r] * DIM + (k - 64)];
            outCE[(long)(rbase + r) * DIM + (k - 64)] = v;
        }
        xs[r][k] = v;
    }
    __syncthreads();

    {
        float acc[4];
        float bb = b1[t];
        #pragma unroll
        for (int r = 0; r < 4; r++) acc[r] = bb;
        #pragma unroll 8
        for (int k = 0; k < 128; k++) {
            float w = W1[k * 256 + t];
            #pragma unroll
            for (int r = 0; r < 4; r++) acc[r] += xs[r][k] * w;
        }
        #pragma unroll
        for (int r = 0; r < 4; r++) h1s[r][t] = fmaxf(acc[r], 0.0f);
    }
    __syncthreads();

    if (t < 128) {
        float acc[4];
        float bb = b2[t];
        #pragma unroll
        for (int r = 0; r < 4; r++) acc[r] = bb;
        #pragma unroll 8
        for (int k = 0; k < 256; k++) {
            float w = W2[k * 128 + t];
            #pragma unroll
            for (int r = 0; r < 4; r++) acc[r] += h1s[r][k] * w;
        }
        #pragma unroll
        for (int r = 0; r < 4; r++) h2s[r][t] = fmaxf(acc[r], 0.0f);
    }
    __syncthreads();

    if (t < 4) {
        float s = b3[0];
        #pragma unroll 8
        for (int k = 0; k < 128; k++) s += h2s[t][k] * W3[k];
        outR[rbase + t] = s;
    }
}

// ================= Kernel 2: HMMA GEMM + screened register top-8 =================
// grid (8 rowtiles, 19 chunks) x 256 threads (8 warps). Warp w: rows w*16..w*16+15.
__global__ void __launch_bounds__(256, 1) gemm_topk_kernel()
{
    __shared__ __align__(1024) unsigned char sB[2][16384];

    const int tid = threadIdx.x;
    const int wid = tid >> 5;
    const int lane = tid & 31;
    const int rowtile = blockIdx.x;
    const int chunk = blockIdx.y;

    const int t_begin = chunk * 82 + min(chunk, 5);
    const int t_end = (chunk + 1) * 82 + min(chunk + 1, 5);
    const int ntiles = t_end - t_begin;

    const uint32_t sb0 = smem_u32(&sB[0][0]);
    const uint32_t sb1 = smem_u32(&sB[1][0]);

    // ---- stage A into sB[0], build register A-fragments ----
    {
        const uint4* asrc = (const uint4*)(g_A + (size_t)rowtile * 128 * 128);
        uint4* adst = (uint4*)&sB[0][0];
        #pragma unroll
        for (int p = 0; p < 4; p++)
            adst[p * 256 + tid] = asrc[p * 256 + tid];
    }
    __syncthreads();

    uint32_t af[4][4];
    {
        const int g2 = lane >> 3;
        const int mrow = wid * 16 + (g2 & 1) * 8 + (lane & 7);
        const int kb = (g2 >> 1) * 16;
        #pragma unroll
        for (int s = 0; s < 4; s++) {
            uint32_t addr = sb0 + (uint32_t)(mrow * 128 + s * 32 + kb);
            ldsm_x4(af[s][0], af[s][1], af[s][2], af[s][3], addr);
        }
    }
    __syncthreads();

    // ---- sorted top-8 per thread per row-half (descending; [7] = current min) ----
    float vLo[K8], vHi[K8];
    int   iLo[K8], iHi[K8];
    #pragma unroll
    for (int j = 0; j < K8; j++) {
        vLo[j] = -CUDART_INF_F; vHi[j] = -CUDART_INF_F;
        iLo[j] = 0x7fffffff;    iHi[j] = 0x7fffffff;
    }

    const int bg2 = lane >> 3;
    const int b_nloc = ((bg2 >> 1) & 1) * 8 + (lane & 7);
    const int b_kb = (bg2 & 1) * 16;
    const int ccol = 2 * (lane & 3);

    // ---- prefetch tile 0 ----
    {
        const char* src = (const char*)(g_B + (size_t)t_begin * 16384);
        #pragma unroll
        for (int p = 0; p < 4; p++)
            CP_ASYNC16(sb0 + (uint32_t)(p * 4096 + tid * 16), src + p * 4096 + tid * 16);
        CP_COMMIT();
    }

    for (int i = 0; i < ntiles; i++) {
        if (i + 1 < ntiles) {
            const char* src = (const char*)(g_B + (size_t)(t_begin + i + 1) * 16384);
            uint32_t dst = ((i + 1) & 1) ? sb1 : sb0;
            #pragma unroll
            for (int p = 0; p < 4; p++)
                CP_ASYNC16(dst + (uint32_t)(p * 4096 + tid * 16), src + p * 4096 + tid * 16);
        }
        CP_COMMIT();
        CP_WAIT1();
        __syncthreads();

        const uint32_t bs = (i & 1) ? sb1 : sb0;
        const int tilec0 = (t_begin + i) * 128;

        #pragma unroll
        for (int half = 0; half < 2; half++) {
            float acc[8][4];
            #pragma unroll
            for (int j = 0; j < 8; j++)
                #pragma unroll
                for (int e = 0; e < 4; e++) acc[j][e] = 0.0f;

            #pragma unroll
            for (int s = 0; s < 4; s++) {
                #pragma unroll
                for (int p = 0; p < 4; p++) {
                    const int n = half * 64 + p * 16 + b_nloc;
                    uint32_t off = (uint32_t)(n * 128 + s * 32 + b_kb);
                    uint32_t b0, b1, b2, b3;
                    ldsm_x4(b0, b1, b2, b3, bs + sw128(off));
                    mma16816(acc[2 * p][0], acc[2 * p][1], acc[2 * p][2], acc[2 * p][3],
                             af[s][0], af[s][1], af[s][2], af[s][3], b0, b1);
                    mma16816(acc[2 * p + 1][0], acc[2 * p + 1][1], acc[2 * p + 1][2], acc[2 * p + 1][3],
                             af[s][0], af[s][1], af[s][2], af[s][3], b2, b3);
                }
            }

            const int cbase = tilec0 + half * 64;

            // ---- screening maxes (branch-free), then ONE branch per row-half ----
            float mLo = acc[0][0], mHi = acc[0][2];
            #pragma unroll
            for (int j = 0; j < 8; j++) {
                mLo = fmaxf(mLo, fmaxf(acc[j][0], acc[j][1]));
                mHi = fmaxf(mHi, fmaxf(acc[j][2], acc[j][3]));
            }
            if (mLo > vLo[K8 - 1]) {
                #pragma unroll
                for (int j = 0; j < 8; j++) {
                    const int c0 = cbase + j * 8 + ccol;
                    if (acc[j][0] > vLo[K8 - 1] && c0 < NCAND)     insN<K8>(acc[j][0], c0,     vLo, iLo);
                    if (acc[j][1] > vLo[K8 - 1] && c0 + 1 < NCAND) insN<K8>(acc[j][1], c0 + 1, vLo, iLo);
                }
            }
            if (mHi > vHi[K8 - 1]) {
                #pragma unroll
                for (int j = 0; j < 8; j++) {
                    const int c0 = cbase + j * 8 + ccol;
                    if (acc[j][2] > vHi[K8 - 1] && c0 < NCAND)     insN<K8>(acc[j][2], c0,     vHi, iHi);
                    if (acc[j][3] > vHi[K8 - 1] && c0 + 1 < NCAND) insN<K8>(acc[j][3], c0 + 1, vHi, iHi);
                }
            }
        }
        __syncthreads();
    }

    // ---- dump shortlists: [row][chunk][c*8 + j] packed ----
    {
        const int c = lane & 3;
        const int rowLo = rowtile * 128 + wid * 16 + (lane >> 2);
        const int rowHi = rowLo + 8;
        const long baseLo = ((long)rowLo * NCHUNKS + chunk) * (4 * K8) + c * K8;
        const long baseHi = ((long)rowHi * NCHUNKS + chunk) * (4 * K8) + c * K8;
        #pragma unroll
        for (int j = 0; j < K8; j++) {
            g_p[baseLo + j] = make_uint2(__float_as_uint(vLo[j]), (uint32_t)iLo[j]);
            g_p[baseHi + j] = make_uint2(__float_as_uint(vHi[j]), (uint32_t)iHi[j]);
        }
    }
}

// ================= Kernel 3: merge shortlists + exact fp32 rescore =================
__global__ void __launch_bounds__(256) merge_kernel(
    const int* __restrict__ user_id,
    const float* __restrict__ ut, const float* __restrict__ ct,
    float* __restrict__ outP)
{
    __shared__ float su[8][64];
    __shared__ int   sidx[8][16];
    __shared__ float ssc[8][16];

    const int wid = threadIdx.x >> 5;
    const int lane = threadIdx.x & 31;
    const int row = blockIdx.x * 8 + wid;

    const float* urow = ut + (long)user_id[row] * 64;
    su[wid][lane] = urow[lane];
    su[wid][lane + 32] = urow[lane + 32];

    // phase 1: lane-strided sorted top-8 (registers) over packed entries
    float tv[K8]; int ti[K8];
    #pragma unroll
    for (int j = 0; j < K8; j++) { tv[j] = -CUDART_INF_F; ti[j] = 0x7fffffff; }
    const long rb = (long)row * NENT;
    for (int e = lane; e < NENT; e += 32) {
        uint2 pv = g_p[rb + e];
        float v = __uint_as_float(pv.x);
        if (v > tv[K8 - 1]) {
            int idx = (int)pv.y;
            if (idx < NCAND) insN<K8>(v, idx, tv, ti);
        }
    }

    // phase 2: warp-cooperative 16-round max extraction from per-lane sorted lists
    {
        float h = tv[0];
        #pragma unroll 1
        for (int r = 0; r < 16; r++) {
            float m = h;
            #pragma unroll
            for (int d = 16; d > 0; d >>= 1)
                m = fmaxf(m, __shfl_xor_sync(0xFFFFFFFFu, m, d));
            unsigned msk = __ballot_sync(0xFFFFFFFFu, h == m);
            int owner = __ffs(msk) - 1;
            if (lane == owner) {
                sidx[wid][r] = ti[0];
                #pragma unroll
                for (int q = 0; q < K8 - 1; q++) { tv[q] = tv[q + 1]; ti[q] = ti[q + 1]; }
                tv[K8 - 1] = -CUDART_INF_F;
                h = tv[0];
            }
        }
    }
    __syncwarp();

    // phase 3: exact fp32 rescore of 16-candidate shortlist
    if (lane < 16) {
        int c = sidx[wid][lane];
        float s = -CUDART_INF_F;
        if (c >= 0 && c < NCAND) {
            const float* crow = ct + (long)c * 64;
            s = 0.0f;
            #pragma unroll 8
            for (int k = 0; k < 64; k++) s += su[wid][k] * crow[k];
        }
        ssc[wid][lane] = s;
    }
    __syncwarp();

    // phase 4: sort top-10 (desc value, asc index) and write
    if (lane == 0) {
        float fv[16]; int fi[16];
        #pragma unroll
        for (int j = 0; j < 16; j++) { fv[j] = ssc[wid][j]; fi[j] = sidx[wid][j]; }
        for (int a = 0; a < TOPK; a++) {
            int best = a;
            for (int b = a + 1; b < 16; b++)
                if (fv[b] > fv[best] || (fv[b] == fv[best] && fi[b] < fi[best])) best = b;
            float v = fv[best]; fv[best] = fv[a]; fv[a] = v;
            int   i = fi[best]; fi[best] = fi[a]; fi[a] = i;
            outP[(long)row * TOPK + a] = (float)fi[a];
        }
    }
}

// ================= launch =================
extern "C" void kernel_launch(void* const* d_in, const int* in_sizes, int n_in,
                              void* d_out, int out_size)
{
    const int*   user_id  = (const int*)d_in[0];
    const int*   movie_id = (const int*)d_in[1];
    const float* ut       = (const float*)d_in[2];
    const float* ct       = (const float*)d_in[3];
    const float* W1       = (const float*)d_in[4];
    const float* b1       = (const float*)d_in[5];
    const float* W2       = (const float*)d_in[6];
    const float* b2       = (const float*)d_in[7];
    const float* W3       = (const float*)d_in[8];
    const float* b3       = (const float*)d_in[9];

    float* out   = (float*)d_out;
    float* outUE = out;
    float* outCE = out + BATCH * DIM;
    float* outR  = out + 2 * BATCH * DIM;
    float* outP  = out + 2 * BATCH * DIM + BATCH;

    const int convBlocks = (NT * 1024 + BATCH * 8 + 255) / 256;
    convert_kernel<<<convBlocks, 256>>>(ct, ut, user_id);

    mlp_kernel<<<BATCH / 4, 256>>>(user_id, movie_id, ut, ct,
                                   W1, b1, W2, b2, W3, b3,
                                   outUE, outCE, outR);

    dim3 g2(NROWT, NCHUNKS);
    gemm_topk_kernel<<<g2, 256>>>();

    merge_kernel<<<BATCH / 8, 256>>>(user_id, ut, ct, outP);
}

// round 7
// speedup vs baseline: 2.3189x; 1.4116x over previous
#include <cuda_runtime.h>
#include <cuda_bf16.h>
#include <math_constants.h>
#include <cstdint>
#include <cstring>

// ---------------- problem constants ----------------
#define BATCH   1024
#define DIM     64
#define NCAND   200000
#define TOPK    10
#define K8      8                  // per-thread shortlist size (sorted, in registers)
#define NT      1563               // ceil(200000/128) tiles of 128 cands
#define NCHUNKS 38                 // tile chunks  (8 x 38 = 304 CTAs ~ 2/SM)
#define NROWT   8                  // 1024/128 row tiles
#define NENT    (NCHUNKS * 4 * K8) // shortlist entries per row = 1216

// ---------------- device scratch ----------------
static __device__ __align__(1024) unsigned char g_B[(size_t)NT * 16384];  // SW128-swizzled bf16 cand tiles [128c x 64k]
static __device__ __align__(128)  unsigned char g_A[(size_t)BATCH * 128]; // gathered bf16 user rows
static __device__ uint2 g_p[(size_t)BATCH * NENT];                        // packed (float bits, cand idx)

// ---------------- helpers ----------------
__device__ __forceinline__ uint32_t smem_u32(const void* p) {
    uint32_t a;
    asm("{ .reg .u64 t; cvta.to.shared.u64 t, %1; cvt.u32.u64 %0, t; }" : "=r"(a) : "l"(p));
    return a;
}
__device__ __forceinline__ uint32_t pack_bf16x2(float x, float y) {
    __nv_bfloat16 lo = __float2bfloat16(x);
    __nv_bfloat16 hi = __float2bfloat16(y);
    uint16_t lo16, hi16;
    memcpy(&lo16, &lo, 2);
    memcpy(&hi16, &hi, 2);
    return (uint32_t)lo16 | ((uint32_t)hi16 << 16);
}
__device__ __forceinline__ uint32_t sw128(uint32_t off) {
    return off ^ ((off >> 3) & 0x70);
}
__device__ __forceinline__ void ldsm_x4(uint32_t& r0, uint32_t& r1, uint32_t& r2, uint32_t& r3, uint32_t addr) {
    asm volatile("ldmatrix.sync.aligned.m8n8.x4.shared.b16 {%0,%1,%2,%3}, [%4];"
                 : "=r"(r0), "=r"(r1), "=r"(r2), "=r"(r3) : "r"(addr));
}
__device__ __forceinline__ void mma16816(float& d0, float& d1, float& d2, float& d3,
                                         uint32_t a0, uint32_t a1, uint32_t a2, uint32_t a3,
                                         uint32_t b0, uint32_t b1) {
    asm volatile("mma.sync.aligned.m16n8k16.row.col.f32.bf16.bf16.f32 "
                 "{%0,%1,%2,%3}, {%4,%5,%6,%7}, {%8,%9}, {%0,%1,%2,%3};"
                 : "+f"(d0), "+f"(d1), "+f"(d2), "+f"(d3)
                 : "r"(a0), "r"(a1), "r"(a2), "r"(a3), "r"(b0), "r"(b1));
}
#define CP_ASYNC16(smem, gptr) \
    asm volatile("cp.async.cg.shared.global [%0], [%1], 16;" :: "r"(smem), "l"(gptr))
#define CP_COMMIT() asm volatile("cp.async.commit_group;")
#define CP_WAIT1()  asm volatile("cp.async.wait_group 1;")

// Sorted-descending top-N insert, all constant indices after unroll (register-resident).
template<int N>
__device__ __forceinline__ void insN(float s, int ci, float* v, int* ix) {
    v[N - 1] = s; ix[N - 1] = ci;
    #pragma unroll
    for (int q = N - 1; q > 0; q--) {
        if (v[q] > v[q - 1]) {
            float tv = v[q]; v[q] = v[q - 1]; v[q - 1] = tv;
            int  ti = ix[q]; ix[q] = ix[q - 1]; ix[q - 1] = ti;
        }
    }
}

// ================= Kernel 0: convert & pre-tile (fp32 -> bf16, SW128) =================
__global__ void __launch_bounds__(256) convert_kernel(
    const float* __restrict__ ct, const float* __restrict__ ut,
    const int* __restrict__ user_id)
{
    const long NBC = (long)NT * 1024;   // 16B chunks in g_B
    long gid = (long)blockIdx.x * 256 + threadIdx.x;
    if (gid < NBC) {
        long tile = gid >> 10;
        int within = (int)(gid & 1023);
        int r = within >> 3, sub = within & 7;
        long c = tile * 128 + r;
        uint32_t sw = sw128((uint32_t)(r * 128 + sub * 16));
        uint4 out = make_uint4(0u, 0u, 0u, 0u);
        if (c < NCAND) {
            const float4* src = (const float4*)(ct + c * 64 + sub * 8);
            float4 a = src[0], b = src[1];
            out.x = pack_bf16x2(a.x, a.y); out.y = pack_bf16x2(a.z, a.w);
            out.z = pack_bf16x2(b.x, b.y); out.w = pack_bf16x2(b.z, b.w);
        }
        *(uint4*)(g_B + tile * 16384 + sw) = out;
    } else {
        long g2 = gid - NBC;
        if (g2 >= (long)BATCH * 8) return;
        int u = (int)(g2 >> 3), sub = (int)(g2 & 7);
        const float4* src = (const float4*)(ut + (long)user_id[u] * 64 + sub * 8);
        float4 a = src[0], b = src[1];
        uint4 out;
        out.x = pack_bf16x2(a.x, a.y); out.y = pack_bf16x2(a.z, a.w);
        out.z = pack_bf16x2(b.x, b.y); out.w = pack_bf16x2(b.z, b.w);
        *(uint4*)(g_A + (long)u * 128 + sub * 16) = out;
    }
}

// ================= Kernel 1: gather + MLP (256 blocks x 4 rows) =================
__global__ void __launch_bounds__(256) mlp_kernel(
    const int* __restrict__ user_id, const int* __restrict__ movie_id,
    const float* __restrict__ ut, const float* __restrict__ ct,
    const float* __restrict__ W1, const float* __restrict__ b1,
    const float* __restrict__ W2, const float* __restrict__ b2,
    const float* __restrict__ W3, const float* __restrict__ b3,
    float* __restrict__ outUE, float* __restrict__ outCE, float* __restrict__ outR)
{
    __shared__ float xs[4][128];
    __shared__ float h1s[4][256];
    __shared__ float h2s[4][128];
    __shared__ int uid[4], mid[4];

    const int t = threadIdx.x;
    const int rbase = blockIdx.x * 4;

    if (t < 4) { uid[t] = user_id[rbase + t]; mid[t] = movie_id[rbase + t]; }
    __syncthreads();

    for (int idx = t; idx < 4 * 128; idx += 256) {
        int r = idx >> 7, k = idx & 127;
        float v;
        if (k < 64) {
            v = ut[(long)uid[r] * DIM + k];
            outUE[(long)(rbase + r) * DIM + k] = v;
        } else {
            v = ct[(long)mid[r] * DIM + (k - 64)];
            outCE[(long)(rbase + r) * DIM + (k - 64)] = v;
        }
        xs[r][k] = v;
    }
    __syncthreads();

    {
        float acc[4];
        float bb = b1[t];
        #pragma unroll
        for (int r = 0; r < 4; r++) acc[r] = bb;
        #pragma unroll 8
        for (int k = 0; k < 128; k++) {
            float w = W1[k * 256 + t];
            #pragma unroll
            for (int r = 0; r < 4; r++) acc[r] += xs[r][k] * w;
        }
        #pragma unroll
        for (int r = 0; r < 4; r++) h1s[r][t] = fmaxf(acc[r], 0.0f);
    }
    __syncthreads();

    if (t < 128) {
        float acc[4];
        float bb = b2[t];
        #pragma unroll
        for (int r = 0; r < 4; r++) acc[r] = bb;
        #pragma unroll 8
        for (int k = 0; k < 256; k++) {
            float w = W2[k * 128 + t];
            #pragma unroll
            for (int r = 0; r < 4; r++) acc[r] += h1s[r][k] * w;
        }
        #pragma unroll
        for (int r = 0; r < 4; r++) h2s[r][t] = fmaxf(acc[r], 0.0f);
    }
    __syncthreads();

    if (t < 4) {
        float s = b3[0];
        #pragma unroll 8
        for (int k = 0; k < 128; k++) s += h2s[t][k] * W3[k];
        outR[rbase + t] = s;
    }
}

// ================= Kernel 2: HMMA GEMM + screened register top-8 =================
// grid (8 rowtiles, 38 chunks) x 256 threads (8 warps), 2 CTAs/SM.
__global__ void __launch_bounds__(256, 2) gemm_topk_kernel()
{
    __shared__ __align__(1024) unsigned char sB[2][16384];

    const int tid = threadIdx.x;
    const int wid = tid >> 5;
    const int lane = tid & 31;
    const int rowtile = blockIdx.x;
    const int chunk = blockIdx.y;

    const int t_begin = chunk * 41 + min(chunk, 5);
    const int t_end = (chunk + 1) * 41 + min(chunk + 1, 5);
    const int ntiles = t_end - t_begin;

    const uint32_t sb0 = smem_u32(&sB[0][0]);
    const uint32_t sb1 = smem_u32(&sB[1][0]);

    // ---- stage A into sB[0], build register A-fragments ----
    {
        const uint4* asrc = (const uint4*)(g_A + (size_t)rowtile * 128 * 128);
        uint4* adst = (uint4*)&sB[0][0];
        #pragma unroll
        for (int p = 0; p < 4; p++)
            adst[p * 256 + tid] = asrc[p * 256 + tid];
    }
    __syncthreads();

    uint32_t af[4][4];
    {
        const int g2 = lane >> 3;
        const int mrow = wid * 16 + (g2 & 1) * 8 + (lane & 7);
        const int kb = (g2 >> 1) * 16;
        #pragma unroll
        for (int s = 0; s < 4; s++) {
            uint32_t addr = sb0 + (uint32_t)(mrow * 128 + s * 32 + kb);
            ldsm_x4(af[s][0], af[s][1], af[s][2], af[s][3], addr);
        }
    }
    __syncthreads();

    // ---- sorted top-8 per thread per row-half (descending; [7] = current min) ----
    float vLo[K8], vHi[K8];
    int   iLo[K8], iHi[K8];
    #pragma unroll
    for (int j = 0; j < K8; j++) {
        vLo[j] = -CUDART_INF_F; vHi[j] = -CUDART_INF_F;
        iLo[j] = 0x7fffffff;    iHi[j] = 0x7fffffff;
    }

    const int bg2 = lane >> 3;
    const int b_nloc = ((bg2 >> 1) & 1) * 8 + (lane & 7);
    const int b_kb = (bg2 & 1) * 16;
    const int ccol = 2 * (lane & 3);

    // ---- prefetch tile 0 ----
    {
        const char* src = (const char*)(g_B + (size_t)t_begin * 16384);
        #pragma unroll
        for (int p = 0; p < 4; p++)
            CP_ASYNC16(sb0 + (uint32_t)(p * 4096 + tid * 16), src + p * 4096 + tid * 16);
        CP_COMMIT();
    }

    for (int i = 0; i < ntiles; i++) {
        if (i + 1 < ntiles) {
            const char* src = (const char*)(g_B + (size_t)(t_begin + i + 1) * 16384);
            uint32_t dst = ((i + 1) & 1) ? sb1 : sb0;
            #pragma unroll
            for (int p = 0; p < 4; p++)
                CP_ASYNC16(dst + (uint32_t)(p * 4096 + tid * 16), src + p * 4096 + tid * 16);
        }
        CP_COMMIT();
        CP_WAIT1();
        __syncthreads();

        const uint32_t bs = (i & 1) ? sb1 : sb0;
        const int tilec0 = (t_begin + i) * 128;

        // 4 quarters of 32 candidates: acc[4][4] keeps live regs low (2 CTAs/SM)
        #pragma unroll
        for (int q = 0; q < 4; q++) {
            float acc[4][4];
            #pragma unroll
            for (int j = 0; j < 4; j++)
                #pragma unroll
                for (int e = 0; e < 4; e++) acc[j][e] = 0.0f;

            #pragma unroll
            for (int s = 0; s < 4; s++) {
                #pragma unroll
                for (int p = 0; p < 2; p++) {
                    const int n = q * 32 + p * 16 + b_nloc;
                    uint32_t off = (uint32_t)(n * 128 + s * 32 + b_kb);
                    uint32_t b0, b1, b2, b3;
                    ldsm_x4(b0, b1, b2, b3, bs + sw128(off));
                    mma16816(acc[2 * p][0], acc[2 * p][1], acc[2 * p][2], acc[2 * p][3],
                             af[s][0], af[s][1], af[s][2], af[s][3], b0, b1);
                    mma16816(acc[2 * p + 1][0], acc[2 * p + 1][1], acc[2 * p + 1][2], acc[2 * p + 1][3],
                             af[s][0], af[s][1], af[s][2], af[s][3], b2, b3);
                }
            }

            const int cbase = tilec0 + q * 32;

            // screening maxes (branch-free), then ONE branch per row-half
            float mLo = acc[0][0], mHi = acc[0][2];
            #pragma unroll
            for (int j = 0; j < 4; j++) {
                mLo = fmaxf(mLo, fmaxf(acc[j][0], acc[j][1]));
                mHi = fmaxf(mHi, fmaxf(acc[j][2], acc[j][3]));
            }
            if (mLo > vLo[K8 - 1]) {
                #pragma unroll
                for (int j = 0; j < 4; j++) {
                    const int c0 = cbase + j * 8 + ccol;
                    if (acc[j][0] > vLo[K8 - 1]) insN<K8>(acc[j][0], c0,     vLo, iLo);
                    if (acc[j][1] > vLo[K8 - 1]) insN<K8>(acc[j][1], c0 + 1, vLo, iLo);
                }
            }
            if (mHi > vHi[K8 - 1]) {
                #pragma unroll
                for (int j = 0; j < 4; j++) {
                    const int c0 = cbase + j * 8 + ccol;
                    if (acc[j][2] > vHi[K8 - 1]) insN<K8>(acc[j][2], c0,     vHi, iHi);
                    if (acc[j][3] > vHi[K8 - 1]) insN<K8>(acc[j][3], c0 + 1, vHi, iHi);
                }
            }
        }
        __syncthreads();
    }

    // ---- dump shortlists: [row][chunk][c*8 + j] packed ----
    {
        const int c = lane & 3;
        const int rowLo = rowtile * 128 + wid * 16 + (lane >> 2);
        const int rowHi = rowLo + 8;
        const long baseLo = ((long)rowLo * NCHUNKS + chunk) * (4 * K8) + c * K8;
        const long baseHi = ((long)rowHi * NCHUNKS + chunk) * (4 * K8) + c * K8;
        #pragma unroll
        for (int j = 0; j < K8; j++) {
            g_p[baseLo + j] = make_uint2(__float_as_uint(vLo[j]), (uint32_t)iLo[j]);
            g_p[baseHi + j] = make_uint2(__float_as_uint(vHi[j]), (uint32_t)iHi[j]);
        }
    }
}

// ================= Kernel 3: merge shortlists + exact fp32 rescore =================
__global__ void __launch_bounds__(256) merge_kernel(
    const int* __restrict__ user_id,
    const float* __restrict__ ut, const float* __restrict__ ct,
    float* __restrict__ outP)
{
    __shared__ float su[8][64];
    __shared__ int   sidx[8][16];
    __shared__ float ssc[8][16];

    const int wid = threadIdx.x >> 5;
    const int lane = threadIdx.x & 31;
    const int row = blockIdx.x * 8 + wid;

    const float* urow = ut + (long)user_id[row] * 64;
    su[wid][lane] = urow[lane];
    su[wid][lane + 32] = urow[lane + 32];

    // phase 1: lane-strided sorted top-8 (registers) over packed entries
    float tv[K8]; int ti[K8];
    #pragma unroll
    for (int j = 0; j < K8; j++) { tv[j] = -CUDART_INF_F; ti[j] = 0x7fffffff; }
    const long rb = (long)row * NENT;
    for (int e = lane; e < NENT; e += 32) {
        uint2 pv = g_p[rb + e];
        float v = __uint_as_float(pv.x);
        if (v > tv[K8 - 1]) {
            int idx = (int)pv.y;
            if (idx < NCAND) insN<K8>(v, idx, tv, ti);
        }
    }

    // phase 2: warp-cooperative 16-round max extraction from per-lane sorted lists
    {
        float h = tv[0];
        #pragma unroll 1
        for (int r = 0; r < 16; r++) {
            float m = h;
            #pragma unroll
            for (int d = 16; d > 0; d >>= 1)
                m = fmaxf(m, __shfl_xor_sync(0xFFFFFFFFu, m, d));
            unsigned msk = __ballot_sync(0xFFFFFFFFu, h == m);
            int owner = __ffs(msk) - 1;
            if (lane == owner) {
                sidx[wid][r] = ti[0];
                #pragma unroll
                for (int q = 0; q < K8 - 1; q++) { tv[q] = tv[q + 1]; ti[q] = ti[q + 1]; }
                tv[K8 - 1] = -CUDART_INF_F;
                h = tv[0];
            }
        }
    }
    __syncwarp();

    // phase 3: exact fp32 rescore of 16-candidate shortlist
    if (lane < 16) {
        int c = sidx[wid][lane];
        float s = -CUDART_INF_F;
        if (c >= 0 && c < NCAND) {
            const float* crow = ct + (long)c * 64;
            s = 0.0f;
            #pragma unroll 8
            for (int k = 0; k < 64; k++) s += su[wid][k] * crow[k];
        }
        ssc[wid][lane] = s;
    }
    __syncwarp();

    // phase 4: sort top-10 (desc value, asc index) and write
    if (lane == 0) {
        float fv[16]; int fi[16];
        #pragma unroll
        for (int j = 0; j < 16; j++) { fv[j] = ssc[wid][j]; fi[j] = sidx[wid][j]; }
        for (int a = 0; a < TOPK; a++) {
            int best = a;
            for (int b = a + 1; b < 16; b++)
                if (fv[b] > fv[best] || (fv[b] == fv[best] && fi[b] < fi[best])) best = b;
            float v = fv[best]; fv[best] = fv[a]; fv[a] = v;
            int   i = fi[best]; fi[best] = fi[a]; fi[a] = i;
            outP[(long)row * TOPK + a] = (float)fi[a];
        }
    }
}

// ================= launch =================
extern "C" void kernel_launch(void* const* d_in, const int* in_sizes, int n_in,
                              void* d_out, int out_size)
{
    const int*   user_id  = (const int*)d_in[0];
    const int*   movie_id = (const int*)d_in[1];
    const float* ut       = (const float*)d_in[2];
    const float* ct       = (const float*)d_in[3];
    const float* W1       = (const float*)d_in[4];
    const float* b1       = (const float*)d_in[5];
    const float* W2       = (const float*)d_in[6];
    const float* b2       = (const float*)d_in[7];
    const float* W3       = (const float*)d_in[8];
    const float* b3       = (const float*)d_in[9];

    float* out   = (float*)d_out;
    float* outUE = out;
    float* outCE = out + BATCH * DIM;
    float* outR  = out + 2 * BATCH * DIM;
    float* outP  = out + 2 * BATCH * DIM + BATCH;

    const int convBlocks = (NT * 1024 + BATCH * 8 + 255) / 256;
    convert_kernel<<<convBlocks, 256>>>(ct, ut, user_id);

    mlp_kernel<<<BATCH / 4, 256>>>(user_id, movie_id, ut, ct,
                                   W1, b1, W2, b2, W3, b3,
                                   outUE, outCE, outR);

    dim3 g2(NROWT, NCHUNKS);
    gemm_topk_kernel<<<g2, 256>>>();

    merge_kernel<<<BATCH / 8, 256>>>(user_id, ut, ct, outP);
}

// round 9
// speedup vs baseline: 2.4124x; 1.0403x over previous
#include <cuda_runtime.h>
#include <cuda_bf16.h>
#include <math_constants.h>
#include <cstdint>
#include <cstring>

// ---------------- problem constants ----------------
#define BATCH   1024
#define DIM     64
#define NCAND   200000
#define TOPK    10
#define K8      8                  // per-thread shortlist size (sorted, in registers)
#define NT      1563               // ceil(200000/128) tiles of 128 cands
#define NCHUNKS 57                 // tile chunks  (8 x 57 = 456 CTAs ~ 3/SM)
#define NROWT   8                  // 1024/128 row tiles
#define NENT    (NCHUNKS * 4 * K8) // shortlist entries per row = 1824

// ---------------- device scratch ----------------
static __device__ __align__(1024) unsigned char g_B[(size_t)NT * 16384];  // SW128-swizzled bf16 cand tiles [128c x 64k]
static __device__ __align__(128)  unsigned char g_A[(size_t)BATCH * 128]; // gathered bf16 user rows
static __device__ uint2 g_p[(size_t)BATCH * NENT];                        // packed (float bits, cand idx)

// ---------------- helpers ----------------
__device__ __forceinline__ uint32_t smem_u32(const void* p) {
    uint32_t a;
    asm("{ .reg .u64 t; cvta.to.shared.u64 t, %1; cvt.u32.u64 %0, t; }" : "=r"(a) : "l"(p));
    return a;
}
__device__ __forceinline__ uint32_t pack_bf16x2(float x, float y) {
    __nv_bfloat16 lo = __float2bfloat16(x);
    __nv_bfloat16 hi = __float2bfloat16(y);
    uint16_t lo16, hi16;
    memcpy(&lo16, &lo, 2);
    memcpy(&hi16, &hi, 2);
    return (uint32_t)lo16 | ((uint32_t)hi16 << 16);
}
__device__ __forceinline__ uint32_t sw128(uint32_t off) {
    return off ^ ((off >> 3) & 0x70);
}
__device__ __forceinline__ void ldsm_x4(uint32_t& r0, uint32_t& r1, uint32_t& r2, uint32_t& r3, uint32_t addr) {
    asm volatile("ldmatrix.sync.aligned.m8n8.x4.shared.b16 {%0,%1,%2,%3}, [%4];"
                 : "=r"(r0), "=r"(r1), "=r"(r2), "=r"(r3) : "r"(addr));
}
__device__ __forceinline__ void mma16816(float& d0, float& d1, float& d2, float& d3,
                                         uint32_t a0, uint32_t a1, uint32_t a2, uint32_t a3,
                                         uint32_t b0, uint32_t b1) {
    asm volatile("mma.sync.aligned.m16n8k16.row.col.f32.bf16.bf16.f32 "
                 "{%0,%1,%2,%3}, {%4,%5,%6,%7}, {%8,%9}, {%0,%1,%2,%3};"
                 : "+f"(d0), "+f"(d1), "+f"(d2), "+f"(d3)
                 : "r"(a0), "r"(a1), "r"(a2), "r"(a3), "r"(b0), "r"(b1));
}
#define CP_ASYNC16(smem, gptr) \
    asm volatile("cp.async.cg.shared.global [%0], [%1], 16;" :: "r"(smem), "l"(gptr))
#define CP_COMMIT() asm volatile("cp.async.commit_group;")
#define CP_WAIT1()  asm volatile("cp.async.wait_group 1;")

// Sorted-descending top-N insert, all constant indices after unroll (register-resident).
template<int N>
__device__ __forceinline__ void insN(float s, int ci, float* v, int* ix) {
    v[N - 1] = s; ix[N - 1] = ci;
    #pragma unroll
    for (int q = N - 1; q > 0; q--) {
        if (v[q] > v[q - 1]) {
            float tv = v[q]; v[q] = v[q - 1]; v[q - 1] = tv;
            int  ti = ix[q]; ix[q] = ix[q - 1]; ix[q - 1] = ti;
        }
    }
}

// ================= Kernel 0: convert & pre-tile (fp32 -> bf16, SW128) =================
__global__ void __launch_bounds__(256) convert_kernel(
    const float* __restrict__ ct, const float* __restrict__ ut,
    const int* __restrict__ user_id)
{
    const long NBC = (long)NT * 1024;   // 16B chunks in g_B
    long gid = (long)blockIdx.x * 256 + threadIdx.x;
    if (gid < NBC) {
        long tile = gid >> 10;
        int within = (int)(gid & 1023);
        int r = within >> 3, sub = within & 7;
        long c = tile * 128 + r;
        uint32_t sw = sw128((uint32_t)(r * 128 + sub * 16));
        uint4 out = make_uint4(0u, 0u, 0u, 0u);
        if (c < NCAND) {
            const float4* src = (const float4*)(ct + c * 64 + sub * 8);
            float4 a = src[0], b = src[1];
            out.x = pack_bf16x2(a.x, a.y); out.y = pack_bf16x2(a.z, a.w);
            out.z = pack_bf16x2(b.x, b.y); out.w = pack_bf16x2(b.z, b.w);
        }
        *(uint4*)(g_B + tile * 16384 + sw) = out;
    } else {
        long g2 = gid - NBC;
        if (g2 >= (long)BATCH * 8) return;
        int u = (int)(g2 >> 3), sub = (int)(g2 & 7);
        const float4* src = (const float4*)(ut + (long)user_id[u] * 64 + sub * 8);
        float4 a = src[0], b = src[1];
        uint4 out;
        out.x = pack_bf16x2(a.x, a.y); out.y = pack_bf16x2(a.z, a.w);
        out.z = pack_bf16x2(b.x, b.y); out.w = pack_bf16x2(b.z, b.w);
        *(uint4*)(g_A + (long)u * 128 + sub * 16) = out;
    }
}

// ================= Kernel 1: gather + MLP (256 blocks x 4 rows) =================
__global__ void __launch_bounds__(256) mlp_kernel(
    const int* __restrict__ user_id, const int* __restrict__ movie_id,
    const float* __restrict__ ut, const float* __restrict__ ct,
    const float* __restrict__ W1, const float* __restrict__ b1,
    const float* __restrict__ W2, const float* __restrict__ b2,
    const float* __restrict__ W3, const float* __restrict__ b3,
    float* __restrict__ outUE, float* __restrict__ outCE, float* __restrict__ outR)
{
    __shared__ float xs[4][128];
    __shared__ float h1s[4][256];
    __shared__ float h2s[4][128];
    __shared__ int uid[4], mid[4];

    const int t = threadIdx.x;
    const int rbase = blockIdx.x * 4;

    if (t < 4) { uid[t] = user_id[rbase + t]; mid[t] = movie_id[rbase + t]; }
    __syncthreads();

    for (int idx = t; idx < 4 * 128; idx += 256) {
        int r = idx >> 7, k = idx & 127;
        float v;
        if (k < 64) {
            v = ut[(long)uid[r] * DIM + k];
            outUE[(long)(rbase + r) * DIM + k] = v;
        } else {
            v = ct[(long)mid[r] * DIM + (k - 64)];
            outCE[(long)(rbase + r) * DIM + (k - 64)] = v;
        }
        xs[r][k] = v;
    }
    __syncthreads();

    {
        float acc[4];
        float bb = b1[t];
        #pragma unroll
        for (int r = 0; r < 4; r++) acc[r] = bb;
        #pragma unroll 8
        for (int k = 0; k < 128; k++) {
            float w = W1[k * 256 + t];
            #pragma unroll
            for (int r = 0; r < 4; r++) acc[r] += xs[r][k] * w;
        }
        #pragma unroll
        for (int r = 0; r < 4; r++) h1s[r][t] = fmaxf(acc[r], 0.0f);
    }
    __syncthreads();

    if (t < 128) {
        float acc[4];
        float bb = b2[t];
        #pragma unroll
        for (int r = 0; r < 4; r++) acc[r] = bb;
        #pragma unroll 8
        for (int k = 0; k < 256; k++) {
            float w = W2[k * 128 + t];
            #pragma unroll
            for (int r = 0; r < 4; r++) acc[r] += h1s[r][k] * w;
        }
        #pragma unroll
        for (int r = 0; r < 4; r++) h2s[r][t] = fmaxf(acc[r], 0.0f);
    }
    __syncthreads();

    if (t < 4) {
        float s = b3[0];
        #pragma unroll 8
        for (int k = 0; k < 128; k++) s += h2s[t][k] * W3[k];
        outR[rbase + t] = s;
    }
}

// ================= Kernel 2: HMMA GEMM + screened register top-8 =================
// grid (8 rowtiles, 57 chunks) x 256 threads (8 warps), 3 CTAs/SM.
// 3-stage cp.async pipeline, ONE __syncthreads per tile.
__global__ void __launch_bounds__(256, 3) gemm_topk_kernel()
{
    __shared__ __align__(1024) unsigned char sB[3][16384];

    const int tid = threadIdx.x;
    const int wid = tid >> 5;
    const int lane = tid & 31;
    const int rowtile = blockIdx.x;
    const int chunk = blockIdx.y;

    // 24 chunks of 28 tiles, 33 chunks of 27 tiles: 24*28 + 33*27 = 1563
    const int t_begin = chunk * 27 + min(chunk, 24);
    const int t_end = (chunk + 1) * 27 + min(chunk + 1, 24);
    const int ntiles = t_end - t_begin;

    uint32_t sbuf[3];
    sbuf[0] = smem_u32(&sB[0][0]);
    sbuf[1] = smem_u32(&sB[1][0]);
    sbuf[2] = smem_u32(&sB[2][0]);

    // ---- stage A into sB[0], build register A-fragments ----
    {
        const uint4* asrc = (const uint4*)(g_A + (size_t)rowtile * 128 * 128);
        uint4* adst = (uint4*)&sB[0][0];
        #pragma unroll
        for (int p = 0; p < 4; p++)
            adst[p * 256 + tid] = asrc[p * 256 + tid];
    }
    __syncthreads();

    uint32_t af[4][4];
    {
        const int g2 = lane >> 3;
        const int mrow = wid * 16 + (g2 & 1) * 8 + (lane & 7);
        const int kb = (g2 >> 1) * 16;
        #pragma unroll
        for (int s = 0; s < 4; s++) {
            uint32_t addr = sbuf[0] + (uint32_t)(mrow * 128 + s * 32 + kb);
            ldsm_x4(af[s][0], af[s][1], af[s][2], af[s][3], addr);
        }
    }
    __syncthreads();   // A reads done before prefetch overwrites sB[0]

    // ---- sorted top-8 per thread per row-half (descending; [7] = current min) ----
    float vLo[K8], vHi[K8];
    int   iLo[K8], iHi[K8];
    #pragma unroll
    for (int j = 0; j < K8; j++) {
        vLo[j] = -CUDART_INF_F; vHi[j] = -CUDART_INF_F;
        iLo[j] = 0x7fffffff;    iHi[j] = 0x7fffffff;
    }

    const int bg2 = lane >> 3;
    const int b_nloc = ((bg2 >> 1) & 1) * 8 + (lane & 7);
    const int b_kb = (bg2 & 1) * 16;
    const int ccol = 2 * (lane & 3);

    // ---- prefetch tiles 0 and 1 (separate groups) ----
    #pragma unroll
    for (int w = 0; w < 2; w++) {
        if (w < ntiles) {
            const char* src = (const char*)(g_B + (size_t)(t_begin + w) * 16384);
            #pragma unroll
            for (int p = 0; p < 4; p++)
                CP_ASYNC16(sbuf[w] + (uint32_t)(p * 4096 + tid * 16), src + p * 4096 + tid * 16);
        }
        CP_COMMIT();
    }

    for (int i = 0; i < ntiles; i++) {
        CP_WAIT1();          // tile i complete (≤1 group pending: tile i+1)
        __syncthreads();     // visibility of tile i + all warps done with tile i-1 (buf (i+2)%3)

        // prefetch tile i+2 into buf (i+2)%3
        if (i + 2 < ntiles) {
            const char* src = (const char*)(g_B + (size_t)(t_begin + i + 2) * 16384);
            uint32_t dst = sbuf[(i + 2) % 3];
            #pragma unroll
            for (int p = 0; p < 4; p++)
                CP_ASYNC16(dst + (uint32_t)(p * 4096 + tid * 16), src + p * 4096 + tid * 16);
        }
        CP_COMMIT();

        const uint32_t bs = sbuf[i % 3];
        const int tilec0 = (t_begin + i) * 128;

        // 4 quarters of 32 candidates: acc[4][4] keeps live regs low
        #pragma unroll
        for (int q = 0; q < 4; q++) {
            float acc[4][4];
            #pragma unroll
            for (int j = 0; j < 4; j++)
                #pragma unroll
                for (int e = 0; e < 4; e++) acc[j][e] = 0.0f;

            #pragma unroll
            for (int s = 0; s < 4; s++) {
                #pragma unroll
                for (int p = 0; p < 2; p++) {
                    const int n = q * 32 + p * 16 + b_nloc;
                    uint32_t off = (uint32_t)(n * 128 + s * 32 + b_kb);
                    uint32_t b0, b1, b2, b3;
                    ldsm_x4(b0, b1, b2, b3, bs + sw128(off));
                    mma16816(acc[2 * p][0], acc[2 * p][1], acc[2 * p][2], acc[2 * p][3],
                             af[s][0], af[s][1], af[s][2], af[s][3], b0, b1);
                    mma16816(acc[2 * p + 1][0], acc[2 * p + 1][1], acc[2 * p + 1][2], acc[2 * p + 1][3],
                             af[s][0], af[s][1], af[s][2], af[s][3], b2, b3);
                }
            }

            const int cbase = tilec0 + q * 32;

            // screening maxes (branch-free), then ONE branch per row-half
            float mLo = acc[0][0], mHi = acc[0][2];
            #pragma unroll
            for (int j = 0; j < 4; j++) {
                mLo = fmaxf(mLo, fmaxf(acc[j][0], acc[j][1]));
                mHi = fmaxf(mHi, fmaxf(acc[j][2], acc[j][3]));
            }
            if (mLo > vLo[K8 - 1]) {
                #pragma unroll
                for (int j = 0; j < 4; j++) {
                    const int c0 = cbase + j * 8 + ccol;
                    if (acc[j][0] > vLo[K8 - 1]) insN<K8>(acc[j][0], c0,     vLo, iLo);
                    if (acc[j][1] > vLo[K8 - 1]) insN<K8>(acc[j][1], c0 + 1, vLo, iLo);
                }
            }
            if (mHi > vHi[K8 - 1]) {
                #pragma unroll
                for (int j = 0; j < 4; j++) {
                    const int c0 = cbase + j * 8 + ccol;
                    if (acc[j][2] > vHi[K8 - 1]) insN<K8>(acc[j][2], c0,     vHi, iHi);
                    if (acc[j][3] > vHi[K8 - 1]) insN<K8>(acc[j][3], c0 + 1, vHi, iHi);
                }
            }
        }
    }

    // ---- dump shortlists: [row][chunk][c*8 + j] packed ----
    {
        const int c = lane & 3;
        const int rowLo = rowtile * 128 + wid * 16 + (lane >> 2);
        const int rowHi = rowLo + 8;
        const long baseLo = ((long)rowLo * NCHUNKS + chunk) * (4 * K8) + c * K8;
        const long baseHi = ((long)rowHi * NCHUNKS + chunk) * (4 * K8) + c * K8;
        #pragma unroll
        for (int j = 0; j < K8; j++) {
            g_p[baseLo + j] = make_uint2(__float_as_uint(vLo[j]), (uint32_t)iLo[j]);
            g_p[baseHi + j] = make_uint2(__float_as_uint(vHi[j]), (uint32_t)iHi[j]);
        }
    }
}

// ================= Kernel 3: merge shortlists + exact fp32 rescore =================
__global__ void __launch_bounds__(256) merge_kernel(
    const int* __restrict__ user_id,
    const float* __restrict__ ut, const float* __restrict__ ct,
    float* __restrict__ outP)
{
    __shared__ float su[8][64];
    __shared__ int   sidx[8][16];
    __shared__ float ssc[8][16];

    const int wid = threadIdx.x >> 5;
    const int lane = threadIdx.x & 31;
    const int row = blockIdx.x * 8 + wid;

    const float* urow = ut + (long)user_id[row] * 64;
    su[wid][lane] = urow[lane];
    su[wid][lane + 32] = urow[lane + 32];

    // phase 1: lane-strided sorted top-8 (registers) over packed entries
    float tv[K8]; int ti[K8];
    #pragma unroll
    for (int j = 0; j < K8; j++) { tv[j] = -CUDART_INF_F; ti[j] = 0x7fffffff; }
    const long rb = (long)row * NENT;
    for (int e = lane; e < NENT; e += 32) {
        uint2 pv = g_p[rb + e];
        float v = __uint_as_float(pv.x);
        if (v > tv[K8 - 1]) {
            int idx = (int)pv.y;
            if (idx < NCAND) insN<K8>(v, idx, tv, ti);
        }
    }

    // phase 2: warp-cooperative 16-round max extraction from per-lane sorted lists
    {
        float h = tv[0];
        #pragma unroll 1
        for (int r = 0; r < 16; r++) {
            float m = h;
            #pragma unroll
            for (int d = 16; d > 0; d >>= 1)
                m = fmaxf(m, __shfl_xor_sync(0xFFFFFFFFu, m, d));
            unsigned msk = __ballot_sync(0xFFFFFFFFu, h == m);
            int owner = __ffs(msk) - 1;
            if (lane == owner) {
                sidx[wid][r] = ti[0];
                #pragma unroll
                for (int q = 0; q < K8 - 1; q++) { tv[q] = tv[q + 1]; ti[q] = ti[q + 1]; }
                tv[K8 - 1] = -CUDART_INF_F;
                h = tv[0];
            }
        }
    }
    __syncwarp();

    // phase 3: exact fp32 rescore of 16-candidate shortlist
    if (lane < 16) {
        int c = sidx[wid][lane];
        float s = -CUDART_INF_F;
        if (c >= 0 && c < NCAND) {
            const float* crow = ct + (long)c * 64;
            s = 0.0f;
            #pragma unroll 8
            for (int k = 0; k < 64; k++) s += su[wid][k] * crow[k];
        }
        ssc[wid][lane] = s;
    }
    __syncwarp();

    // phase 4: sort top-10 (desc value, asc index) and write
    if (lane == 0) {
        float fv[16]; int fi[16];
        #pragma unroll
        for (int j = 0; j < 16; j++) { fv[j] = ssc[wid][j]; fi[j] = sidx[wid][j]; }
        for (int a = 0; a < TOPK; a++) {
            int best = a;
            for (int b = a + 1; b < 16; b++)
                if (fv[b] > fv[best] || (fv[b] == fv[best] && fi[b] < fi[best])) best = b;
            float v = fv[best]; fv[best] = fv[a]; fv[a] = v;
            int   i = fi[best]; fi[best] = fi[a]; fi[a] = i;
            outP[(long)row * TOPK + a] = (float)fi[a];
        }
    }
}

// ================= launch =================
extern "C" void kernel_launch(void* const* d_in, const int* in_sizes, int n_in,
                              void* d_out, int out_size)
{
    const int*   user_id  = (const int*)d_in[0];
    const int*   movie_id = (const int*)d_in[1];
    const float* ut       = (const float*)d_in[2];
    const float* ct       = (const float*)d_in[3];
    const float* W1       = (const float*)d_in[4];
    const float* b1       = (const float*)d_in[5];
    const float* W2       = (const float*)d_in[6];
    const float* b2       = (const float*)d_in[7];
    const float* W3       = (const float*)d_in[8];
    const float* b3       = (const float*)d_in[9];

    float* out   = (float*)d_out;
    float* outUE = out;
    float* outCE = out + BATCH * DIM;
    float* outR  = out + 2 * BATCH * DIM;
    float* outP  = out + 2 * BATCH * DIM + BATCH;

    const int convBlocks = (NT * 1024 + BATCH * 8 + 255) / 256;
    convert_kernel<<<convBlocks, 256>>>(ct, ut, user_id);

    mlp_kernel<<<BATCH / 4, 256>>>(user_id, movie_id, ut, ct,
                                   W1, b1, W2, b2, W3, b3,
                                   outUE, outCE, outR);

    dim3 g2(NROWT, NCHUNKS);
    gemm_topk_kernel<<<g2, 256>>>();

    merge_kernel<<<BATCH / 8, 256>>>(user_id, ut, ct, outP);
}

// round 10
// speedup vs baseline: 4.4686x; 1.8524x over previous
#include <cuda_runtime.h>
#include <cuda_bf16.h>
#include <math_constants.h>
#include <cstdint>
#include <cstring>

// ---------------- problem constants ----------------
#define BATCH   1024
#define DIM     64
#define NCAND   200000
#define TOPK    10
#define K4      4                  // per-thread in-loop shortlist size
#define K8      8                  // merge-phase per-lane list
#define NT      1563               // ceil(200000/128) tiles of 128 cands
#define NCHUNKS 57                 // tile chunks  (8 x 57 = 456 CTAs ~ 3/SM)
#define NROWT   8                  // 1024/128 row tiles
#define NENT    (NCHUNKS * 4 * K4) // shortlist entries per row = 912

// ---------------- device scratch ----------------
static __device__ __align__(1024) unsigned char g_B[(size_t)NT * 16384];  // SW128-swizzled bf16 cand tiles [128c x 64k]
static __device__ __align__(128)  unsigned char g_A[(size_t)BATCH * 128]; // gathered bf16 user rows
static __device__ uint2 g_p[(size_t)BATCH * NENT];                        // packed (float bits, cand idx)

// ---------------- helpers ----------------
__device__ __forceinline__ uint32_t smem_u32(const void* p) {
    uint32_t a;
    asm("{ .reg .u64 t; cvta.to.shared.u64 t, %1; cvt.u32.u64 %0, t; }" : "=r"(a) : "l"(p));
    return a;
}
__device__ __forceinline__ uint32_t pack_bf16x2(float x, float y) {
    __nv_bfloat16 lo = __float2bfloat16(x);
    __nv_bfloat16 hi = __float2bfloat16(y);
    uint16_t lo16, hi16;
    memcpy(&lo16, &lo, 2);
    memcpy(&hi16, &hi, 2);
    return (uint32_t)lo16 | ((uint32_t)hi16 << 16);
}
__device__ __forceinline__ uint32_t sw128(uint32_t off) {
    return off ^ ((off >> 3) & 0x70);
}
__device__ __forceinline__ void ldsm_x4(uint32_t& r0, uint32_t& r1, uint32_t& r2, uint32_t& r3, uint32_t addr) {
    asm volatile("ldmatrix.sync.aligned.m8n8.x4.shared.b16 {%0,%1,%2,%3}, [%4];"
                 : "=r"(r0), "=r"(r1), "=r"(r2), "=r"(r3) : "r"(addr));
}
__device__ __forceinline__ void mma16816(float& d0, float& d1, float& d2, float& d3,
                                         uint32_t a0, uint32_t a1, uint32_t a2, uint32_t a3,
                                         uint32_t b0, uint32_t b1) {
    asm volatile("mma.sync.aligned.m16n8k16.row.col.f32.bf16.bf16.f32 "
                 "{%0,%1,%2,%3}, {%4,%5,%6,%7}, {%8,%9}, {%0,%1,%2,%3};"
                 : "+f"(d0), "+f"(d1), "+f"(d2), "+f"(d3)
                 : "r"(a0), "r"(a1), "r"(a2), "r"(a3), "r"(b0), "r"(b1));
}
#define CP_ASYNC16(smem, gptr) \
    asm volatile("cp.async.cg.shared.global [%0], [%1], 16;" :: "r"(smem), "l"(gptr))
#define CP_COMMIT() asm volatile("cp.async.commit_group;")
#define CP_WAIT1()  asm volatile("cp.async.wait_group 1;")

// Sorted-descending top-N insert, all constant indices after unroll (register-resident).
template<int N>
__device__ __forceinline__ void insN(float s, int ci, float* v, int* ix) {
    v[N - 1] = s; ix[N - 1] = ci;
    #pragma unroll
    for (int q = N - 1; q > 0; q--) {
        if (v[q] > v[q - 1]) {
            float tv = v[q]; v[q] = v[q - 1]; v[q - 1] = tv;
            int  ti = ix[q]; ix[q] = ix[q - 1]; ix[q - 1] = ti;
        }
    }
}

// ================= Kernel 0: convert & pre-tile (fp32 -> bf16, SW128) =================
__global__ void __launch_bounds__(256) convert_kernel(
    const float* __restrict__ ct, const float* __restrict__ ut,
    const int* __restrict__ user_id)
{
    const long NBC = (long)NT * 1024;   // 16B chunks in g_B
    long gid = (long)blockIdx.x * 256 + threadIdx.x;
    if (gid < NBC) {
        long tile = gid >> 10;
        int within = (int)(gid & 1023);
        int r = within >> 3, sub = within & 7;
        long c = tile * 128 + r;
        uint32_t sw = sw128((uint32_t)(r * 128 + sub * 16));
        uint4 out = make_uint4(0u, 0u, 0u, 0u);
        if (c < NCAND) {
            const float4* src = (const float4*)(ct + c * 64 + sub * 8);
            float4 a = src[0], b = src[1];
            out.x = pack_bf16x2(a.x, a.y); out.y = pack_bf16x2(a.z, a.w);
            out.z = pack_bf16x2(b.x, b.y); out.w = pack_bf16x2(b.z, b.w);
        }
        *(uint4*)(g_B + tile * 16384 + sw) = out;
    } else {
        long g2 = gid - NBC;
        if (g2 >= (long)BATCH * 8) return;
        int u = (int)(g2 >> 3), sub = (int)(g2 & 7);
        const float4* src = (const float4*)(ut + (long)user_id[u] * 64 + sub * 8);
        float4 a = src[0], b = src[1];
        uint4 out;
        out.x = pack_bf16x2(a.x, a.y); out.y = pack_bf16x2(a.z, a.w);
        out.z = pack_bf16x2(b.x, b.y); out.w = pack_bf16x2(b.z, b.w);
        *(uint4*)(g_A + (long)u * 128 + sub * 16) = out;
    }
}

// ================= Kernel 1: gather + MLP (256 blocks x 4 rows) =================
__global__ void __launch_bounds__(256) mlp_kernel(
    const int* __restrict__ user_id, const int* __restrict__ movie_id,
    const float* __restrict__ ut, const float* __restrict__ ct,
    const float* __restrict__ W1, const float* __restrict__ b1,
    const float* __restrict__ W2, const float* __restrict__ b2,
    const float* __restrict__ W3, const float* __restrict__ b3,
    float* __restrict__ outUE, float* __restrict__ outCE, float* __restrict__ outR)
{
    __shared__ float xs[4][128];
    __shared__ float h1s[4][256];
    __shared__ float h2s[4][128];
    __shared__ int uid[4], mid[4];

    const int t = threadIdx.x;
    const int rbase = blockIdx.x * 4;

    if (t < 4) { uid[t] = user_id[rbase + t]; mid[t] = movie_id[rbase + t]; }
    __syncthreads();

    for (int idx = t; idx < 4 * 128; idx += 256) {
        int r = idx >> 7, k = idx & 127;
        float v;
        if (k < 64) {
            v = ut[(long)uid[r] * DIM + k];
            outUE[(long)(rbase + r) * DIM + k] = v;
        } else {
            v = ct[(long)mid[r] * DIM + (k - 64)];
            outCE[(long)(rbase + r) * DIM + (k - 64)] = v;
        }
        xs[r][k] = v;
    }
    __syncthreads();

    {
        float acc[4];
        float bb = b1[t];
        #pragma unroll
        for (int r = 0; r < 4; r++) acc[r] = bb;
        #pragma unroll 8
        for (int k = 0; k < 128; k++) {
            float w = W1[k * 256 + t];
            #pragma unroll
            for (int r = 0; r < 4; r++) acc[r] += xs[r][k] * w;
        }
        #pragma unroll
        for (int r = 0; r < 4; r++) h1s[r][t] = fmaxf(acc[r], 0.0f);
    }
    __syncthreads();

    if (t < 128) {
        float acc[4];
        float bb = b2[t];
        #pragma unroll
        for (int r = 0; r < 4; r++) acc[r] = bb;
        #pragma unroll 8
        for (int k = 0; k < 256; k++) {
            float w = W2[k * 128 + t];
            #pragma unroll
            for (int r = 0; r < 4; r++) acc[r] += h1s[r][k] * w;
        }
        #pragma unroll
        for (int r = 0; r < 4; r++) h2s[r][t] = fmaxf(acc[r], 0.0f);
    }
    __syncthreads();

    if (t < 4) {
        float s = b3[0];
        #pragma unroll 8
        for (int k = 0; k < 128; k++) s += h2s[t][k] * W3[k];
        outR[rbase + t] = s;
    }
}

// ================= Kernel 2: HMMA GEMM + screened register top-4 =================
// grid (8 rowtiles, 57 chunks) x 256 threads (8 warps), 3 CTAs/SM.
// 3-stage cp.async pipeline, ONE __syncthreads per tile.
__global__ void __launch_bounds__(256, 3) gemm_topk_kernel()
{
    __shared__ __align__(1024) unsigned char sB[3][16384];

    const int tid = threadIdx.x;
    const int wid = tid >> 5;
    const int lane = tid & 31;
    const int rowtile = blockIdx.x;
    const int chunk = blockIdx.y;

    // 24 chunks of 28 tiles, 33 chunks of 27 tiles: 24*28 + 33*27 = 1563
    const int t_begin = chunk * 27 + min(chunk, 24);
    const int t_end = (chunk + 1) * 27 + min(chunk + 1, 24);
    const int ntiles = t_end - t_begin;

    uint32_t sbuf[3];
    sbuf[0] = smem_u32(&sB[0][0]);
    sbuf[1] = smem_u32(&sB[1][0]);
    sbuf[2] = smem_u32(&sB[2][0]);

    // ---- stage A into sB[0], build register A-fragments ----
    {
        const uint4* asrc = (const uint4*)(g_A + (size_t)rowtile * 128 * 128);
        uint4* adst = (uint4*)&sB[0][0];
        #pragma unroll
        for (int p = 0; p < 4; p++)
            adst[p * 256 + tid] = asrc[p * 256 + tid];
    }
    __syncthreads();

    uint32_t af[4][4];
    {
        const int g2 = lane >> 3;
        const int mrow = wid * 16 + (g2 & 1) * 8 + (lane & 7);
        const int kb = (g2 >> 1) * 16;
        #pragma unroll
        for (int s = 0; s < 4; s++) {
            uint32_t addr = sbuf[0] + (uint32_t)(mrow * 128 + s * 32 + kb);
            ldsm_x4(af[s][0], af[s][1], af[s][2], af[s][3], addr);
        }
    }
    __syncthreads();   // A reads done before prefetch overwrites sB[0]

    // ---- sorted top-4 per thread per row-half (descending; [3] = current min) ----
    float vLo[K4], vHi[K4];
    int   iLo[K4], iHi[K4];
    #pragma unroll
    for (int j = 0; j < K4; j++) {
        vLo[j] = -CUDART_INF_F; vHi[j] = -CUDART_INF_F;
        iLo[j] = 0x7fffffff;    iHi[j] = 0x7fffffff;
    }

    const int bg2 = lane >> 3;
    const int b_nloc = ((bg2 >> 1) & 1) * 8 + (lane & 7);
    const int b_kb = (bg2 & 1) * 16;
    const int ccol = 2 * (lane & 3);

    // ---- prefetch tiles 0 and 1 (separate groups) ----
    #pragma unroll
    for (int w = 0; w < 2; w++) {
        if (w < ntiles) {
            const char* src = (const char*)(g_B + (size_t)(t_begin + w) * 16384);
            #pragma unroll
            for (int p = 0; p < 4; p++)
                CP_ASYNC16(sbuf[w] + (uint32_t)(p * 4096 + tid * 16), src + p * 4096 + tid * 16);
        }
        CP_COMMIT();
    }

    for (int i = 0; i < ntiles; i++) {
        CP_WAIT1();          // tile i complete (≤1 group pending: tile i+1)
        __syncthreads();     // visibility of tile i + all warps done with tile i-1 (buf (i+2)%3)

        // prefetch tile i+2 into buf (i+2)%3
        if (i + 2 < ntiles) {
            const char* src = (const char*)(g_B + (size_t)(t_begin + i + 2) * 16384);
            uint32_t dst = sbuf[(i + 2) % 3];
            #pragma unroll
            for (int p = 0; p < 4; p++)
                CP_ASYNC16(dst + (uint32_t)(p * 4096 + tid * 16), src + p * 4096 + tid * 16);
        }
        CP_COMMIT();

        const uint32_t bs = sbuf[i % 3];
        const int tilec0 = (t_begin + i) * 128;

        // 4 quarters of 32 candidates: acc[4][4] keeps live regs low
        #pragma unroll
        for (int q = 0; q < 4; q++) {
            float acc[4][4];
            #pragma unroll
            for (int j = 0; j < 4; j++)
                #pragma unroll
                for (int e = 0; e < 4; e++) acc[j][e] = 0.0f;

            #pragma unroll
            for (int s = 0; s < 4; s++) {
                #pragma unroll
                for (int p = 0; p < 2; p++) {
                    const int n = q * 32 + p * 16 + b_nloc;
                    uint32_t off = (uint32_t)(n * 128 + s * 32 + b_kb);
                    uint32_t b0, b1, b2, b3;
                    ldsm_x4(b0, b1, b2, b3, bs + sw128(off));
                    mma16816(acc[2 * p][0], acc[2 * p][1], acc[2 * p][2], acc[2 * p][3],
                             af[s][0], af[s][1], af[s][2], af[s][3], b0, b1);
                    mma16816(acc[2 * p + 1][0], acc[2 * p + 1][1], acc[2 * p + 1][2], acc[2 * p + 1][3],
                             af[s][0], af[s][1], af[s][2], af[s][3], b2, b3);
                }
            }

            const int cbase = tilec0 + q * 32;

            // screening maxes (branch-free), then ONE branch per row-half
            float mLo = acc[0][0], mHi = acc[0][2];
            #pragma unroll
            for (int j = 0; j < 4; j++) {
                mLo = fmaxf(mLo, fmaxf(acc[j][0], acc[j][1]));
                mHi = fmaxf(mHi, fmaxf(acc[j][2], acc[j][3]));
            }
            if (mLo > vLo[K4 - 1]) {
                #pragma unroll
                for (int j = 0; j < 4; j++) {
                    const int c0 = cbase + j * 8 + ccol;
                    if (acc[j][0] > vLo[K4 - 1]) insN<K4>(acc[j][0], c0,     vLo, iLo);
                    if (acc[j][1] > vLo[K4 - 1]) insN<K4>(acc[j][1], c0 + 1, vLo, iLo);
                }
            }
            if (mHi > vHi[K4 - 1]) {
                #pragma unroll
                for (int j = 0; j < 4; j++) {
                    const int c0 = cbase + j * 8 + ccol;
                    if (acc[j][2] > vHi[K4 - 1]) insN<K4>(acc[j][2], c0,     vHi, iHi);
                    if (acc[j][3] > vHi[K4 - 1]) insN<K4>(acc[j][3], c0 + 1, vHi, iHi);
                }
            }
        }
    }

    // ---- dump shortlists: [row][chunk][c*4 + j] packed ----
    {
        const int c = lane & 3;
        const int rowLo = rowtile * 128 + wid * 16 + (lane >> 2);
        const int rowHi = rowLo + 8;
        const long baseLo = ((long)rowLo * NCHUNKS + chunk) * (4 * K4) + c * K4;
        const long baseHi = ((long)rowHi * NCHUNKS + chunk) * (4 * K4) + c * K4;
        #pragma unroll
        for (int j = 0; j < K4; j++) {
            g_p[baseLo + j] = make_uint2(__float_as_uint(vLo[j]), (uint32_t)iLo[j]);
            g_p[baseHi + j] = make_uint2(__float_as_uint(vHi[j]), (uint32_t)iHi[j]);
        }
    }
}

// ================= Kernel 3: merge shortlists + exact fp32 rescore =================
__global__ void __launch_bounds__(256) merge_kernel(
    const int* __restrict__ user_id,
    const float* __restrict__ ut, const float* __restrict__ ct,
    float* __restrict__ outP)
{
    __shared__ float su[8][64];
    __shared__ int   sidx[8][16];
    __shared__ float ssc[8][16];

    const int wid = threadIdx.x >> 5;
    const int lane = threadIdx.x & 31;
    const int row = blockIdx.x * 8 + wid;

    const float* urow = ut + (long)user_id[row] * 64;
    su[wid][lane] = urow[lane];
    su[wid][lane + 32] = urow[lane + 32];

    // phase 1: lane-strided sorted top-8 (registers) over packed entries
    float tv[K8]; int ti[K8];
    #pragma unroll
    for (int j = 0; j < K8; j++) { tv[j] = -CUDART_INF_F; ti[j] = 0x7fffffff; }
    const long rb = (long)row * NENT;
    for (int e = lane; e < NENT; e += 32) {
        uint2 pv = g_p[rb + e];
        float v = __uint_as_float(pv.x);
        if (v > tv[K8 - 1]) {
            int idx = (int)pv.y;
            if (idx < NCAND) insN<K8>(v, idx, tv, ti);
        }
    }

    // phase 2: warp-cooperative 16-round max extraction from per-lane sorted lists
    {
        float h = tv[0];
        #pragma unroll 1
        for (int r = 0; r < 16; r++) {
            float m = h;
            #pragma unroll
            for (int d = 16; d > 0; d >>= 1)
                m = fmaxf(m, __shfl_xor_sync(0xFFFFFFFFu, m, d));
            unsigned msk = __ballot_sync(0xFFFFFFFFu, h == m);
            int owner = __ffs(msk) - 1;
            if (lane == owner) {
                sidx[wid][r] = ti[0];
                #pragma unroll
                for (int q = 0; q < K8 - 1; q++) { tv[q] = tv[q + 1]; ti[q] = ti[q + 1]; }
                tv[K8 - 1] = -CUDART_INF_F;
                h = tv[0];
            }
        }
    }
    __syncwarp();

    // phase 3: exact fp32 rescore of 16-candidate shortlist
    if (lane < 16) {
        int c = sidx[wid][lane];
        float s = -CUDART_INF_F;
        if (c >= 0 && c < NCAND) {
            const float* crow = ct + (long)c * 64;
            s = 0.0f;
            #pragma unroll 8
            for (int k = 0; k < 64; k++) s += su[wid][k] * crow[k];
        }
        ssc[wid][lane] = s;
    }
    __syncwarp();

    // phase 4: sort top-10 (desc value, asc index) and write
    if (lane == 0) {
        float fv[16]; int fi[16];
        #pragma unroll
        for (int j = 0; j < 16; j++) { fv[j] = ssc[wid][j]; fi[j] = sidx[wid][j]; }
        for (int a = 0; a < TOPK; a++) {
            int best = a;
            for (int b = a + 1; b < 16; b++)
                if (fv[b] > fv[best] || (fv[b] == fv[best] && fi[b] < fi[best])) best = b;
            float v = fv[best]; fv[best] = fv[a]; fv[a] = v;
            int   i = fi[best]; fi[best] = fi[a]; fi[a] = i;
            outP[(long)row * TOPK + a] = (float)fi[a];
        }
    }
}

// ================= launch =================
extern "C" void kernel_launch(void* const* d_in, const int* in_sizes, int n_in,
                              void* d_out, int out_size)
{
    const int*   user_id  = (const int*)d_in[0];
    const int*   movie_id = (const int*)d_in[1];
    const float* ut       = (const float*)d_in[2];
    const float* ct       = (const float*)d_in[3];
    const float* W1       = (const float*)d_in[4];
    const float* b1       = (const float*)d_in[5];
    const float* W2       = (const float*)d_in[6];
    const float* b2       = (const float*)d_in[7];
    const float* W3       = (const float*)d_in[8];
    const float* b3       = (const float*)d_in[9];

    float* out   = (float*)d_out;
    float* outUE = out;
    float* outCE = out + BATCH * DIM;
    float* outR  = out + 2 * BATCH * DIM;
    float* outP  = out + 2 * BATCH * DIM + BATCH;

    const int convBlocks = (NT * 1024 + BATCH * 8 + 255) / 256;
    convert_kernel<<<convBlocks, 256>>>(ct, ut, user_id);

    mlp_kernel<<<BATCH / 4, 256>>>(user_id, movie_id, ut, ct,
                                   W1, b1, W2, b2, W3, b3,
                                   outUE, outCE, outR);

    dim3 g2(NROWT, NCHUNKS);
    gemm_topk_kernel<<<g2, 256>>>();

    merge_kernel<<<BATCH / 8, 256>>>(user_id, ut, ct, outP);
}

// round 11
// speedup vs baseline: 4.6913x; 1.0498x over previous
#include <cuda_runtime.h>
#include <cuda_bf16.h>
#include <math_constants.h>
#include <cstdint>
#include <cstring>

// ---------------- problem constants ----------------
#define BATCH   1024
#define DIM     64
#define NCAND   200000
#define TOPK    10
#define K4      4                  // per-thread in-loop shortlist size
#define K8      8                  // merge-phase per-lane list
#define NT      1563               // ceil(200000/128) tiles of 128 cands
#define NCHUNKS 57                 // tile chunks  (8 x 57 = 456 CTAs ~ 3/SM)
#define NROWT   8                  // 1024/128 row tiles
#define NENT    (NCHUNKS * 4 * K4) // shortlist entries per row = 912
#define NENT_H  (NENT / 2)         // 456 per merge-warp half
#define MLPB    256                // mlp blocks inside fused kernel

// ---------------- device scratch ----------------
static __device__ __align__(1024) unsigned char g_B[(size_t)NT * 16384];  // SW128-swizzled bf16 cand tiles [128c x 64k]
static __device__ __align__(128)  unsigned char g_A[(size_t)BATCH * 128]; // gathered bf16 user rows
static __device__ uint2 g_p[(size_t)BATCH * NENT];                        // packed (float bits, cand idx)

// ---------------- helpers ----------------
__device__ __forceinline__ uint32_t smem_u32(const void* p) {
    uint32_t a;
    asm("{ .reg .u64 t; cvta.to.shared.u64 t, %1; cvt.u32.u64 %0, t; }" : "=r"(a) : "l"(p));
    return a;
}
__device__ __forceinline__ uint32_t pack_bf16x2(float x, float y) {
    __nv_bfloat16 lo = __float2bfloat16(x);
    __nv_bfloat16 hi = __float2bfloat16(y);
    uint16_t lo16, hi16;
    memcpy(&lo16, &lo, 2);
    memcpy(&hi16, &hi, 2);
    return (uint32_t)lo16 | ((uint32_t)hi16 << 16);
}
__device__ __forceinline__ uint32_t sw128(uint32_t off) {
    return off ^ ((off >> 3) & 0x70);
}
__device__ __forceinline__ void ldsm_x4(uint32_t& r0, uint32_t& r1, uint32_t& r2, uint32_t& r3, uint32_t addr) {
    asm volatile("ldmatrix.sync.aligned.m8n8.x4.shared.b16 {%0,%1,%2,%3}, [%4];"
                 : "=r"(r0), "=r"(r1), "=r"(r2), "=r"(r3) : "r"(addr));
}
__device__ __forceinline__ void mma16816(float& d0, float& d1, float& d2, float& d3,
                                         uint32_t a0, uint32_t a1, uint32_t a2, uint32_t a3,
                                         uint32_t b0, uint32_t b1) {
    asm volatile("mma.sync.aligned.m16n8k16.row.col.f32.bf16.bf16.f32 "
                 "{%0,%1,%2,%3}, {%4,%5,%6,%7}, {%8,%9}, {%0,%1,%2,%3};"
                 : "+f"(d0), "+f"(d1), "+f"(d2), "+f"(d3)
                 : "r"(a0), "r"(a1), "r"(a2), "r"(a3), "r"(b0), "r"(b1));
}
#define CP_ASYNC16(smem, gptr) \
    asm volatile("cp.async.cg.shared.global [%0], [%1], 16;" :: "r"(smem), "l"(gptr))
#define CP_COMMIT() asm volatile("cp.async.commit_group;")
#define CP_WAIT0()  asm volatile("cp.async.wait_group 0;")

// Sorted-descending top-N insert, all constant indices after unroll (register-resident).
template<int N>
__device__ __forceinline__ void insN(float s, int ci, float* v, int* ix) {
    v[N - 1] = s; ix[N - 1] = ci;
    #pragma unroll
    for (int q = N - 1; q > 0; q--) {
        if (v[q] > v[q - 1]) {
            float tv = v[q]; v[q] = v[q - 1]; v[q - 1] = tv;
            int  ti = ix[q]; ix[q] = ix[q - 1]; ix[q - 1] = ti;
        }
    }
}

// order-preserving float->uint transform
__device__ __forceinline__ uint32_t f2ord(float f) {
    uint32_t b = __float_as_uint(f);
    return (b & 0x80000000u) ? ~b : (b | 0x80000000u);
}

// ================= Kernel 0: FUSED convert/pre-tile + gather/MLP =================
// blocks [0, MLPB): mlp on 4 rows each. blocks [MLPB, ...): fp32->bf16 tiling.
__global__ void __launch_bounds__(256) prep_kernel(
    const int* __restrict__ user_id, const int* __restrict__ movie_id,
    const float* __restrict__ ut, const float* __restrict__ ct,
    const float* __restrict__ W1, const float* __restrict__ b1,
    const float* __restrict__ W2, const float* __restrict__ b2,
    const float* __restrict__ W3, const float* __restrict__ b3,
    float* __restrict__ outUE, float* __restrict__ outCE, float* __restrict__ outR)
{
    const int t = threadIdx.x;

    if (blockIdx.x >= MLPB) {
        // ---------------- convert part ----------------
        const long NBC = (long)NT * 1024;   // 16B chunks in g_B
        long gid = (long)(blockIdx.x - MLPB) * 256 + t;
        if (gid < NBC) {
            long tile = gid >> 10;
            int within = (int)(gid & 1023);
            int r = within >> 3, sub = within & 7;
            long c = tile * 128 + r;
            uint32_t sw = sw128((uint32_t)(r * 128 + sub * 16));
            uint4 out = make_uint4(0u, 0u, 0u, 0u);
            if (c < NCAND) {
                const float4* src = (const float4*)(ct + c * 64 + sub * 8);
                float4 a = src[0], b = src[1];
                out.x = pack_bf16x2(a.x, a.y); out.y = pack_bf16x2(a.z, a.w);
                out.z = pack_bf16x2(b.x, b.y); out.w = pack_bf16x2(b.z, b.w);
            }
            *(uint4*)(g_B + tile * 16384 + sw) = out;
        } else {
            long g2 = gid - NBC;
            if (g2 >= (long)BATCH * 8) return;
            int u = (int)(g2 >> 3), sub = (int)(g2 & 7);
            const float4* src = (const float4*)(ut + (long)user_id[u] * 64 + sub * 8);
            float4 a = src[0], b = src[1];
            uint4 out;
            out.x = pack_bf16x2(a.x, a.y); out.y = pack_bf16x2(a.z, a.w);
            out.z = pack_bf16x2(b.x, b.y); out.w = pack_bf16x2(b.z, b.w);
            *(uint4*)(g_A + (long)u * 128 + sub * 16) = out;
        }
        return;
    }

    // ---------------- mlp part ----------------
    __shared__ float xs[4][128];
    __shared__ float h1s[4][256];
    __shared__ float h2s[4][128];
    __shared__ int uid[4], mid[4];

    const int rbase = blockIdx.x * 4;

    if (t < 4) { uid[t] = user_id[rbase + t]; mid[t] = movie_id[rbase + t]; }
    __syncthreads();

    for (int idx = t; idx < 4 * 128; idx += 256) {
        int r = idx >> 7, k = idx & 127;
        float v;
        if (k < 64) {
            v = ut[(long)uid[r] * DIM + k];
            outUE[(long)(rbase + r) * DIM + k] = v;
        } else {
            v = ct[(long)mid[r] * DIM + (k - 64)];
            outCE[(long)(rbase + r) * DIM + (k - 64)] = v;
        }
        xs[r][k] = v;
    }
    __syncthreads();

    {
        float acc[4];
        float bb = b1[t];
        #pragma unroll
        for (int r = 0; r < 4; r++) acc[r] = bb;
        #pragma unroll 8
        for (int k = 0; k < 128; k++) {
            float w = W1[k * 256 + t];
            #pragma unroll
            for (int r = 0; r < 4; r++) acc[r] += xs[r][k] * w;
        }
        #pragma unroll
        for (int r = 0; r < 4; r++) h1s[r][t] = fmaxf(acc[r], 0.0f);
    }
    __syncthreads();

    if (t < 128) {
        float acc[4];
        float bb = b2[t];
        #pragma unroll
        for (int r = 0; r < 4; r++) acc[r] = bb;
        #pragma unroll 8
        for (int k = 0; k < 256; k++) {
            float w = W2[k * 128 + t];
            #pragma unroll
            for (int r = 0; r < 4; r++) acc[r] += h1s[r][k] * w;
        }
        #pragma unroll
        for (int r = 0; r < 4; r++) h2s[r][t] = fmaxf(acc[r], 0.0f);
    }
    __syncthreads();

    if (t < 4) {
        float s = b3[0];
        #pragma unroll 8
        for (int k = 0; k < 128; k++) s += h2s[t][k] * W3[k];
        outR[rbase + t] = s;
    }
}

// ================= Kernel 1: HMMA GEMM + screened register top-4 =================
// grid (8 rowtiles, 57 chunks) x 256 threads (8 warps), 3 CTAs/SM.
// 4 buffers / 2-tile groups: ONE __syncthreads per TWO tiles.
__global__ void __launch_bounds__(256, 3) gemm_topk_kernel()
{
    extern __shared__ __align__(1024) unsigned char sBd[];   // 4 * 16384

    const int tid = threadIdx.x;
    const int wid = tid >> 5;
    const int lane = tid & 31;
    const int rowtile = blockIdx.x;
    const int chunk = blockIdx.y;

    // 24 chunks of 28 tiles, 33 chunks of 27 tiles: 24*28 + 33*27 = 1563
    const int t_begin = chunk * 27 + min(chunk, 24);
    const int t_end = (chunk + 1) * 27 + min(chunk + 1, 24);
    const int ntiles = t_end - t_begin;
    const int ngroups = (ntiles + 1) >> 1;

    uint32_t sbuf[4];
    #pragma unroll
    for (int b = 0; b < 4; b++) sbuf[b] = smem_u32(sBd + b * 16384);

    // ---- stage A into buf0, build register A-fragments ----
    {
        const uint4* asrc = (const uint4*)(g_A + (size_t)rowtile * 128 * 128);
        uint4* adst = (uint4*)sBd;
        #pragma unroll
        for (int p = 0; p < 4; p++)
            adst[p * 256 + tid] = asrc[p * 256 + tid];
    }
    __syncthreads();

    uint32_t af[4][4];
    {
        const int g2 = lane >> 3;
        const int mrow = wid * 16 + (g2 & 1) * 8 + (lane & 7);
        const int kb = (g2 >> 1) * 16;
        #pragma unroll
        for (int s = 0; s < 4; s++) {
            uint32_t addr = sbuf[0] + (uint32_t)(mrow * 128 + s * 32 + kb);
            ldsm_x4(af[s][0], af[s][1], af[s][2], af[s][3], addr);
        }
    }
    __syncthreads();   // A reads done before group-0 prefetch overwrites buf0

    // ---- sorted top-4 per thread per row-half (descending; [3] = current min) ----
    float vLo[K4], vHi[K4];
    int   iLo[K4], iHi[K4];
    #pragma unroll
    for (int j = 0; j < K4; j++) {
        vLo[j] = -CUDART_INF_F; vHi[j] = -CUDART_INF_F;
        iLo[j] = 0x7fffffff;    iHi[j] = 0x7fffffff;
    }

    const int bg2 = lane >> 3;
    const int b_nloc = ((bg2 >> 1) & 1) * 8 + (lane & 7);
    const int b_kb = (bg2 & 1) * 16;
    const int ccol = 2 * (lane & 3);

    // ---- prefetch group 0 (tiles 0,1 -> bufs 0,1) ----
    #pragma unroll
    for (int w = 0; w < 2; w++) {
        if (w < ntiles) {
            const char* src = (const char*)(g_B + (size_t)(t_begin + w) * 16384);
            #pragma unroll
            for (int p = 0; p < 4; p++)
                CP_ASYNC16(sbuf[w] + (uint32_t)(p * 4096 + tid * 16), src + p * 4096 + tid * 16);
        }
    }
    CP_COMMIT();

    for (int g = 0; g < ngroups; g++) {
        CP_WAIT0();          // group g landed (only pending group)
        __syncthreads();     // visibility + all warps done with group g-1 (its buf pair = target below)

        // prefetch group g+1 into pair (g+1)&1
        {
            const int pr = ((g + 1) & 1) * 2;
            #pragma unroll
            for (int w = 0; w < 2; w++) {
                const int tl = 2 * (g + 1) + w;
                if (tl < ntiles) {
                    const char* src = (const char*)(g_B + (size_t)(t_begin + tl) * 16384);
                    #pragma unroll
                    for (int p = 0; p < 4; p++)
                        CP_ASYNC16(sbuf[pr + w] + (uint32_t)(p * 4096 + tid * 16), src + p * 4096 + tid * 16);
                }
            }
            CP_COMMIT();
        }

        // ---- compute the 2 tiles of group g ----
        #pragma unroll 1
        for (int tt = 0; tt < 2; tt++) {
            const int ti_ = 2 * g + tt;
            if (ti_ >= ntiles) break;
            const uint32_t bs = sbuf[(g & 1) * 2 + tt];
            const int tilec0 = (t_begin + ti_) * 128;

            #pragma unroll
            for (int q = 0; q < 4; q++) {
                float acc[4][4];
                #pragma unroll
                for (int j = 0; j < 4; j++)
                    #pragma unroll
                    for (int e = 0; e < 4; e++) acc[j][e] = 0.0f;

                #pragma unroll
                for (int s = 0; s < 4; s++) {
                    #pragma unroll
                    for (int p = 0; p < 2; p++) {
                        const int n = q * 32 + p * 16 + b_nloc;
                        uint32_t off = (uint32_t)(n * 128 + s * 32 + b_kb);
                        uint32_t b0, b1, b2, b3;
                        ldsm_x4(b0, b1, b2, b3, bs + sw128(off));
                        mma16816(acc[2 * p][0], acc[2 * p][1], acc[2 * p][2], acc[2 * p][3],
                                 af[s][0], af[s][1], af[s][2], af[s][3], b0, b1);
                        mma16816(acc[2 * p + 1][0], acc[2 * p + 1][1], acc[2 * p + 1][2], acc[2 * p + 1][3],
                                 af[s][0], af[s][1], af[s][2], af[s][3], b2, b3);
                    }
                }

                const int cbase = tilec0 + q * 32;

                // screening maxes (branch-free), then ONE branch per row-half
                float mLo = acc[0][0], mHi = acc[0][2];
                #pragma unroll
                for (int j = 0; j < 4; j++) {
                    mLo = fmaxf(mLo, fmaxf(acc[j][0], acc[j][1]));
                    mHi = fmaxf(mHi, fmaxf(acc[j][2], acc[j][3]));
                }
                if (mLo > vLo[K4 - 1]) {
                    #pragma unroll
                    for (int j = 0; j < 4; j++) {
                        const int c0 = cbase + j * 8 + ccol;
                        if (acc[j][0] > vLo[K4 - 1]) insN<K4>(acc[j][0], c0,     vLo, iLo);
                        if (acc[j][1] > vLo[K4 - 1]) insN<K4>(acc[j][1], c0 + 1, vLo, iLo);
                    }
                }
                if (mHi > vHi[K4 - 1]) {
                    #pragma unroll
                    for (int j = 0; j < 4; j++) {
                        const int c0 = cbase + j * 8 + ccol;
                        if (acc[j][2] > vHi[K4 - 1]) insN<K4>(acc[j][2], c0,     vHi, iHi);
                        if (acc[j][3] > vHi[K4 - 1]) insN<K4>(acc[j][3], c0 + 1, vHi, iHi);
                    }
                }
            }
        }
    }

    // ---- dump shortlists: [row][chunk][c*4 + j] packed ----
    {
        const int c = lane & 3;
        const int rowLo = rowtile * 128 + wid * 16 + (lane >> 2);
        const int rowHi = rowLo + 8;
        const long baseLo = ((long)rowLo * NCHUNKS + chunk) * (4 * K4) + c * K4;
        const long baseHi = ((long)rowHi * NCHUNKS + chunk) * (4 * K4) + c * K4;
        #pragma unroll
        for (int j = 0; j < K4; j++) {
            g_p[baseLo + j] = make_uint2(__float_as_uint(vLo[j]), (uint32_t)iLo[j]);
            g_p[baseHi + j] = make_uint2(__float_as_uint(vHi[j]), (uint32_t)iHi[j]);
        }
    }
}

// ================= Kernel 2: merge shortlists + exact fp32 rescore =================
// 256 blocks x 256 threads: 4 rows/block, 2 warps/row (each scans half the entries).
__global__ void __launch_bounds__(256) merge_kernel(
    const int* __restrict__ user_id,
    const float* __restrict__ ut, const float* __restrict__ ct,
    float* __restrict__ outP)
{
    __shared__ float su[4][64];
    __shared__ int   scand[4][32];

    const int wid = threadIdx.x >> 5;
    const int lane = threadIdx.x & 31;
    const int row4 = wid >> 1;            // 0..3
    const int half = wid & 1;             // 0..1
    const int row = blockIdx.x * 4 + row4;

    if (half == 0) {
        const float* urow = ut + (long)user_id[row] * 64;
        su[row4][lane] = urow[lane];
        su[row4][lane + 32] = urow[lane + 32];
    }

    // phase 1: per-warp scan over its half of the entries -> per-lane sorted top-8
    float tv[K8]; int ti[K8];
    #pragma unroll
    for (int j = 0; j < K8; j++) { tv[j] = -CUDART_INF_F; ti[j] = 0x7fffffff; }
    const long base = (long)row * NENT + (long)half * NENT_H;
    for (int e = lane; e < NENT_H; e += 32) {
        uint2 pv = g_p[base + e];
        float v = __uint_as_float(pv.x);
        if (v > tv[K8 - 1]) {
            int idx = (int)pv.y;
            if (idx < NCAND) insN<K8>(v, idx, tv, ti);
        }
    }

    // phase 2: 16-round max extraction from per-lane sorted lists -> 16 cands per half
    {
        float h = tv[0];
        #pragma unroll 1
        for (int r = 0; r < 16; r++) {
            float m = h;
            #pragma unroll
            for (int d = 16; d > 0; d >>= 1)
                m = fmaxf(m, __shfl_xor_sync(0xFFFFFFFFu, m, d));
            unsigned msk = __ballot_sync(0xFFFFFFFFu, h == m);
            int owner = __ffs(msk) - 1;
            if (lane == owner) {
                scand[row4][half * 16 + r] = ti[0];
                #pragma unroll
                for (int q = 0; q < K8 - 1; q++) { tv[q] = tv[q + 1]; ti[q] = ti[q + 1]; }
                tv[K8 - 1] = -CUDART_INF_F;
                h = tv[0];
            }
        }
    }
    __syncthreads();

    // phase 3: half-0 warp rescores all 32 shortlisted candidates exactly (fp32),
    // then 10 rounds of packed-key warp max -> output.
    if (half == 0) {
        const int c = scand[row4][lane];
        float s = -CUDART_INF_F;
        if (c >= 0 && c < NCAND) {
            const float* crow = ct + (long)c * 64;
            s = 0.0f;
            #pragma unroll 8
            for (int k = 0; k < 64; k++) s += su[row4][k] * crow[k];
        }
        // packed sortable key: (ordered float) << 32 | (~idx)  -> value desc, idx asc
        unsigned long long key = ((unsigned long long)f2ord(s) << 32) |
                                 (unsigned long long)(0xFFFFFFFFu - (uint32_t)c);
        #pragma unroll 1
        for (int r = 0; r < TOPK; r++) {
            unsigned long long m = key;
            #pragma unroll
            for (int d = 16; d > 0; d >>= 1) {
                unsigned long long o = __shfl_xor_sync(0xFFFFFFFFu, m, d);
                if (o > m) m = o;
            }
            if (key == m) key = 0;   // winner retires (unique: candidate ids distinct)
            if (lane == 0) {
                uint32_t ci = 0xFFFFFFFFu - (uint32_t)(m & 0xFFFFFFFFu);
                outP[(long)row * TOPK + r] = (float)ci;
            }
        }
    }
}

// ================= launch =================
extern "C" void kernel_launch(void* const* d_in, const int* in_sizes, int n_in,
                              void* d_out, int out_size)
{
    const int*   user_id  = (const int*)d_in[0];
    const int*   movie_id = (const int*)d_in[1];
    const float* ut       = (const float*)d_in[2];
    const float* ct       = (const float*)d_in[3];
    const float* W1       = (const float*)d_in[4];
    const float* b1       = (const float*)d_in[5];
    const float* W2       = (const float*)d_in[6];
    const float* b2       = (const float*)d_in[7];
    const float* W3       = (const float*)d_in[8];
    const float* b3       = (const float*)d_in[9];

    float* out   = (float*)d_out;
    float* outUE = out;
    float* outCE = out + BATCH * DIM;
    float* outR  = out + 2 * BATCH * DIM;
    float* outP  = out + 2 * BATCH * DIM + BATCH;

    // fused convert + mlp
    const int convBlocks = (NT * 1024 + BATCH * 8 + 255) / 256;
    prep_kernel<<<MLPB + convBlocks, 256>>>(user_id, movie_id, ut, ct,
                                            W1, b1, W2, b2, W3, b3,
                                            outUE, outCE, outR);

    // gemm + fused screened top-4 (64KB dynamic smem)
    cudaFuncSetAttribute(gemm_topk_kernel,
                         cudaFuncAttributeMaxDynamicSharedMemorySize, 4 * 16384);
    dim3 g2(NROWT, NCHUNKS);
    gemm_topk_kernel<<<g2, 256, 4 * 16384>>>();

    // merge + exact rescore
    merge_kernel<<<BATCH / 4, 256>>>(user_id, ut, ct, outP);
}

// round 12
// speedup vs baseline: 4.9272x; 1.0503x over previous
#include <cuda_runtime.h>
#include <cuda_bf16.h>
#include <math_constants.h>
#include <cstdint>
#include <cstring>

// ---------------- problem constants ----------------
#define BATCH   1024
#define DIM     64
#define NCAND   200000
#define TOPK    10
#define K4      4                  // per-thread in-loop shortlist size
#define K8      8                  // merge-phase per-lane list
#define NT      1563               // ceil(200000/128) tiles of 128 cands
#define NCHUNKS 57                 // tile chunks  (8 x 57 = 456 CTAs ~ 3/SM)
#define NROWT   8                  // 1024/128 row tiles
#define NENT    (NCHUNKS * 4 * K4) // shortlist entries per row = 912
#define NENT_H  (NENT / 2)         // 456 per merge-warp half
#define MLPB    256                // mlp blocks inside fused kernel

// ---------------- device scratch ----------------
static __device__ __align__(1024) unsigned char g_B[(size_t)NT * 16384];  // SW128-swizzled bf16 cand tiles [128c x 64k]
static __device__ __align__(128)  unsigned char g_A[(size_t)BATCH * 128]; // gathered bf16 user rows
static __device__ uint2 g_p[(size_t)BATCH * NENT];                        // packed (float bits, cand idx)

// ---------------- helpers ----------------
__device__ __forceinline__ uint32_t smem_u32(const void* p) {
    uint32_t a;
    asm("{ .reg .u64 t; cvta.to.shared.u64 t, %1; cvt.u32.u64 %0, t; }" : "=r"(a) : "l"(p));
    return a;
}
__device__ __forceinline__ uint32_t pack_bf16x2(float x, float y) {
    __nv_bfloat16 lo = __float2bfloat16(x);
    __nv_bfloat16 hi = __float2bfloat16(y);
    uint16_t lo16, hi16;
    memcpy(&lo16, &lo, 2);
    memcpy(&hi16, &hi, 2);
    return (uint32_t)lo16 | ((uint32_t)hi16 << 16);
}
__device__ __forceinline__ uint32_t sw128(uint32_t off) {
    return off ^ ((off >> 3) & 0x70);
}
__device__ __forceinline__ void ldsm_x4(uint32_t& r0, uint32_t& r1, uint32_t& r2, uint32_t& r3, uint32_t addr) {
    asm volatile("ldmatrix.sync.aligned.m8n8.x4.shared.b16 {%0,%1,%2,%3}, [%4];"
                 : "=r"(r0), "=r"(r1), "=r"(r2), "=r"(r3) : "r"(addr));
}
__device__ __forceinline__ void mma16816(float& d0, float& d1, float& d2, float& d3,
                                         uint32_t a0, uint32_t a1, uint32_t a2, uint32_t a3,
                                         uint32_t b0, uint32_t b1) {
    asm volatile("mma.sync.aligned.m16n8k16.row.col.f32.bf16.bf16.f32 "
                 "{%0,%1,%2,%3}, {%4,%5,%6,%7}, {%8,%9}, {%0,%1,%2,%3};"
                 : "+f"(d0), "+f"(d1), "+f"(d2), "+f"(d3)
                 : "r"(a0), "r"(a1), "r"(a2), "r"(a3), "r"(b0), "r"(b1));
}
#define CP_ASYNC16(smem, gptr) \
    asm volatile("cp.async.cg.shared.global [%0], [%1], 16;" :: "r"(smem), "l"(gptr))
#define CP_COMMIT() asm volatile("cp.async.commit_group;")
#define CP_WAIT0()  asm volatile("cp.async.wait_group 0;")

// Sorted-descending top-N insert, all constant indices after unroll (register-resident).
template<int N>
__device__ __forceinline__ void insN(float s, int ci, float* v, int* ix) {
    v[N - 1] = s; ix[N - 1] = ci;
    #pragma unroll
    for (int q = N - 1; q > 0; q--) {
        if (v[q] > v[q - 1]) {
            float tv = v[q]; v[q] = v[q - 1]; v[q - 1] = tv;
            int  ti = ix[q]; ix[q] = ix[q - 1]; ix[q - 1] = ti;
        }
    }
}

// order-preserving float->uint transform
__device__ __forceinline__ uint32_t f2ord(float f) {
    uint32_t b = __float_as_uint(f);
    return (b & 0x80000000u) ? ~b : (b | 0x80000000u);
}

// ================= Kernel 0: FUSED convert/pre-tile + gather/MLP =================
// blocks [0, MLPB): mlp on 4 rows each.
// blocks [MLPB, ...): fp32->bf16 tiling, ONE HALF-ROW (32 floats) per thread, MLP=8.
__global__ void __launch_bounds__(256) prep_kernel(
    const int* __restrict__ user_id, const int* __restrict__ movie_id,
    const float* __restrict__ ut, const float* __restrict__ ct,
    const float* __restrict__ W1, const float* __restrict__ b1,
    const float* __restrict__ W2, const float* __restrict__ b2,
    const float* __restrict__ W3, const float* __restrict__ b3,
    float* __restrict__ outUE, float* __restrict__ outCE, float* __restrict__ outR)
{
    const int t = threadIdx.x;

    if (blockIdx.x >= MLPB) {
        const long NHR = (long)NT * 256;   // half-rows in g_B
        long gid = (long)(blockIdx.x - MLPB) * 256 + t;
        if (gid < NHR) {
            // ---------------- convert: one half-row per thread ----------------
            long tile = gid >> 8;
            int within = (int)(gid & 255);
            int r = within >> 1, h = within & 1;     // cand-in-tile, half (32 floats)
            long c = tile * 128 + r;

            float4 f[8];
            if (c < NCAND) {
                const float4* src = (const float4*)(ct + c * 64 + h * 32);
                #pragma unroll
                for (int u = 0; u < 8; u++) f[u] = src[u];   // 8 independent LDG.128
            } else {
                #pragma unroll
                for (int u = 0; u < 8; u++) f[u] = make_float4(0.f, 0.f, 0.f, 0.f);
            }
            unsigned char* dstb = g_B + tile * 16384;
            #pragma unroll
            for (int u = 0; u < 4; u++) {
                uint4 out;
                out.x = pack_bf16x2(f[2 * u].x, f[2 * u].y);
                out.y = pack_bf16x2(f[2 * u].z, f[2 * u].w);
                out.z = pack_bf16x2(f[2 * u + 1].x, f[2 * u + 1].y);
                out.w = pack_bf16x2(f[2 * u + 1].z, f[2 * u + 1].w);
                uint32_t off = (uint32_t)(r * 128 + (h * 4 + u) * 16);
                *(uint4*)(dstb + sw128(off)) = out;
            }
        } else {
            // ---------------- A gather (bf16 user rows) ----------------
            long g2 = gid - NHR;
            if (g2 >= (long)BATCH * 8) return;
            int u = (int)(g2 >> 3), sub = (int)(g2 & 7);
            const float4* src = (const float4*)(ut + (long)user_id[u] * 64 + sub * 8);
            float4 a = src[0], b = src[1];
            uint4 out;
            out.x = pack_bf16x2(a.x, a.y); out.y = pack_bf16x2(a.z, a.w);
            out.z = pack_bf16x2(b.x, b.y); out.w = pack_bf16x2(b.z, b.w);
            *(uint4*)(g_A + (long)u * 128 + sub * 16) = out;
        }
        return;
    }

    // ---------------- mlp part ----------------
    __shared__ float xs[4][128];
    __shared__ float h1s[4][256];
    __shared__ float h2s[4][128];
    __shared__ int uid[4], mid[4];

    const int rbase = blockIdx.x * 4;

    if (t < 4) { uid[t] = user_id[rbase + t]; mid[t] = movie_id[rbase + t]; }
    __syncthreads();

    for (int idx = t; idx < 4 * 128; idx += 256) {
        int r = idx >> 7, k = idx & 127;
        float v;
        if (k < 64) {
            v = ut[(long)uid[r] * DIM + k];
            outUE[(long)(rbase + r) * DIM + k] = v;
        } else {
            v = ct[(long)mid[r] * DIM + (k - 64)];
            outCE[(long)(rbase + r) * DIM + (k - 64)] = v;
        }
        xs[r][k] = v;
    }
    __syncthreads();

    {
        float acc[4];
        float bb = b1[t];
        #pragma unroll
        for (int r = 0; r < 4; r++) acc[r] = bb;
        #pragma unroll 8
        for (int k = 0; k < 128; k++) {
            float w = W1[k * 256 + t];
            #pragma unroll
            for (int r = 0; r < 4; r++) acc[r] += xs[r][k] * w;
        }
        #pragma unroll
        for (int r = 0; r < 4; r++) h1s[r][t] = fmaxf(acc[r], 0.0f);
    }
    __syncthreads();

    if (t < 128) {
        float acc[4];
        float bb = b2[t];
        #pragma unroll
        for (int r = 0; r < 4; r++) acc[r] = bb;
        #pragma unroll 8
        for (int k = 0; k < 256; k++) {
            float w = W2[k * 128 + t];
            #pragma unroll
            for (int r = 0; r < 4; r++) acc[r] += h1s[r][k] * w;
        }
        #pragma unroll
        for (int r = 0; r < 4; r++) h2s[r][t] = fmaxf(acc[r], 0.0f);
    }
    __syncthreads();

    if (t < 4) {
        float s = b3[0];
        #pragma unroll 8
        for (int k = 0; k < 128; k++) s += h2s[t][k] * W3[k];
        outR[rbase + t] = s;
    }
}

// ================= Kernel 1: HMMA GEMM + screened register top-4 =================
// grid (8 rowtiles, 57 chunks) x 256 threads (8 warps), 3 CTAs/SM.
// 4 buffers / 2-tile groups. Swizzle factored into lane-constant sx[s]:
//   sw128(n*128 + s*32 + kb) = n*128 + ((s*32 + kb) ^ ((lane&7)<<4))
__global__ void __launch_bounds__(256, 3) gemm_topk_kernel()
{
    extern __shared__ __align__(1024) unsigned char sBd[];   // 4 * 16384

    const int tid = threadIdx.x;
    const int wid = tid >> 5;
    const int lane = tid & 31;
    const int rowtile = blockIdx.x;
    const int chunk = blockIdx.y;

    // 24 chunks of 28 tiles, 33 chunks of 27 tiles: 24*28 + 33*27 = 1563
    const int t_begin = chunk * 27 + min(chunk, 24);
    const int t_end = (chunk + 1) * 27 + min(chunk + 1, 24);
    const int ntiles = t_end - t_begin;
    const int ngroups = (ntiles + 1) >> 1;

    uint32_t sbuf[4];
    #pragma unroll
    for (int b = 0; b < 4; b++) sbuf[b] = smem_u32(sBd + b * 16384);

    // ---- stage A into buf0, build register A-fragments ----
    {
        const uint4* asrc = (const uint4*)(g_A + (size_t)rowtile * 128 * 128);
        uint4* adst = (uint4*)sBd;
        #pragma unroll
        for (int p = 0; p < 4; p++)
            adst[p * 256 + tid] = asrc[p * 256 + tid];
    }
    __syncthreads();

    uint32_t af[4][4];
    {
        const int g2 = lane >> 3;
        const int mrow = wid * 16 + (g2 & 1) * 8 + (lane & 7);
        const int kb = (g2 >> 1) * 16;
        #pragma unroll
        for (int s = 0; s < 4; s++) {
            uint32_t addr = sbuf[0] + (uint32_t)(mrow * 128 + s * 32 + kb);
            ldsm_x4(af[s][0], af[s][1], af[s][2], af[s][3], addr);
        }
    }
    __syncthreads();   // A reads done before group-0 prefetch overwrites buf0

    // ---- sorted top-4 per thread per row-half (descending; [3] = current min) ----
    float vLo[K4], vHi[K4];
    int   iLo[K4], iHi[K4];
    #pragma unroll
    for (int j = 0; j < K4; j++) {
        vLo[j] = -CUDART_INF_F; vHi[j] = -CUDART_INF_F;
        iLo[j] = 0x7fffffff;    iHi[j] = 0x7fffffff;
    }

    const int bg2 = lane >> 3;
    const int b_nloc = ((bg2 >> 1) & 1) * 8 + (lane & 7);
    const int b_kb = (bg2 & 1) * 16;
    const int ccol = 2 * (lane & 3);

    // lane-constant swizzled k-step offsets
    uint32_t sx[4];
    {
        const uint32_t X = (uint32_t)((lane & 7) << 4);
        #pragma unroll
        for (int s = 0; s < 4; s++)
            sx[s] = ((uint32_t)(s * 32 + b_kb)) ^ X;
    }
    const uint32_t bnl128 = (uint32_t)(b_nloc * 128);

    // ---- prefetch group 0 (tiles 0,1 -> bufs 0,1) ----
    #pragma unroll
    for (int w = 0; w < 2; w++) {
        if (w < ntiles) {
            const char* src = (const char*)(g_B + (size_t)(t_begin + w) * 16384);
            #pragma unroll
            for (int p = 0; p < 4; p++)
                CP_ASYNC16(sbuf[w] + (uint32_t)(p * 4096 + tid * 16), src + p * 4096 + tid * 16);
        }
    }
    CP_COMMIT();

    for (int g = 0; g < ngroups; g++) {
        CP_WAIT0();          // group g landed (only pending group)
        __syncthreads();     // visibility + all warps done with group g-1 (its buf pair = target below)

        // prefetch group g+1 into pair (g+1)&1
        {
            const int pr = ((g + 1) & 1) * 2;
            #pragma unroll
            for (int w = 0; w < 2; w++) {
                const int tl = 2 * (g + 1) + w;
                if (tl < ntiles) {
                    const char* src = (const char*)(g_B + (size_t)(t_begin + tl) * 16384);
                    #pragma unroll
                    for (int p = 0; p < 4; p++)
                        CP_ASYNC16(sbuf[pr + w] + (uint32_t)(p * 4096 + tid * 16), src + p * 4096 + tid * 16);
                }
            }
            CP_COMMIT();
        }

        // ---- compute the 2 tiles of group g ----
        #pragma unroll 1
        for (int tt = 0; tt < 2; tt++) {
            const int ti_ = 2 * g + tt;
            if (ti_ >= ntiles) break;
            const uint32_t bsn = sbuf[(g & 1) * 2 + tt] + bnl128;   // lane base for this tile
            const int tilec0 = (t_begin + ti_) * 128;

            #pragma unroll
            for (int q = 0; q < 4; q++) {
                float acc[4][4];
                #pragma unroll
                for (int j = 0; j < 4; j++)
                    #pragma unroll
                    for (int e = 0; e < 4; e++) acc[j][e] = 0.0f;

                #pragma unroll
                for (int s = 0; s < 4; s++) {
                    #pragma unroll
                    for (int p = 0; p < 2; p++) {
                        // addr = base + sx[s] + immediate(q*4096 + p*2048)
                        uint32_t addr = bsn + sx[s] + (uint32_t)(q * 4096 + p * 2048);
                        uint32_t b0, b1, b2, b3;
                        ldsm_x4(b0, b1, b2, b3, addr);
                        mma16816(acc[2 * p][0], acc[2 * p][1], acc[2 * p][2], acc[2 * p][3],
                                 af[s][0], af[s][1], af[s][2], af[s][3], b0, b1);
                        mma16816(acc[2 * p + 1][0], acc[2 * p + 1][1], acc[2 * p + 1][2], acc[2 * p + 1][3],
                                 af[s][0], af[s][1], af[s][2], af[s][3], b2, b3);
                    }
                }

                const int cbase = tilec0 + q * 32;

                // screening maxes (branch-free), then ONE branch per row-half
                float mLo = acc[0][0], mHi = acc[0][2];
                #pragma unroll
                for (int j = 0; j < 4; j++) {
                    mLo = fmaxf(mLo, fmaxf(acc[j][0], acc[j][1]));
                    mHi = fmaxf(mHi, fmaxf(acc[j][2], acc[j][3]));
                }
                if (mLo > vLo[K4 - 1]) {
                    #pragma unroll
                    for (int j = 0; j < 4; j++) {
                        const int c0 = cbase + j * 8 + ccol;
                        if (acc[j][0] > vLo[K4 - 1]) insN<K4>(acc[j][0], c0,     vLo, iLo);
                        if (acc[j][1] > vLo[K4 - 1]) insN<K4>(acc[j][1], c0 + 1, vLo, iLo);
                    }
                }
                if (mHi > vHi[K4 - 1]) {
                    #pragma unroll
                    for (int j = 0; j < 4; j++) {
                        const int c0 = cbase + j * 8 + ccol;
                        if (acc[j][2] > vHi[K4 - 1]) insN<K4>(acc[j][2], c0,     vHi, iHi);
                        if (acc[j][3] > vHi[K4 - 1]) insN<K4>(acc[j][3], c0 + 1, vHi, iHi);
                    }
                }
            }
        }
    }

    // ---- dump shortlists: [row][chunk][c*4 + j] packed ----
    {
        const int c = lane & 3;
        const int rowLo = rowtile * 128 + wid * 16 + (lane >> 2);
        const int rowHi = rowLo + 8;
        const long baseLo = ((long)rowLo * NCHUNKS + chunk) * (4 * K4) + c * K4;
        const long baseHi = ((long)rowHi * NCHUNKS + chunk) * (4 * K4) + c * K4;
        #pragma unroll
        for (int j = 0; j < K4; j++) {
            g_p[baseLo + j] = make_uint2(__float_as_uint(vLo[j]), (uint32_t)iLo[j]);
            g_p[baseHi + j] = make_uint2(__float_as_uint(vHi[j]), (uint32_t)iHi[j]);
        }
    }
}

// ================= Kernel 2: merge shortlists + exact fp32 rescore =================
// 256 blocks x 256 threads: 4 rows/block, 2 warps/row (each scans half the entries).
__global__ void __launch_bounds__(256) merge_kernel(
    const int* __restrict__ user_id,
    const float* __restrict__ ut, const float* __restrict__ ct,
    float* __restrict__ outP)
{
    __shared__ float su[4][64];
    __shared__ int   scand[4][32];

    const int wid = threadIdx.x >> 5;
    const int lane = threadIdx.x & 31;
    const int row4 = wid >> 1;            // 0..3
    const int half = wid & 1;             // 0..1
    const int row = blockIdx.x * 4 + row4;

    if (half == 0) {
        const float* urow = ut + (long)user_id[row] * 64;
        su[row4][lane] = urow[lane];
        su[row4][lane + 32] = urow[lane + 32];
    }

    // phase 1: per-warp scan over its half of the entries -> per-lane sorted top-8
    float tv[K8]; int ti[K8];
    #pragma unroll
    for (int j = 0; j < K8; j++) { tv[j] = -CUDART_INF_F; ti[j] = 0x7fffffff; }
    const long base = (long)row * NENT + (long)half * NENT_H;
    for (int e = lane; e < NENT_H; e += 32) {
        uint2 pv = g_p[base + e];
        float v = __uint_as_float(pv.x);
        if (v > tv[K8 - 1]) {
            int idx = (int)pv.y;
            if (idx < NCAND) insN<K8>(v, idx, tv, ti);
        }
    }

    // phase 2: 16-round max extraction from per-lane sorted lists -> 16 cands per half
    {
        float h = tv[0];
        #pragma unroll 1
        for (int r = 0; r < 16; r++) {
            float m = h;
            #pragma unroll
            for (int d = 16; d > 0; d >>= 1)
                m = fmaxf(m, __shfl_xor_sync(0xFFFFFFFFu, m, d));
            unsigned msk = __ballot_sync(0xFFFFFFFFu, h == m);
            int owner = __ffs(msk) - 1;
            if (lane == owner) {
                scand[row4][half * 16 + r] = ti[0];
                #pragma unroll
                for (int q = 0; q < K8 - 1; q++) { tv[q] = tv[q + 1]; ti[q] = ti[q + 1]; }
                tv[K8 - 1] = -CUDART_INF_F;
                h = tv[0];
            }
        }
    }
    __syncthreads();

    // phase 3: half-0 warp rescores all 32 shortlisted candidates exactly (fp32),
    // then 10 rounds of packed-key warp max -> output.
    if (half == 0) {
        const int c = scand[row4][lane];
        float s = -CUDART_INF_F;
        if (c >= 0 && c < NCAND) {
            const float* crow = ct + (long)c * 64;
            s = 0.0f;
            #pragma unroll 8
            for (int k = 0; k < 64; k++) s += su[row4][k] * crow[k];
        }
        // packed sortable key: (ordered float) << 32 | (~idx)  -> value desc, idx asc
        unsigned long long key = ((unsigned long long)f2ord(s) << 32) |
                                 (unsigned long long)(0xFFFFFFFFu - (uint32_t)c);
        #pragma unroll 1
        for (int r = 0; r < TOPK; r++) {
            unsigned long long m = key;
            #pragma unroll
            for (int d = 16; d > 0; d >>= 1) {
                unsigned long long o = __shfl_xor_sync(0xFFFFFFFFu, m, d);
                if (o > m) m = o;
            }
            if (key == m) key = 0;   // winner retires (unique: candidate ids distinct)
            if (lane == 0) {
                uint32_t ci = 0xFFFFFFFFu - (uint32_t)(m & 0xFFFFFFFFu);
                outP[(long)row * TOPK + r] = (float)ci;
            }
        }
    }
}

// ================= launch =================
extern "C" void kernel_launch(void* const* d_in, const int* in_sizes, int n_in,
                              void* d_out, int out_size)
{
    const int*   user_id  = (const int*)d_in[0];
    const int*   movie_id = (const int*)d_in[1];
    const float* ut       = (const float*)d_in[2];
    const float* ct       = (const float*)d_in[3];
    const float* W1       = (const float*)d_in[4];
    const float* b1       = (const float*)d_in[5];
    const float* W2       = (const float*)d_in[6];
    const float* b2       = (const float*)d_in[7];
    const float* W3       = (const float*)d_in[8];
    const float* b3       = (const float*)d_in[9];

    float* out   = (float*)d_out;
    float* outUE = out;
    float* outCE = out + BATCH * DIM;
    float* outR  = out + 2 * BATCH * DIM;
    float* outP  = out + 2 * BATCH * DIM + BATCH;

    // fused convert (half-row per thread) + A-gather + mlp
    const long convWork = (long)NT * 256 + BATCH * 8;          // half-rows + A chunks
    const int convBlocks = (int)((convWork + 255) / 256);
    prep_kernel<<<MLPB + convBlocks, 256>>>(user_id, movie_id, ut, ct,
                                            W1, b1, W2, b2, W3, b3,
                                            outUE, outCE, outR);

    // gemm + fused screened top-4 (64KB dynamic smem)
    cudaFuncSetAttribute(gemm_topk_kernel,
                         cudaFuncAttributeMaxDynamicSharedMemorySize, 4 * 16384);
    dim3 g2(NROWT, NCHUNKS);
    gemm_topk_kernel<<<g2, 256, 4 * 16384>>>();

    // merge + exact rescore
    merge_kernel<<<BATCH / 4, 256>>>(user_id, ut, ct, outP);
}

// round 13
// speedup vs baseline: 5.0638x; 1.0277x over previous
#include <cuda_runtime.h>
#include <cuda_bf16.h>
#include <math_constants.h>
#include <cstdint>
#include <cstring>

// ---------------- problem constants ----------------
#define BATCH   1024
#define DIM     64
#define NCAND   200000
#define TOPK    10
#define K4      4                  // per-thread in-loop shortlist size
#define K8      8                  // merge-phase per-lane list
#define NT      1563               // ceil(200000/128) tiles of 128 cands
#define NCHUNKS 57                 // tile chunks  (8 x 57 = 456 CTAs ~ 3/SM)
#define NROWT   8                  // 1024/128 row tiles
#define NENT    (NCHUNKS * 4 * K4) // shortlist entries per row = 912
#define NENT_H  (NENT / 2)         // 456 per merge-warp half
#define MLPB    256                // mlp blocks inside fused kernel

// ---------------- device scratch ----------------
static __device__ __align__(1024) unsigned char g_B[(size_t)NT * 16384];  // SW128-swizzled bf16 cand tiles [128c x 64k]
static __device__ __align__(128)  unsigned char g_A[(size_t)BATCH * 128]; // gathered bf16 user rows
static __device__ uint2 g_p[(size_t)BATCH * NENT];                        // packed (float bits, cand idx)

// ---------------- helpers ----------------
__device__ __forceinline__ uint32_t smem_u32(const void* p) {
    uint32_t a;
    asm("{ .reg .u64 t; cvta.to.shared.u64 t, %1; cvt.u32.u64 %0, t; }" : "=r"(a) : "l"(p));
    return a;
}
__device__ __forceinline__ uint32_t pack_bf16x2(float x, float y) {
    __nv_bfloat16 lo = __float2bfloat16(x);
    __nv_bfloat16 hi = __float2bfloat16(y);
    uint16_t lo16, hi16;
    memcpy(&lo16, &lo, 2);
    memcpy(&hi16, &hi, 2);
    return (uint32_t)lo16 | ((uint32_t)hi16 << 16);
}
__device__ __forceinline__ uint32_t sw128(uint32_t off) {
    return off ^ ((off >> 3) & 0x70);
}
__device__ __forceinline__ void ldsm_x4(uint32_t& r0, uint32_t& r1, uint32_t& r2, uint32_t& r3, uint32_t addr) {
    asm volatile("ldmatrix.sync.aligned.m8n8.x4.shared.b16 {%0,%1,%2,%3}, [%4];"
                 : "=r"(r0), "=r"(r1), "=r"(r2), "=r"(r3) : "r"(addr));
}
__device__ __forceinline__ void mma16816(float& d0, float& d1, float& d2, float& d3,
                                         uint32_t a0, uint32_t a1, uint32_t a2, uint32_t a3,
                                         uint32_t b0, uint32_t b1) {
    asm volatile("mma.sync.aligned.m16n8k16.row.col.f32.bf16.bf16.f32 "
                 "{%0,%1,%2,%3}, {%4,%5,%6,%7}, {%8,%9}, {%0,%1,%2,%3};"
                 : "+f"(d0), "+f"(d1), "+f"(d2), "+f"(d3)
                 : "r"(a0), "r"(a1), "r"(a2), "r"(a3), "r"(b0), "r"(b1));
}
#define CP_ASYNC16(smem, gptr) \
    asm volatile("cp.async.cg.shared.global [%0], [%1], 16;" :: "r"(smem), "l"(gptr))
#define CP_COMMIT() asm volatile("cp.async.commit_group;")
#define CP_WAIT0()  asm volatile("cp.async.wait_group 0;")

// Sorted-descending top-N insert, all constant indices after unroll (register-resident).
template<int N>
__device__ __forceinline__ void insN(float s, int ci, float* v, int* ix) {
    v[N - 1] = s; ix[N - 1] = ci;
    #pragma unroll
    for (int q = N - 1; q > 0; q--) {
        if (v[q] > v[q - 1]) {
            float tv = v[q]; v[q] = v[q - 1]; v[q - 1] = tv;
            int  ti = ix[q]; ix[q] = ix[q - 1]; ix[q - 1] = ti;
        }
    }
}

// order-preserving float->uint transform
__device__ __forceinline__ uint32_t f2ord(float f) {
    uint32_t b = __float_as_uint(f);
    return (b & 0x80000000u) ? ~b : (b | 0x80000000u);
}

// ================= Kernel 0: FUSED convert/pre-tile + gather/MLP =================
// blocks [0, MLPB): mlp on 4 rows each.
// blocks [MLPB, ...): 32B-unit converter, 4 units/thread, warp-coalesced, MLP=8.
// unit u < NBC: B-tile chunk (tile = u>>10, r = (u&1023)>>3, sub = u&7)
// unit u >= NBC: A-gather chunk.
__global__ void __launch_bounds__(256) prep_kernel(
    const int* __restrict__ user_id, const int* __restrict__ movie_id,
    const float* __restrict__ ut, const float* __restrict__ ct,
    const float* __restrict__ W1, const float* __restrict__ b1,
    const float* __restrict__ W2, const float* __restrict__ b2,
    const float* __restrict__ W3, const float* __restrict__ b3,
    float* __restrict__ outUE, float* __restrict__ outCE, float* __restrict__ outR)
{
    const int t = threadIdx.x;

    if (blockIdx.x >= MLPB) {
        const long NBC = (long)NT * 1024;            // B units (32B fp32 -> 16B bf16)
        const long TOTAL = NBC + (long)BATCH * 8;    // + A units
        // warp handles 128 consecutive units; lane takes {i, i+32, i+64, i+96}
        const long base = (long)(blockIdx.x - MLPB) * 1024 + (long)(t >> 5) * 128 + (t & 31);

        float4 f[4][2];
        unsigned char* dst[4];
        bool valid[4];

        // ---- load phase: up to 8 independent LDG.128, warp-coalesced ----
        #pragma unroll
        for (int k = 0; k < 4; k++) {
            const long u = base + (long)k * 32;
            valid[k] = (u < TOTAL);
            dst[k] = nullptr;
            f[k][0] = make_float4(0.f, 0.f, 0.f, 0.f);
            f[k][1] = make_float4(0.f, 0.f, 0.f, 0.f);
            if (!valid[k]) continue;
            if (u < NBC) {
                const long tile = u >> 10;
                const int within = (int)(u & 1023);
                const int r = within >> 3, sub = within & 7;
                const long c = tile * 128 + r;
                dst[k] = g_B + tile * 16384 + sw128((uint32_t)(r * 128 + sub * 16));
                if (c < NCAND) {
                    const float4* src = (const float4*)(ct + c * 64 + sub * 8);
                    f[k][0] = src[0];
                    f[k][1] = src[1];
                }
            } else {
                const long g2 = u - NBC;
                const int urow = (int)(g2 >> 3), sub = (int)(g2 & 7);
                const float4* src = (const float4*)(ut + (long)user_id[urow] * 64 + sub * 8);
                f[k][0] = src[0];
                f[k][1] = src[1];
                dst[k] = g_A + (long)urow * 128 + sub * 16;
            }
        }

        // ---- pack + store phase ----
        #pragma unroll
        for (int k = 0; k < 4; k++) {
            if (!valid[k]) continue;
            uint4 out;
            out.x = pack_bf16x2(f[k][0].x, f[k][0].y);
            out.y = pack_bf16x2(f[k][0].z, f[k][0].w);
            out.z = pack_bf16x2(f[k][1].x, f[k][1].y);
            out.w = pack_bf16x2(f[k][1].z, f[k][1].w);
            *(uint4*)dst[k] = out;
        }
        return;
    }

    // ---------------- mlp part ----------------
    __shared__ float xs[4][128];
    __shared__ float h1s[4][256];
    __shared__ float h2s[4][128];
    __shared__ int uid[4], mid[4];

    const int rbase = blockIdx.x * 4;

    if (t < 4) { uid[t] = user_id[rbase + t]; mid[t] = movie_id[rbase + t]; }
    __syncthreads();

    for (int idx = t; idx < 4 * 128; idx += 256) {
        int r = idx >> 7, k = idx & 127;
        float v;
        if (k < 64) {
            v = ut[(long)uid[r] * DIM + k];
            outUE[(long)(rbase + r) * DIM + k] = v;
        } else {
            v = ct[(long)mid[r] * DIM + (k - 64)];
            outCE[(long)(rbase + r) * DIM + (k - 64)] = v;
        }
        xs[r][k] = v;
    }
    __syncthreads();

    {
        float acc[4];
        float bb = b1[t];
        #pragma unroll
        for (int r = 0; r < 4; r++) acc[r] = bb;
        #pragma unroll 8
        for (int k = 0; k < 128; k++) {
            float w = W1[k * 256 + t];
            #pragma unroll
            for (int r = 0; r < 4; r++) acc[r] += xs[r][k] * w;
        }
        #pragma unroll
        for (int r = 0; r < 4; r++) h1s[r][t] = fmaxf(acc[r], 0.0f);
    }
    __syncthreads();

    if (t < 128) {
        float acc[4];
        float bb = b2[t];
        #pragma unroll
        for (int r = 0; r < 4; r++) acc[r] = bb;
        #pragma unroll 8
        for (int k = 0; k < 256; k++) {
            float w = W2[k * 128 + t];
            #pragma unroll
            for (int r = 0; r < 4; r++) acc[r] += h1s[r][k] * w;
        }
        #pragma unroll
        for (int r = 0; r < 4; r++) h2s[r][t] = fmaxf(acc[r], 0.0f);
    }
    __syncthreads();

    if (t < 4) {
        float s = b3[0];
        #pragma unroll 8
        for (int k = 0; k < 128; k++) s += h2s[t][k] * W3[k];
        outR[rbase + t] = s;
    }
}

// ================= Kernel 1: HMMA GEMM + screened register top-4 =================
// grid (8 rowtiles, 57 chunks) x 256 threads (8 warps), 3 CTAs/SM.
// 4 buffers / 2-tile groups. Swizzle factored into lane-constant sx[s].
__global__ void __launch_bounds__(256, 3) gemm_topk_kernel()
{
    extern __shared__ __align__(1024) unsigned char sBd[];   // 4 * 16384

    const int tid = threadIdx.x;
    const int wid = tid >> 5;
    const int lane = tid & 31;
    const int rowtile = blockIdx.x;
    const int chunk = blockIdx.y;

    // 24 chunks of 28 tiles, 33 chunks of 27 tiles: 24*28 + 33*27 = 1563
    const int t_begin = chunk * 27 + min(chunk, 24);
    const int t_end = (chunk + 1) * 27 + min(chunk + 1, 24);
    const int ntiles = t_end - t_begin;
    const int ngroups = (ntiles + 1) >> 1;

    uint32_t sbuf[4];
    #pragma unroll
    for (int b = 0; b < 4; b++) sbuf[b] = smem_u32(sBd + b * 16384);

    // ---- stage A into buf0, build register A-fragments ----
    {
        const uint4* asrc = (const uint4*)(g_A + (size_t)rowtile * 128 * 128);
        uint4* adst = (uint4*)sBd;
        #pragma unroll
        for (int p = 0; p < 4; p++)
            adst[p * 256 + tid] = asrc[p * 256 + tid];
    }
    __syncthreads();

    uint32_t af[4][4];
    {
        const int g2 = lane >> 3;
        const int mrow = wid * 16 + (g2 & 1) * 8 + (lane & 7);
        const int kb = (g2 >> 1) * 16;
        #pragma unroll
        for (int s = 0; s < 4; s++) {
            uint32_t addr = sbuf[0] + (uint32_t)(mrow * 128 + s * 32 + kb);
            ldsm_x4(af[s][0], af[s][1], af[s][2], af[s][3], addr);
        }
    }
    __syncthreads();   // A reads done before group-0 prefetch overwrites buf0

    // ---- sorted top-4 per thread per row-half (descending; [3] = current min) ----
    float vLo[K4], vHi[K4];
    int   iLo[K4], iHi[K4];
    #pragma unroll
    for (int j = 0; j < K4; j++) {
        vLo[j] = -CUDART_INF_F; vHi[j] = -CUDART_INF_F;
        iLo[j] = 0x7fffffff;    iHi[j] = 0x7fffffff;
    }

    const int bg2 = lane >> 3;
    const int b_nloc = ((bg2 >> 1) & 1) * 8 + (lane & 7);
    const int b_kb = (bg2 & 1) * 16;
    const int ccol = 2 * (lane & 3);

    // lane-constant swizzled k-step offsets
    uint32_t sx[4];
    {
        const uint32_t X = (uint32_t)((lane & 7) << 4);
        #pragma unroll
        for (int s = 0; s < 4; s++)
            sx[s] = ((uint32_t)(s * 32 + b_kb)) ^ X;
    }
    const uint32_t bnl128 = (uint32_t)(b_nloc * 128);

    // ---- prefetch group 0 (tiles 0,1 -> bufs 0,1) ----
    #pragma unroll
    for (int w = 0; w < 2; w++) {
        if (w < ntiles) {
            const char* src = (const char*)(g_B + (size_t)(t_begin + w) * 16384);
            #pragma unroll
            for (int p = 0; p < 4; p++)
                CP_ASYNC16(sbuf[w] + (uint32_t)(p * 4096 + tid * 16), src + p * 4096 + tid * 16);
        }
    }
    CP_COMMIT();

    for (int g = 0; g < ngroups; g++) {
        CP_WAIT0();          // group g landed (only pending group)
        __syncthreads();     // visibility + all warps done with group g-1 (its buf pair = target below)

        // prefetch group g+1 into pair (g+1)&1
        {
            const int pr = ((g + 1) & 1) * 2;
            #pragma unroll
            for (int w = 0; w < 2; w++) {
                const int tl = 2 * (g + 1) + w;
                if (tl < ntiles) {
                    const char* src = (const char*)(g_B + (size_t)(t_begin + tl) * 16384);
                    #pragma unroll
                    for (int p = 0; p < 4; p++)
                        CP_ASYNC16(sbuf[pr + w] + (uint32_t)(p * 4096 + tid * 16), src + p * 4096 + tid * 16);
                }
            }
            CP_COMMIT();
        }

        // ---- compute the 2 tiles of group g ----
        #pragma unroll 1
        for (int tt = 0; tt < 2; tt++) {
            const int ti_ = 2 * g + tt;
            if (ti_ >= ntiles) break;
            const uint32_t bsn = sbuf[(g & 1) * 2 + tt] + bnl128;   // lane base for this tile
            const int tilec0 = (t_begin + ti_) * 128;

            #pragma unroll
            for (int q = 0; q < 4; q++) {
                float acc[4][4];
                #pragma unroll
                for (int j = 0; j < 4; j++)
                    #pragma unroll
                    for (int e = 0; e < 4; e++) acc[j][e] = 0.0f;

                #pragma unroll
                for (int s = 0; s < 4; s++) {
                    #pragma unroll
                    for (int p = 0; p < 2; p++) {
                        uint32_t addr = bsn + sx[s] + (uint32_t)(q * 4096 + p * 2048);
                        uint32_t b0, b1, b2, b3;
                        ldsm_x4(b0, b1, b2, b3, addr);
                        mma16816(acc[2 * p][0], acc[2 * p][1], acc[2 * p][2], acc[2 * p][3],
                                 af[s][0], af[s][1], af[s][2], af[s][3], b0, b1);
                        mma16816(acc[2 * p + 1][0], acc[2 * p + 1][1], acc[2 * p + 1][2], acc[2 * p + 1][3],
                                 af[s][0], af[s][1], af[s][2], af[s][3], b2, b3);
                    }
                }

                const int cbase = tilec0 + q * 32;

                // screening maxes (branch-free), then ONE branch per row-half
                float mLo = acc[0][0], mHi = acc[0][2];
                #pragma unroll
                for (int j = 0; j < 4; j++) {
                    mLo = fmaxf(mLo, fmaxf(acc[j][0], acc[j][1]));
                    mHi = fmaxf(mHi, fmaxf(acc[j][2], acc[j][3]));
                }
                if (mLo > vLo[K4 - 1]) {
                    #pragma unroll
                    for (int j = 0; j < 4; j++) {
                        const int c0 = cbase + j * 8 + ccol;
                        if (acc[j][0] > vLo[K4 - 1]) insN<K4>(acc[j][0], c0,     vLo, iLo);
                        if (acc[j][1] > vLo[K4 - 1]) insN<K4>(acc[j][1], c0 + 1, vLo, iLo);
                    }
                }
                if (mHi > vHi[K4 - 1]) {
                    #pragma unroll
                    for (int j = 0; j < 4; j++) {
                        const int c0 = cbase + j * 8 + ccol;
                        if (acc[j][2] > vHi[K4 - 1]) insN<K4>(acc[j][2], c0,     vHi, iHi);
                        if (acc[j][3] > vHi[K4 - 1]) insN<K4>(acc[j][3], c0 + 1, vHi, iHi);
                    }
                }
            }
        }
    }

    // ---- dump shortlists: [row][chunk][c*4 + j] packed ----
    {
        const int c = lane & 3;
        const int rowLo = rowtile * 128 + wid * 16 + (lane >> 2);
        const int rowHi = rowLo + 8;
        const long baseLo = ((long)rowLo * NCHUNKS + chunk) * (4 * K4) + c * K4;
        const long baseHi = ((long)rowHi * NCHUNKS + chunk) * (4 * K4) + c * K4;
        #pragma unroll
        for (int j = 0; j < K4; j++) {
            g_p[baseLo + j] = make_uint2(__float_as_uint(vLo[j]), (uint32_t)iLo[j]);
            g_p[baseHi + j] = make_uint2(__float_as_uint(vHi[j]), (uint32_t)iHi[j]);
        }
    }
}

// ================= Kernel 2: merge shortlists + exact fp32 rescore =================
// 256 blocks x 256 threads: 4 rows/block, 2 warps/row (each scans half the entries).
__global__ void __launch_bounds__(256) merge_kernel(
    const int* __restrict__ user_id,
    const float* __restrict__ ut, const float* __restrict__ ct,
    float* __restrict__ outP)
{
    __shared__ float su[4][64];
    __shared__ int   scand[4][32];

    const int wid = threadIdx.x >> 5;
    const int lane = threadIdx.x & 31;
    const int row4 = wid >> 1;            // 0..3
    const int half = wid & 1;             // 0..1
    const int row = blockIdx.x * 4 + row4;

    if (half == 0) {
        const float* urow = ut + (long)user_id[row] * 64;
        su[row4][lane] = urow[lane];
        su[row4][lane + 32] = urow[lane + 32];
    }

    // phase 1: per-warp scan over its half, 4 batched loads per iteration (MLP=4)
    float tv[K8]; int ti[K8];
    #pragma unroll
    for (int j = 0; j < K8; j++) { tv[j] = -CUDART_INF_F; ti[j] = 0x7fffffff; }
    const long base = (long)row * NENT + (long)half * NENT_H;
    for (int e0 = lane; e0 < NENT_H; e0 += 128) {
        uint2 pv[4];
        #pragma unroll
        for (int k = 0; k < 4; k++) {
            const int e = e0 + k * 32;
            pv[k] = (e < NENT_H) ? g_p[base + e] : make_uint2(0u, 0x7fffffffu);
        }
        #pragma unroll
        for (int k = 0; k < 4; k++) {
            float v = __uint_as_float(pv[k].x);
            if (v > tv[K8 - 1]) {
                int idx = (int)pv[k].y;
                if (idx < NCAND) insN<K8>(v, idx, tv, ti);
            }
        }
    }

    // phase 2: 16-round max extraction from per-lane sorted lists -> 16 cands per half
    {
        float h = tv[0];
        #pragma unroll 1
        for (int r = 0; r < 16; r++) {
            float m = h;
            #pragma unroll
            for (int d = 16; d > 0; d >>= 1)
                m = fmaxf(m, __shfl_xor_sync(0xFFFFFFFFu, m, d));
            unsigned msk = __ballot_sync(0xFFFFFFFFu, h == m);
            int owner = __ffs(msk) - 1;
            if (lane == owner) {
                scand[row4][half * 16 + r] = ti[0];
                #pragma unroll
                for (int q = 0; q < K8 - 1; q++) { tv[q] = tv[q + 1]; ti[q] = ti[q + 1]; }
                tv[K8 - 1] = -CUDART_INF_F;
                h = tv[0];
            }
        }
    }
    __syncthreads();

    // phase 3: half-0 warp rescores all 32 shortlisted candidates exactly (fp32),
    // then 10 rounds of packed-key warp max -> output.
    if (half == 0) {
        const int c = scand[row4][lane];
        float s = -CUDART_INF_F;
        if (c >= 0 && c < NCAND) {
            const float* crow = ct + (long)c * 64;
            s = 0.0f;
            #pragma unroll 8
            for (int k = 0; k < 64; k++) s += su[row4][k] * crow[k];
        }
        // packed sortable key: (ordered float) << 32 | (~idx)  -> value desc, idx asc
        unsigned long long key = ((unsigned long long)f2ord(s) << 32) |
                                 (unsigned long long)(0xFFFFFFFFu - (uint32_t)c);
        #pragma unroll 1
        for (int r = 0; r < TOPK; r++) {
            unsigned long long m = key;
            #pragma unroll
            for (int d = 16; d > 0; d >>= 1) {
                unsigned long long o = __shfl_xor_sync(0xFFFFFFFFu, m, d);
                if (o > m) m = o;
            }
            if (key == m) key = 0;   // winner retires (unique: candidate ids distinct)
            if (lane == 0) {
                uint32_t ci = 0xFFFFFFFFu - (uint32_t)(m & 0xFFFFFFFFu);
                outP[(long)row * TOPK + r] = (float)ci;
            }
        }
    }
}

// ================= launch =================
extern "C" void kernel_launch(void* const* d_in, const int* in_sizes, int n_in,
                              void* d_out, int out_size)
{
    const int*   user_id  = (const int*)d_in[0];
    const int*   movie_id = (const int*)d_in[1];
    const float* ut       = (const float*)d_in[2];
    const float* ct       = (const float*)d_in[3];
    const float* W1       = (const float*)d_in[4];
    const float* b1       = (const float*)d_in[5];
    const float* W2       = (const float*)d_in[6];
    const float* b2       = (const float*)d_in[7];
    const float* W3       = (const float*)d_in[8];
    const float* b3       = (const float*)d_in[9];

    float* out   = (float*)d_out;
    float* outUE = out;
    float* outCE = out + BATCH * DIM;
    float* outR  = out + 2 * BATCH * DIM;
    float* outP  = out + 2 * BATCH * DIM + BATCH;

    // fused convert (4 coalesced 32B units / thread) + A-gather + mlp
    const long convUnits = (long)NT * 1024 + BATCH * 8;
    const int convBlocks = (int)((convUnits + 1023) / 1024);   // 1024 units per block
    prep_kernel<<<MLPB + convBlocks, 256>>>(user_id, movie_id, ut, ct,
                                            W1, b1, W2, b2, W3, b3,
                                            outUE, outCE, outR);

    // gemm + fused screened top-4 (64KB dynamic smem)
    cudaFuncSetAttribute(gemm_topk_kernel,
                         cudaFuncAttributeMaxDynamicSharedMemorySize, 4 * 16384);
    dim3 g2(NROWT, NCHUNKS);
    gemm_topk_kernel<<<g2, 256, 4 * 16384>>>();

    // merge + exact rescore
    merge_kernel<<<BATCH / 4, 256>>>(user_id, ut, ct, outP);
}

// round 14
// speedup vs baseline: 6.7986x; 1.3426x over previous
#include <cuda_runtime.h>
#include <cuda_bf16.h>
#include <math_constants.h>
#include <cstdint>
#include <cstring>

// ---------------- problem constants ----------------
#define BATCH   1024
#define DIM     64
#define NCAND   200000
#define TOPK    10
#define K4      4                  // per-thread in-loop shortlist size
#define K8      8                  // merge-phase per-lane list
#define NT      1563               // ceil(200000/128) tiles of 128 cands
#define NCHUNKS 55                 // tile chunks  (8 x 55 = 440 CTAs = ONE wave at 3/SM)
#define NROWT   8                  // 1024/128 row tiles
#define NENT    (NCHUNKS * 4 * K4) // shortlist entries per row = 880
#define NENT_H  (NENT / 2)         // 440 per merge-warp half
#define MLPB    256                // mlp blocks inside fused kernel

// ---------------- device scratch ----------------
static __device__ __align__(1024) unsigned char g_B[(size_t)NT * 16384];  // SW128-swizzled bf16 cand tiles [128c x 64k]
static __device__ __align__(128)  unsigned char g_A[(size_t)BATCH * 128]; // gathered bf16 user rows
static __device__ uint2 g_p[(size_t)BATCH * NENT];                        // packed (float bits, cand idx)

// ---------------- helpers ----------------
__device__ __forceinline__ uint32_t smem_u32(const void* p) {
    uint32_t a;
    asm("{ .reg .u64 t; cvta.to.shared.u64 t, %1; cvt.u32.u64 %0, t; }" : "=r"(a) : "l"(p));
    return a;
}
__device__ __forceinline__ uint32_t pack_bf16x2(float x, float y) {
    __nv_bfloat16 lo = __float2bfloat16(x);
    __nv_bfloat16 hi = __float2bfloat16(y);
    uint16_t lo16, hi16;
    memcpy(&lo16, &lo, 2);
    memcpy(&hi16, &hi, 2);
    return (uint32_t)lo16 | ((uint32_t)hi16 << 16);
}
__device__ __forceinline__ uint32_t sw128(uint32_t off) {
    return off ^ ((off >> 3) & 0x70);
}
__device__ __forceinline__ void ldsm_x4(uint32_t& r0, uint32_t& r1, uint32_t& r2, uint32_t& r3, uint32_t addr) {
    asm volatile("ldmatrix.sync.aligned.m8n8.x4.shared.b16 {%0,%1,%2,%3}, [%4];"
                 : "=r"(r0), "=r"(r1), "=r"(r2), "=r"(r3) : "r"(addr));
}
__device__ __forceinline__ void mma16816(float& d0, float& d1, float& d2, float& d3,
                                         uint32_t a0, uint32_t a1, uint32_t a2, uint32_t a3,
                                         uint32_t b0, uint32_t b1) {
    asm volatile("mma.sync.aligned.m16n8k16.row.col.f32.bf16.bf16.f32 "
                 "{%0,%1,%2,%3}, {%4,%5,%6,%7}, {%8,%9}, {%0,%1,%2,%3};"
                 : "+f"(d0), "+f"(d1), "+f"(d2), "+f"(d3)
                 : "r"(a0), "r"(a1), "r"(a2), "r"(a3), "r"(b0), "r"(b1));
}
#define CP_ASYNC16(smem, gptr) \
    asm volatile("cp.async.cg.shared.global [%0], [%1], 16;" :: "r"(smem), "l"(gptr))
#define CP_COMMIT() asm volatile("cp.async.commit_group;")
#define CP_WAIT0()  asm volatile("cp.async.wait_group 0;")

// Sorted-descending top-N insert, all constant indices after unroll (register-resident).
template<int N>
__device__ __forceinline__ void insN(float s, int ci, float* v, int* ix) {
    v[N - 1] = s; ix[N - 1] = ci;
    #pragma unroll
    for (int q = N - 1; q > 0; q--) {
        if (v[q] > v[q - 1]) {
            float tv = v[q]; v[q] = v[q - 1]; v[q - 1] = tv;
            int  ti = ix[q]; ix[q] = ix[q - 1]; ix[q - 1] = ti;
        }
    }
}

// order-preserving float->uint transform
__device__ __forceinline__ uint32_t f2ord(float f) {
    uint32_t b = __float_as_uint(f);
    return (b & 0x80000000u) ? ~b : (b | 0x80000000u);
}

// ================= Kernel 0: FUSED convert/pre-tile + gather/MLP =================
// blocks [0, MLPB): mlp on 4 rows each.
// blocks [MLPB, ...): converter. Unit = 16B input (one float4) -> 8B bf16 output.
//   B units: NT*2048 (tile = u>>11, r = (u&2047)>>4, sub16 = u&15). Fully lane-coalesced.
//   A units (after B): 32B input -> 16B output, gathered user rows.
__global__ void __launch_bounds__(256) prep_kernel(
    const int* __restrict__ user_id, const int* __restrict__ movie_id,
    const float* __restrict__ ut, const float* __restrict__ ct,
    const float* __restrict__ W1, const float* __restrict__ b1,
    const float* __restrict__ W2, const float* __restrict__ b2,
    const float* __restrict__ W3, const float* __restrict__ b3,
    float* __restrict__ outUE, float* __restrict__ outCE, float* __restrict__ outR)
{
    const int t = threadIdx.x;

    if (blockIdx.x >= MLPB) {
        const long NBU = (long)NT * 2048;            // B units (16B fp32 -> 8B bf16)
        const long TOTAL = NBU + (long)BATCH * 8;    // + A units
        // warp handles 128 consecutive units; lane takes {i, i+32, i+64, i+96}
        const long base = (long)(blockIdx.x - MLPB) * 1024 + (long)(t >> 5) * 128 + (t & 31);

        float4 f[4];
        float4 fa[4];        // second half for A units only
        unsigned char* dst[4];
        int kind[4];         // 0 = skip, 1 = B unit, 2 = A unit

        // ---- load phase: 4 independent, fully coalesced LDG.128 ----
        #pragma unroll
        for (int k = 0; k < 4; k++) {
            const long u = base + (long)k * 32;
            kind[k] = 0;
            dst[k] = nullptr;
            f[k] = make_float4(0.f, 0.f, 0.f, 0.f);
            if (u >= TOTAL) continue;
            if (u < NBU) {
                const long tile = u >> 11;
                const int within = (int)(u & 2047);
                const int r = within >> 4, sub16 = within & 15;
                const long c = tile * 128 + r;
                kind[k] = 1;
                dst[k] = g_B + tile * 16384 + sw128((uint32_t)(r * 128 + sub16 * 8));
                if (c < NCAND)
                    f[k] = *(const float4*)(ct + c * 64 + sub16 * 4);
            } else {
                const long g2 = u - NBU;
                const int urow = (int)(g2 >> 3), sub = (int)(g2 & 7);
                const float4* src = (const float4*)(ut + (long)user_id[urow] * 64 + sub * 8);
                kind[k] = 2;
                f[k] = src[0];
                fa[k] = src[1];
                dst[k] = g_A + (long)urow * 128 + sub * 16;
            }
        }

        // ---- pack + store phase ----
        #pragma unroll
        for (int k = 0; k < 4; k++) {
            if (kind[k] == 1) {
                uint2 out;
                out.x = pack_bf16x2(f[k].x, f[k].y);
                out.y = pack_bf16x2(f[k].z, f[k].w);
                *(uint2*)dst[k] = out;
            } else if (kind[k] == 2) {
                uint4 out;
                out.x = pack_bf16x2(f[k].x, f[k].y);
                out.y = pack_bf16x2(f[k].z, f[k].w);
                out.z = pack_bf16x2(fa[k].x, fa[k].y);
                out.w = pack_bf16x2(fa[k].z, fa[k].w);
                *(uint4*)dst[k] = out;
            }
        }
        return;
    }

    // ---------------- mlp part ----------------
    __shared__ float xs[4][128];
    __shared__ float h1s[4][256];
    __shared__ float h2s[4][128];
    __shared__ int uid[4], mid[4];

    const int rbase = blockIdx.x * 4;

    if (t < 4) { uid[t] = user_id[rbase + t]; mid[t] = movie_id[rbase + t]; }
    __syncthreads();

    for (int idx = t; idx < 4 * 128; idx += 256) {
        int r = idx >> 7, k = idx & 127;
        float v;
        if (k < 64) {
            v = ut[(long)uid[r] * DIM + k];
            outUE[(long)(rbase + r) * DIM + k] = v;
        } else {
            v = ct[(long)mid[r] * DIM + (k - 64)];
            outCE[(long)(rbase + r) * DIM + (k - 64)] = v;
        }
        xs[r][k] = v;
    }
    __syncthreads();

    {
        float acc[4];
        float bb = b1[t];
        #pragma unroll
        for (int r = 0; r < 4; r++) acc[r] = bb;
        #pragma unroll 8
        for (int k = 0; k < 128; k++) {
            float w = W1[k * 256 + t];
            #pragma unroll
            for (int r = 0; r < 4; r++) acc[r] += xs[r][k] * w;
        }
        #pragma unroll
        for (int r = 0; r < 4; r++) h1s[r][t] = fmaxf(acc[r], 0.0f);
    }
    __syncthreads();

    if (t < 128) {
        float acc[4];
        float bb = b2[t];
        #pragma unroll
        for (int r = 0; r < 4; r++) acc[r] = bb;
        #pragma unroll 8
        for (int k = 0; k < 256; k++) {
            float w = W2[k * 128 + t];
            #pragma unroll
            for (int r = 0; r < 4; r++) acc[r] += h1s[r][k] * w;
        }
        #pragma unroll
        for (int r = 0; r < 4; r++) h2s[r][t] = fmaxf(acc[r], 0.0f);
    }
    __syncthreads();

    if (t < 4) {
        float s = b3[0];
        #pragma unroll 8
        for (int k = 0; k < 128; k++) s += h2s[t][k] * W3[k];
        outR[rbase + t] = s;
    }
}

// ================= Kernel 1: HMMA GEMM + screened register top-4 =================
// grid (8 rowtiles, 55 chunks) = 440 CTAs = ONE full wave at 3 CTAs/SM.
// 4 buffers / 2-tile groups. Swizzle factored into lane-constant sx[s].
__global__ void __launch_bounds__(256, 3) gemm_topk_kernel()
{
    extern __shared__ __align__(1024) unsigned char sBd[];   // 4 * 16384

    const int tid = threadIdx.x;
    const int wid = tid >> 5;
    const int lane = tid & 31;
    const int rowtile = blockIdx.x;
    const int chunk = blockIdx.y;

    // 23 chunks of 29 tiles, 32 chunks of 28 tiles: 23*29 + 32*28 = 1563
    const int t_begin = chunk * 28 + min(chunk, 23);
    const int t_end = (chunk + 1) * 28 + min(chunk + 1, 23);
    const int ntiles = t_end - t_begin;
    const int ngroups = (ntiles + 1) >> 1;

    uint32_t sbuf[4];
    #pragma unroll
    for (int b = 0; b < 4; b++) sbuf[b] = smem_u32(sBd + b * 16384);

    // ---- stage A into buf0, build register A-fragments ----
    {
        const uint4* asrc = (const uint4*)(g_A + (size_t)rowtile * 128 * 128);
        uint4* adst = (uint4*)sBd;
        #pragma unroll
        for (int p = 0; p < 4; p++)
            adst[p * 256 + tid] = asrc[p * 256 + tid];
    }
    __syncthreads();

    uint32_t af[4][4];
    {
        const int g2 = lane >> 3;
        const int mrow = wid * 16 + (g2 & 1) * 8 + (lane & 7);
        const int kb = (g2 >> 1) * 16;
        #pragma unroll
        for (int s = 0; s < 4; s++) {
            uint32_t addr = sbuf[0] + (uint32_t)(mrow * 128 + s * 32 + kb);
            ldsm_x4(af[s][0], af[s][1], af[s][2], af[s][3], addr);
        }
    }
    __syncthreads();   // A reads done before group-0 prefetch overwrites buf0

    // ---- sorted top-4 per thread per row-half (descending; [3] = current min) ----
    float vLo[K4], vHi[K4];
    int   iLo[K4], iHi[K4];
    #pragma unroll
    for (int j = 0; j < K4; j++) {
        vLo[j] = -CUDART_INF_F; vHi[j] = -CUDART_INF_F;
        iLo[j] = 0x7fffffff;    iHi[j] = 0x7fffffff;
    }

    const int bg2 = lane >> 3;
    const int b_nloc = ((bg2 >> 1) & 1) * 8 + (lane & 7);
    const int b_kb = (bg2 & 1) * 16;
    const int ccol = 2 * (lane & 3);

    // lane-constant swizzled k-step offsets
    uint32_t sx[4];
    {
        const uint32_t X = (uint32_t)((lane & 7) << 4);
        #pragma unroll
        for (int s = 0; s < 4; s++)
            sx[s] = ((uint32_t)(s * 32 + b_kb)) ^ X;
    }
    const uint32_t bnl128 = (uint32_t)(b_nloc * 128);

    // ---- prefetch group 0 (tiles 0,1 -> bufs 0,1) ----
    #pragma unroll
    for (int w = 0; w < 2; w++) {
        if (w < ntiles) {
            const char* src = (const char*)(g_B + (size_t)(t_begin + w) * 16384);
            #pragma unroll
            for (int p = 0; p < 4; p++)
                CP_ASYNC16(sbuf[w] + (uint32_t)(p * 4096 + tid * 16), src + p * 4096 + tid * 16);
        }
    }
    CP_COMMIT();

    for (int g = 0; g < ngroups; g++) {
        CP_WAIT0();          // group g landed (only pending group)
        __syncthreads();     // visibility + all warps done with group g-1 (its buf pair = target below)

        // prefetch group g+1 into pair (g+1)&1
        {
            const int pr = ((g + 1) & 1) * 2;
            #pragma unroll
            for (int w = 0; w < 2; w++) {
                const int tl = 2 * (g + 1) + w;
                if (tl < ntiles) {
                    const char* src = (const char*)(g_B + (size_t)(t_begin + tl) * 16384);
                    #pragma unroll
                    for (int p = 0; p < 4; p++)
                        CP_ASYNC16(sbuf[pr + w] + (uint32_t)(p * 4096 + tid * 16), src + p * 4096 + tid * 16);
                }
            }
            CP_COMMIT();
        }

        // ---- compute the 2 tiles of group g ----
        #pragma unroll 1
        for (int tt = 0; tt < 2; tt++) {
            const int ti_ = 2 * g + tt;
            if (ti_ >= ntiles) break;
            const uint32_t bsn = sbuf[(g & 1) * 2 + tt] + bnl128;   // lane base for this tile
            const int tilec0 = (t_begin + ti_) * 128;

            #pragma unroll
            for (int q = 0; q < 4; q++) {
                float acc[4][4];
                #pragma unroll
                for (int j = 0; j < 4; j++)
                    #pragma unroll
                    for (int e = 0; e < 4; e++) acc[j][e] = 0.0f;

                #pragma unroll
                for (int s = 0; s < 4; s++) {
                    #pragma unroll
                    for (int p = 0; p < 2; p++) {
                        uint32_t addr = bsn + sx[s] + (uint32_t)(q * 4096 + p * 2048);
                        uint32_t b0, b1, b2, b3;
                        ldsm_x4(b0, b1, b2, b3, addr);
                        mma16816(acc[2 * p][0], acc[2 * p][1], acc[2 * p][2], acc[2 * p][3],
                                 af[s][0], af[s][1], af[s][2], af[s][3], b0, b1);
                        mma16816(acc[2 * p + 1][0], acc[2 * p + 1][1], acc[2 * p + 1][2], acc[2 * p + 1][3],
                                 af[s][0], af[s][1], af[s][2], af[s][3], b2, b3);
                    }
                }

                const int cbase = tilec0 + q * 32;

                // screening maxes (branch-free), then ONE branch per row-half
                float mLo = acc[0][0], mHi = acc[0][2];
                #pragma unroll
                for (int j = 0; j < 4; j++) {
                    mLo = fmaxf(mLo, fmaxf(acc[j][0], acc[j][1]));
                    mHi = fmaxf(mHi, fmaxf(acc[j][2], acc[j][3]));
                }
                if (mLo > vLo[K4 - 1]) {
                    #pragma unroll
                    for (int j = 0; j < 4; j++) {
                        const int c0 = cbase + j * 8 + ccol;
                        if (acc[j][0] > vLo[K4 - 1]) insN<K4>(acc[j][0], c0,     vLo, iLo);
                        if (acc[j][1] > vLo[K4 - 1]) insN<K4>(acc[j][1], c0 + 1, vLo, iLo);
                    }
                }
                if (mHi > vHi[K4 - 1]) {
                    #pragma unroll
                    for (int j = 0; j < 4; j++) {
                        const int c0 = cbase + j * 8 + ccol;
                        if (acc[j][2] > vHi[K4 - 1]) insN<K4>(acc[j][2], c0,     vHi, iHi);
                        if (acc[j][3] > vHi[K4 - 1]) insN<K4>(acc[j][3], c0 + 1, vHi, iHi);
                    }
                }
            }
        }
    }

    // ---- dump shortlists: [row][chunk][c*4 + j] packed ----
    {
        const int c = lane & 3;
        const int rowLo = rowtile * 128 + wid * 16 + (lane >> 2);
        const int rowHi = rowLo + 8;
        const long baseLo = ((long)rowLo * NCHUNKS + chunk) * (4 * K4) + c * K4;
        const long baseHi = ((long)rowHi * NCHUNKS + chunk) * (4 * K4) + c * K4;
        #pragma unroll
        for (int j = 0; j < K4; j++) {
            g_p[baseLo + j] = make_uint2(__float_as_uint(vLo[j]), (uint32_t)iLo[j]);
            g_p[baseHi + j] = make_uint2(__float_as_uint(vHi[j]), (uint32_t)iHi[j]);
        }
    }
}

// ================= Kernel 2: merge shortlists + exact fp32 rescore =================
// 256 blocks x 256 threads: 4 rows/block, 2 warps/row (each scans half the entries).
__global__ void __launch_bounds__(256) merge_kernel(
    const int* __restrict__ user_id,
    const float* __restrict__ ut, const float* __restrict__ ct,
    float* __restrict__ outP)
{
    __shared__ float su[4][64];
    __shared__ int   scand[4][32];

    const int wid = threadIdx.x >> 5;
    const int lane = threadIdx.x & 31;
    const int row4 = wid >> 1;            // 0..3
    const int half = wid & 1;             // 0..1
    const int row = blockIdx.x * 4 + row4;

    if (half == 0) {
        const float* urow = ut + (long)user_id[row] * 64;
        su[row4][lane] = urow[lane];
        su[row4][lane + 32] = urow[lane + 32];
    }

    // phase 1: per-warp scan over its half, 4 batched loads per iteration (MLP=4)
    float tv[K8]; int ti[K8];
    #pragma unroll
    for (int j = 0; j < K8; j++) { tv[j] = -CUDART_INF_F; ti[j] = 0x7fffffff; }
    const long base = (long)row * NENT + (long)half * NENT_H;
    for (int e0 = lane; e0 < NENT_H; e0 += 128) {
        uint2 pv[4];
        #pragma unroll
        for (int k = 0; k < 4; k++) {
            const int e = e0 + k * 32;
            pv[k] = (e < NENT_H) ? g_p[base + e] : make_uint2(0u, 0x7fffffffu);
        }
        #pragma unroll
        for (int k = 0; k < 4; k++) {
            float v = __uint_as_float(pv[k].x);
            if (v > tv[K8 - 1]) {
                int idx = (int)pv[k].y;
                if (idx < NCAND) insN<K8>(v, idx, tv, ti);
            }
        }
    }

    // phase 2: 16-round max extraction from per-lane sorted lists -> 16 cands per half
    {
        float h = tv[0];
        #pragma unroll 1
        for (int r = 0; r < 16; r++) {
            float m = h;
            #pragma unroll
            for (int d = 16; d > 0; d >>= 1)
                m = fmaxf(m, __shfl_xor_sync(0xFFFFFFFFu, m, d));
            unsigned msk = __ballot_sync(0xFFFFFFFFu, h == m);
            int owner = __ffs(msk) - 1;
            if (lane == owner) {
                scand[row4][half * 16 + r] = ti[0];
                #pragma unroll
                for (int q = 0; q < K8 - 1; q++) { tv[q] = tv[q + 1]; ti[q] = ti[q + 1]; }
                tv[K8 - 1] = -CUDART_INF_F;
                h = tv[0];
            }
        }
    }
    __syncthreads();

    // phase 3: half-0 warp rescores all 32 shortlisted candidates exactly (fp32),
    // then 10 rounds of packed-key warp max -> output.
    if (half == 0) {
        const int c = scand[row4][lane];
        float s = -CUDART_INF_F;
        if (c >= 0 && c < NCAND) {
            const float* crow = ct + (long)c * 64;
            s = 0.0f;
            #pragma unroll 8
            for (int k = 0; k < 64; k++) s += su[row4][k] * crow[k];
        }
        // packed sortable key: (ordered float) << 32 | (~idx)  -> value desc, idx asc
        unsigned long long key = ((unsigned long long)f2ord(s) << 32) |
                                 (unsigned long long)(0xFFFFFFFFu - (uint32_t)c);
        #pragma unroll 1
        for (int r = 0; r < TOPK; r++) {
            unsigned long long m = key;
            #pragma unroll
            for (int d = 16; d > 0; d >>= 1) {
                unsigned long long o = __shfl_xor_sync(0xFFFFFFFFu, m, d);
                if (o > m) m = o;
            }
            if (key == m) key = 0;   // winner retires (unique: candidate ids distinct)
            if (lane == 0) {
                uint32_t ci = 0xFFFFFFFFu - (uint32_t)(m & 0xFFFFFFFFu);
                outP[(long)row * TOPK + r] = (float)ci;
            }
        }
    }
}

// ================= launch =================
extern "C" void kernel_launch(void* const* d_in, const int* in_sizes, int n_in,
                              void* d_out, int out_size)
{
    const int*   user_id  = (const int*)d_in[0];
    const int*   movie_id = (const int*)d_in[1];
    const float* ut       = (const float*)d_in[2];
    const float* ct       = (const float*)d_in[3];
    const float* W1       = (const float*)d_in[4];
    const float* b1       = (const float*)d_in[5];
    const float* W2       = (const float*)d_in[6];
    const float* b2       = (const float*)d_in[7];
    const float* W3       = (const float*)d_in[8];
    const float* b3       = (const float*)d_in[9];

    float* out   = (float*)d_out;
    float* outUE = out;
    float* outCE = out + BATCH * DIM;
    float* outR  = out + 2 * BATCH * DIM;
    float* outP  = out + 2 * BATCH * DIM + BATCH;

    // fused convert (16B-unit, fully coalesced) + A-gather + mlp
    const long convUnits = (long)NT * 2048 + BATCH * 8;
    const int convBlocks = (int)((convUnits + 1023) / 1024);   // 1024 units per block
    prep_kernel<<<MLPB + convBlocks, 256>>>(user_id, movie_id, ut, ct,
                                            W1, b1, W2, b2, W3, b3,
                                            outUE, outCE, outR);

    // gemm + fused screened top-4 (64KB dynamic smem), single full wave
    cudaFuncSetAttribute(gemm_topk_kernel,
                         cudaFuncAttributeMaxDynamicSharedMemorySize, 4 * 16384);
    dim3 g2(NROWT, NCHUNKS);
    gemm_topk_kernel<<<g2, 256, 4 * 16384>>>();

    // merge + exact rescore
    merge_kernel<<<BATCH / 4, 256>>>(user_id, ut, ct, outP);
}